// round 8
// baseline (speedup 1.0000x reference)
#include <cuda_runtime.h>
#include <cuda_bf16.h>
#include <cstdint>

#define Bc 8
#define Sc 384
#define Dc 1024
#define Hc 16
#define HDc 64
#define D3c 3072
#define BSc 3072   // B*S

// ---------------------------------------------------------------------------
// Scratch (static device globals; no runtime allocation)
// ---------------------------------------------------------------------------
__device__ float g_attn[(size_t)Bc * Hc * Sc * Sc];   // fallback attn buffer
__device__ __align__(16) __nv_bfloat16 g_ah[(size_t)BSc * Dc];    // A hi (x, then vals)
__device__ __align__(16) __nv_bfloat16 g_al[(size_t)BSc * Dc];    // A lo
__device__ __align__(16) __nv_bfloat16 g_wqh[(size_t)D3c * Dc];   // qkv_w^T hi [N,K]
__device__ __align__(16) __nv_bfloat16 g_wql[(size_t)D3c * Dc];   // qkv_w^T lo
__device__ __align__(16) __nv_bfloat16 g_woh[(size_t)Dc * Dc];    // out_w^T hi
__device__ __align__(16) __nv_bfloat16 g_wol[(size_t)Dc * Dc];    // out_w^T lo
__device__ __align__(16) __nv_bfloat16 g_qkvh[(size_t)BSc * D3c]; // qkv hi (q pre-scaled /8)
__device__ __align__(16) __nv_bfloat16 g_qkvl[(size_t)BSc * D3c]; // qkv lo

// ---------------------------------------------------------------------------
// Baseline-PTX helpers
// ---------------------------------------------------------------------------
__device__ __forceinline__ uint32_t smem_u32(const void* p) {
    uint32_t a;
    asm("{ .reg .u64 t; cvta.to.shared.u64 t, %1; cvt.u32.u64 %0, t; }" : "=r"(a) : "l"(p));
    return a;
}
#define CP_ASYNC16(sm, gp) \
    asm volatile("cp.async.cg.shared.global [%0], [%1], 16;" :: "r"(sm), "l"(gp))
#define CP_COMMIT() asm volatile("cp.async.commit_group;" ::: "memory")
#define CP_WAIT0()  asm volatile("cp.async.wait_group 0;" ::: "memory")
#define CP_WAIT1()  asm volatile("cp.async.wait_group 1;" ::: "memory")

#define LDSM_X4(r, a) \
    asm volatile("ldmatrix.sync.aligned.m8n8.x4.shared.b16 {%0,%1,%2,%3}, [%4];" \
        : "=r"((r)[0]), "=r"((r)[1]), "=r"((r)[2]), "=r"((r)[3]) : "r"(a))
#define LDSM_X4_T(r, a) \
    asm volatile("ldmatrix.sync.aligned.m8n8.x4.trans.shared.b16 {%0,%1,%2,%3}, [%4];" \
        : "=r"((r)[0]), "=r"((r)[1]), "=r"((r)[2]), "=r"((r)[3]) : "r"(a))

__device__ __forceinline__ void mma_bf16(float* d, const uint32_t* a,
                                         uint32_t b0, uint32_t b1) {
    asm volatile(
        "mma.sync.aligned.m16n8k16.row.col.f32.bf16.bf16.f32 "
        "{%0,%1,%2,%3}, {%4,%5,%6,%7}, {%8,%9}, {%0,%1,%2,%3};"
        : "+f"(d[0]), "+f"(d[1]), "+f"(d[2]), "+f"(d[3])
        : "r"(a[0]), "r"(a[1]), "r"(a[2]), "r"(a[3]), "r"(b0), "r"(b1));
}

// packed f32x2 (Blackwell FFMA2; baseline sm_100+ PTX)
__device__ __forceinline__ unsigned long long packf2(float x, float y) {
    unsigned long long r;
    asm("mov.b64 %0, {%1, %2};" : "=l"(r) : "f"(x), "f"(y));
    return r;
}
#define FFMA2(acc, a, b) \
    asm("fma.rn.f32x2 %0, %1, %2, %0;" : "+l"(acc) : "l"(a), "l"(b))
__device__ __forceinline__ void unpackf2(unsigned long long v, float& lo, float& hi) {
    asm("mov.b64 {%0, %1}, %2;" : "=f"(lo), "=f"(hi) : "l"(v));
}

__device__ __forceinline__ void split2(float x, float y,
                                       __nv_bfloat16* ph, __nv_bfloat16* pl) {
    __nv_bfloat16 hx = __float2bfloat16(x), hy = __float2bfloat16(y);
    *(__nv_bfloat162*)ph = __nv_bfloat162(hx, hy);
    *(__nv_bfloat162*)pl = __nv_bfloat162(
        __float2bfloat16(x - __bfloat162float(hx)),
        __float2bfloat16(y - __bfloat162float(hy)));
}
__device__ __forceinline__ void pack_hilo(float x, float y,
                                          uint32_t& hi, uint32_t& lo) {
    __nv_bfloat16 hx = __float2bfloat16(x), hy = __float2bfloat16(y);
    __nv_bfloat162 h2(hx, hy);
    __nv_bfloat162 l2(__float2bfloat16(x - __bfloat162float(hx)),
                      __float2bfloat16(y - __bfloat162float(hy)));
    hi = *(uint32_t*)&h2;
    lo = *(uint32_t*)&l2;
}

// ---------------------------------------------------------------------------
// HMMA bf16-split GEMM: C = (Ah+Al)@(Bh+Bl)^T + bias
// Single-sync mainloop: wait group -> barrier -> issue(it+2) -> compute(it).
// ---------------------------------------------------------------------------
#define TILE_B 8192
#define BUF_B  (4 * TILE_B)
#define NSTAGE 3
#define GSMEM  (NSTAGE * BUF_B)   // 96 KB

__global__ __launch_bounds__(256, 2) void mma_gemm_kernel(
    const __nv_bfloat16* __restrict__ Ah, const __nv_bfloat16* __restrict__ Al,
    const __nv_bfloat16* __restrict__ Bh, const __nv_bfloat16* __restrict__ Bl,
    const float* __restrict__ bias, float* __restrict__ C,
    __nv_bfloat16* __restrict__ Ch, __nv_bfloat16* __restrict__ Cl,
    int qkv_mode, int M, int N, int K)
{
    extern __shared__ char smem[];
    const uint32_t sbase = smem_u32(smem);
    const int tid  = threadIdx.x;
    const int wid  = tid >> 5;
    const int lane = tid & 31;
    const int m0 = blockIdx.y * 128;
    const int n0 = blockIdx.x * 128;
    const int mw = (wid & 1) * 64;
    const int nw = (wid >> 1) * 32;

    const int lrow = tid >> 1;
    const int c0   = (tid & 1) * 2;
    const int sw0  = (lrow >> 1) & 3;
    const __nv_bfloat16* gAh = Ah + (size_t)(m0 + lrow) * K;
    const __nv_bfloat16* gAl = Al + (size_t)(m0 + lrow) * K;
    const __nv_bfloat16* gBh = Bh + (size_t)(n0 + lrow) * K;
    const __nv_bfloat16* gBl = Bl + (size_t)(n0 + lrow) * K;
    const uint32_t soff0 = lrow * 64 + (((c0 + 0) ^ sw0) << 4);
    const uint32_t soff1 = lrow * 64 + (((c0 + 1) ^ sw0) << 4);

    const int NK = K >> 5;

    auto issue = [&](int it) {
        if (it < NK) {
            const uint32_t tb = sbase + (it % NSTAGE) * BUF_B;
            const int k0 = it << 5;
            CP_ASYNC16(tb + 0 * TILE_B + soff0, gAh + k0 + (c0 + 0) * 8);
            CP_ASYNC16(tb + 0 * TILE_B + soff1, gAh + k0 + (c0 + 1) * 8);
            CP_ASYNC16(tb + 1 * TILE_B + soff0, gAl + k0 + (c0 + 0) * 8);
            CP_ASYNC16(tb + 1 * TILE_B + soff1, gAl + k0 + (c0 + 1) * 8);
            CP_ASYNC16(tb + 2 * TILE_B + soff0, gBh + k0 + (c0 + 0) * 8);
            CP_ASYNC16(tb + 2 * TILE_B + soff1, gBh + k0 + (c0 + 1) * 8);
            CP_ASYNC16(tb + 3 * TILE_B + soff0, gBl + k0 + (c0 + 0) * 8);
            CP_ASYNC16(tb + 3 * TILE_B + soff1, gBl + k0 + (c0 + 1) * 8);
        }
        CP_COMMIT();
    };

    const int frow = lane & 15;
    const int fc   = lane >> 4;
    auto fr_addr = [&](int rbase) -> uint32_t {
        const int row = rbase + frow;
        return (uint32_t)(row * 64 + ((fc ^ ((row >> 1) & 3)) << 4));
    };
    const uint32_t aoff = fr_addr(mw);
    const uint32_t boff = fr_addr(nw);

    float acc[4][4][4];
    #pragma unroll
    for (int i = 0; i < 4; i++)
        #pragma unroll
        for (int j = 0; j < 4; j++)
            #pragma unroll
            for (int r = 0; r < 4; r++) acc[i][j][r] = 0.f;

    issue(0); issue(1);

    for (int it = 0; it < NK; it++) {
        CP_WAIT1();
        __syncthreads();
        issue(it + 2);   // buffer (it+2)%3 == (it-1)%3, consumed by all at the barrier
        const uint32_t tb = sbase + (it % NSTAGE) * BUF_B;
        #pragma unroll
        for (int ks = 0; ks < 2; ks++) {
            const uint32_t kx = ks ? 32u : 0u;
            uint32_t ahf[4][4], bhf[2][4];
            #pragma unroll
            for (int mt = 0; mt < 4; mt++)
                LDSM_X4(ahf[mt], tb + ((aoff + mt * 1024) ^ kx));
            #pragma unroll
            for (int bt = 0; bt < 2; bt++)
                LDSM_X4(bhf[bt], tb + 2 * TILE_B + ((boff + bt * 1024) ^ kx));
            // pass 0: Ah*Bh
            #pragma unroll
            for (int mt = 0; mt < 4; mt++)
                #pragma unroll
                for (int nt = 0; nt < 4; nt++)
                    mma_bf16(acc[mt][nt], ahf[mt],
                             bhf[nt >> 1][nt & 1], bhf[nt >> 1][(nt & 1) + 2]);
            // load Bl while pass0 drains
            uint32_t blf[2][4];
            #pragma unroll
            for (int bt = 0; bt < 2; bt++)
                LDSM_X4(blf[bt], tb + 3 * TILE_B + ((boff + bt * 1024) ^ kx));
            // pass 1: Ah*Bl
            #pragma unroll
            for (int mt = 0; mt < 4; mt++)
                #pragma unroll
                for (int nt = 0; nt < 4; nt++)
                    mma_bf16(acc[mt][nt], ahf[mt],
                             blf[nt >> 1][nt & 1], blf[nt >> 1][(nt & 1) + 2]);
            // load Al while pass1 drains
            uint32_t alf[4][4];
            #pragma unroll
            for (int mt = 0; mt < 4; mt++)
                LDSM_X4(alf[mt], tb + TILE_B + ((aoff + mt * 1024) ^ kx));
            // pass 2: Al*Bh
            #pragma unroll
            for (int mt = 0; mt < 4; mt++)
                #pragma unroll
                for (int nt = 0; nt < 4; nt++)
                    mma_bf16(acc[mt][nt], alf[mt],
                             bhf[nt >> 1][nt & 1], bhf[nt >> 1][(nt & 1) + 2]);
        }
    }

    const int er = lane >> 2;
    const int ec = (lane & 3) * 2;
    #pragma unroll
    for (int mt = 0; mt < 4; mt++) {
        #pragma unroll
        for (int nt = 0; nt < 4; nt++) {
            const int col = n0 + nw + nt * 8 + ec;
            const float bx = __ldg(&bias[col]);
            const float by = __ldg(&bias[col + 1]);
            const int r0 = m0 + mw + mt * 16 + er;
            float2 v0 = make_float2(acc[mt][nt][0] + bx, acc[mt][nt][1] + by);
            float2 v1 = make_float2(acc[mt][nt][2] + bx, acc[mt][nt][3] + by);
            if (C) {
                *(float2*)(C + (size_t)r0 * N + col) = v0;
                *(float2*)(C + (size_t)(r0 + 8) * N + col) = v1;
            }
            if (Ch) {
                const float s = (qkv_mode && (((col >> 6) % 3) == 0)) ? 0.125f : 1.0f;
                split2(v0.x * s, v0.y * s, Ch + (size_t)r0 * N + col,
                       Cl + (size_t)r0 * N + col);
                split2(v1.x * s, v1.y * s, Ch + (size_t)(r0 + 8) * N + col,
                       Cl + (size_t)(r0 + 8) * N + col);
            }
        }
    }
}

// ---------------------------------------------------------------------------
// fp32 -> bf16 hi/lo split (vectorized by 4)
// ---------------------------------------------------------------------------
__global__ __launch_bounds__(256) void split_kernel(
    const float* __restrict__ src, __nv_bfloat16* __restrict__ hi,
    __nv_bfloat16* __restrict__ lo, int n4)
{
    int i = blockIdx.x * blockDim.x + threadIdx.x;
    if (i >= n4) return;
    float4 v = ((const float4*)src)[i];
    split2(v.x, v.y, hi + 4 * (size_t)i, lo + 4 * (size_t)i);
    split2(v.z, v.w, hi + 4 * (size_t)i + 2, lo + 4 * (size_t)i + 2);
}

// ---------------------------------------------------------------------------
// W[K,N] -> Wt[N,K] with bf16 hi/lo split
// ---------------------------------------------------------------------------
__global__ __launch_bounds__(256) void transpose_split_kernel(
    const float* __restrict__ W, __nv_bfloat16* __restrict__ Th,
    __nv_bfloat16* __restrict__ Tl, int K, int N)
{
    __shared__ float t[32][33];
    const int n0 = blockIdx.x * 32, k0 = blockIdx.y * 32;
    const int tx = threadIdx.x, ty = threadIdx.y;
    #pragma unroll
    for (int r = 0; r < 4; r++)
        t[ty + 8 * r][tx] = W[(size_t)(k0 + ty + 8 * r) * N + n0 + tx];
    __syncthreads();
    #pragma unroll
    for (int r = 0; r < 4; r++) {
        float v = t[tx][ty + 8 * r];
        __nv_bfloat16 h = __float2bfloat16(v);
        __nv_bfloat16 l = __float2bfloat16(v - __bfloat162float(h));
        size_t o = (size_t)(n0 + ty + 8 * r) * K + k0 + tx;
        Th[o] = h; Tl[o] = l;
    }
}

// ---------------------------------------------------------------------------
// qk HMMA: logits = (scaled q).k, 3-pass bf16 split, interleaved LDSM.
// ---------------------------------------------------------------------------
#define QK_SMEM (4 * 16384)

__global__ __launch_bounds__(256, 2) void qk_mma_kernel(
    const __nv_bfloat16* __restrict__ qkvh, const __nv_bfloat16* __restrict__ qkvl,
    float* __restrict__ attn)
{
    extern __shared__ char smem[];
    const uint32_t sb = smem_u32(smem);
    const int tid = threadIdx.x, wid = tid >> 5, lane = tid & 31;
    const int bh = blockIdx.z, b = bh >> 4, h = bh & 15;
    const int i0 = blockIdx.y * 128, j0 = blockIdx.x * 128;

    #pragma unroll
    for (int t = 0; t < 4; t++) {
        const __nv_bfloat16* base = (t & 1) ? qkvl : qkvh;
        const int roff = (t < 2) ? i0 : j0;
        const int coff = h * 192 + ((t < 2) ? 0 : 64);
        for (int idx = tid; idx < 1024; idx += 256) {
            const int row = idx >> 3, c = idx & 7;
            const uint32_t dst = sb + t * 16384 + row * 128 + ((c ^ (row & 7)) << 4);
            CP_ASYNC16(dst, base + (size_t)(b * Sc + roff + row) * D3c + coff + c * 8);
        }
    }
    CP_COMMIT(); CP_WAIT0();
    __syncthreads();

    const int mw = (wid & 1) * 64;
    const int nw = (wid >> 1) * 32;
    const int frow = lane & 15, fc = lane >> 4;

    float acc[4][4][4];
    #pragma unroll
    for (int i = 0; i < 4; i++)
        #pragma unroll
        for (int j = 0; j < 4; j++)
            #pragma unroll
            for (int r = 0; r < 4; r++) acc[i][j][r] = 0.f;

    #pragma unroll
    for (int ks = 0; ks < 4; ks++) {
        uint32_t aadr[4], badr[2];
        #pragma unroll
        for (int mt = 0; mt < 4; mt++) {
            const int row = mw + mt * 16 + frow;
            aadr[mt] = row * 128 + (((2 * ks + fc) ^ (row & 7)) << 4);
        }
        #pragma unroll
        for (int bt = 0; bt < 2; bt++) {
            const int row = nw + bt * 16 + frow;
            badr[bt] = row * 128 + (((2 * ks + fc) ^ (row & 7)) << 4);
        }
        uint32_t ahf[4][4], bhf[2][4];
        #pragma unroll
        for (int mt = 0; mt < 4; mt++) LDSM_X4(ahf[mt], sb + aadr[mt]);
        #pragma unroll
        for (int bt = 0; bt < 2; bt++) LDSM_X4(bhf[bt], sb + 2 * 16384 + badr[bt]);
        #pragma unroll
        for (int mt = 0; mt < 4; mt++)
            #pragma unroll
            for (int nt = 0; nt < 4; nt++)
                mma_bf16(acc[mt][nt], ahf[mt],
                         bhf[nt >> 1][nt & 1], bhf[nt >> 1][(nt & 1) + 2]);
        uint32_t blf[2][4];
        #pragma unroll
        for (int bt = 0; bt < 2; bt++) LDSM_X4(blf[bt], sb + 3 * 16384 + badr[bt]);
        #pragma unroll
        for (int mt = 0; mt < 4; mt++)
            #pragma unroll
            for (int nt = 0; nt < 4; nt++)
                mma_bf16(acc[mt][nt], ahf[mt],
                         blf[nt >> 1][nt & 1], blf[nt >> 1][(nt & 1) + 2]);
        uint32_t alf[4][4];
        #pragma unroll
        for (int mt = 0; mt < 4; mt++) LDSM_X4(alf[mt], sb + 16384 + aadr[mt]);
        #pragma unroll
        for (int mt = 0; mt < 4; mt++)
            #pragma unroll
            for (int nt = 0; nt < 4; nt++)
                mma_bf16(acc[mt][nt], alf[mt],
                         bhf[nt >> 1][nt & 1], bhf[nt >> 1][(nt & 1) + 2]);
    }

    const int er = lane >> 2, ec = (lane & 3) * 2;
    float* ob = attn + (size_t)bh * Sc * Sc;
    #pragma unroll
    for (int mt = 0; mt < 4; mt++) {
        #pragma unroll
        for (int nt = 0; nt < 4; nt++) {
            const int r0 = i0 + mw + mt * 16 + er;
            const int col = j0 + nw + nt * 8 + ec;
            *(float2*)(ob + (size_t)r0 * Sc + col) =
                make_float2(acc[mt][nt][0], acc[mt][nt][1]);
            *(float2*)(ob + (size_t)(r0 + 8) * Sc + col) =
                make_float2(acc[mt][nt][2], acc[mt][nt][3]);
        }
    }
}

// ---------------------------------------------------------------------------
// Fused XL relative bias + row softmax — DIAGONAL-FUSED.
// Key identity: slab row r0 = 384 + 24*(i&15) - 24*h - (i>>4) = 384 + 24*d - a
// where d = (i&15) - h, a = i>>4. All (h,i) on a diagonal (fixed a,d) share
// one 98KB slab -> process the whole chain in one block; slab stays in L1.
// Persistent grid (296 blocks = 2/SM) keeps L1 footprint = 2 slabs + smem.
// ---------------------------------------------------------------------------
__global__ __launch_bounds__(128) void rpe_softmax_kernel(
    const __nv_bfloat16* __restrict__ qkvh, const __nv_bfloat16* __restrict__ qkvl,
    const float* __restrict__ rpe, float* __restrict__ attn)
{
    __shared__ unsigned long long Qp[256];   // [dd*4 + p] = (q[2p][dd], q[2p+1][dd])
    __shared__ float L[Bc][Sc];
    const int tid = threadIdx.x;
    const int wrp = tid >> 5, lane = tid & 31;

    for (int work = blockIdx.x; work < 24 * 31; work += gridDim.x) {
        const int a = work / 31;
        const int d = work % 31 - 15;
        const int h_lo = d < 0 ? -d : 0;
        const int h_hi = d > 0 ? 15 - d : 15;
        const float* rbase = rpe + (size_t)(384 + 24 * d - a) * 1024;

        for (int h = h_lo; h <= h_hi; h++) {
            const int i = 16 * a + h + d;
            // gather q (reconstruct from hi/lo, x8 undoes qk pre-scale)
            for (int t = tid; t < 256; t += 128) {
                const int p = t & 3, dd = t >> 2;
                const size_t i0x = (size_t)((2 * p) * Sc + i) * D3c + h * 192 + dd;
                const size_t i1x = (size_t)((2 * p + 1) * Sc + i) * D3c + h * 192 + dd;
                const float q0 = (__bfloat162float(qkvh[i0x]) + __bfloat162float(qkvl[i0x])) * 8.f;
                const float q1 = (__bfloat162float(qkvh[i1x]) + __bfloat162float(qkvl[i1x])) * 8.f;
                Qp[t] = packf2(q0, q1);
            }
            __syncthreads();

            unsigned long long acc2[3][4];
            #pragma unroll
            for (int jj = 0; jj < 3; jj++)
                #pragma unroll
                for (int p = 0; p < 4; p++) acc2[jj][p] = 0ull;

            #pragma unroll
            for (int c = 0; c < 16; c++) {
                unsigned long long qp[4][4];
                #pragma unroll
                for (int d2 = 0; d2 < 4; d2++)
                    #pragma unroll
                    for (int p = 0; p < 4; p++)
                        qp[d2][p] = Qp[(c * 4 + d2) * 4 + p];
                #pragma unroll
                for (int jj = 0; jj < 3; jj++) {
                    const int j = tid + jj * 128;
                    const float4 rv = *(const float4*)(rbase + (size_t)j * 64 + c * 4);
                    const unsigned long long s0 = packf2(rv.x, rv.x);
                    const unsigned long long s1 = packf2(rv.y, rv.y);
                    const unsigned long long s2 = packf2(rv.z, rv.z);
                    const unsigned long long s3 = packf2(rv.w, rv.w);
                    #pragma unroll
                    for (int p = 0; p < 4; p++) {
                        FFMA2(acc2[jj][p], qp[0][p], s0);
                        FFMA2(acc2[jj][p], qp[1][p], s1);
                        FFMA2(acc2[jj][p], qp[2][p], s2);
                        FFMA2(acc2[jj][p], qp[3][p], s3);
                    }
                }
            }
            #pragma unroll
            for (int jj = 0; jj < 3; jj++) {
                const int j = tid + jj * 128;
                #pragma unroll
                for (int p = 0; p < 4; p++) {
                    float lo, hi;
                    unpackf2(acc2[jj][p], lo, hi);
                    const int b0 = 2 * p, b1 = 2 * p + 1;
                    L[b0][j] = attn[((size_t)(b0 * Hc + h) * Sc + i) * Sc + j] + lo;
                    L[b1][j] = attn[((size_t)(b1 * Hc + h) * Sc + i) * Sc + j] + hi;
                }
            }
            __syncthreads();

            #pragma unroll
            for (int bb = 0; bb < 2; bb++) {
                const int b = wrp * 2 + bb;
                float v[12];
                float m = -1e30f;
                #pragma unroll
                for (int r = 0; r < 12; r++) { v[r] = L[b][lane + 32 * r]; m = fmaxf(m, v[r]); }
                #pragma unroll
                for (int o = 16; o > 0; o >>= 1) m = fmaxf(m, __shfl_xor_sync(0xffffffffu, m, o));
                float s = 0.f;
                #pragma unroll
                for (int r = 0; r < 12; r++) { v[r] = __expf(v[r] - m); s += v[r]; }
                #pragma unroll
                for (int o = 16; o > 0; o >>= 1) s += __shfl_xor_sync(0xffffffffu, s, o);
                const float inv = 1.0f / s;
                float* orow = attn + ((size_t)(b * Hc + h) * Sc + i) * Sc;
                #pragma unroll
                for (int r = 0; r < 12; r++) orow[lane + 32 * r] = v[r] * inv;
            }
            // no extra sync needed: next iteration's first barrier orders L/Qp reuse
        }
    }
}

// ---------------------------------------------------------------------------
// av HMMA: values = attn(fp32) @ v, 3-pass bf16 split. (unchanged)
// ---------------------------------------------------------------------------
#define AV_AROW 72
#define AV_ATILE (128 * AV_AROW * 4)
#define AV_VTILE 8192
#define AV_STAGE (AV_ATILE + 2 * AV_VTILE)
#define AV_SMEM  (2 * AV_STAGE)

__global__ __launch_bounds__(256, 2) void av_mma_kernel(
    const float* __restrict__ attn,
    const __nv_bfloat16* __restrict__ qkvh, const __nv_bfloat16* __restrict__ qkvl,
    __nv_bfloat16* __restrict__ vh_out, __nv_bfloat16* __restrict__ vl_out)
{
    extern __shared__ char smem[];
    const uint32_t sb = smem_u32(smem);
    float* sA_f = (float*)smem;
    const int tid = threadIdx.x, wid = tid >> 5, lane = tid & 31;
    const int bh = blockIdx.y, b = bh >> 4, h = bh & 15;
    const int i0 = blockIdx.x * 128;

    const float* abase = attn + ((size_t)bh * Sc + i0) * Sc;
    const __nv_bfloat16* vbase_h = qkvh + h * 192 + 128;
    const __nv_bfloat16* vbase_l = qkvl + h * 192 + 128;

    auto issue = [&](int ck) {
        if (ck >= 6) { CP_COMMIT(); return; }
        const uint32_t st = sb + (ck & 1) * AV_STAGE;
        const int j0 = ck * 64;
        for (int idx = tid; idx < 2048; idx += 256) {
            const int row = idx >> 4, c = idx & 15;
            CP_ASYNC16(st + row * (AV_AROW * 4) + c * 16,
                       abase + (size_t)row * Sc + j0 + c * 4);
        }
        for (int idx = tid; idx < 512; idx += 256) {
            const int row = idx >> 3, c = idx & 7;
            const uint32_t sw = row * 128 + ((c ^ (row & 7)) << 4);
            const size_t go = (size_t)(b * Sc + j0 + row) * D3c + c * 8;
            CP_ASYNC16(st + AV_ATILE + sw, vbase_h + go);
            CP_ASYNC16(st + AV_ATILE + AV_VTILE + sw, vbase_l + go);
        }
        CP_COMMIT();
    };

    const int wm = (wid & 3) * 32;
    const int wn = (wid >> 2) * 32;
    const int er = lane >> 2;
    const int ecb = (lane & 3) * 2;
    const int krow = (lane & 7) | ((lane & 16) >> 1);
    const int colc = (lane >> 3) & 1;

    float acc[2][4][4];
    #pragma unroll
    for (int i = 0; i < 2; i++)
        #pragma unroll
        for (int j = 0; j < 4; j++)
            #pragma unroll
            for (int r = 0; r < 4; r++) acc[i][j][r] = 0.f;

    issue(0);
    for (int ck = 0; ck < 6; ck++) {
        issue(ck + 1);
        CP_WAIT1();
        __syncthreads();
        const int stg = (ck & 1);
        float* sA = sA_f + stg * (AV_STAGE / 4);
        const uint32_t vt_h = sb + stg * AV_STAGE + AV_ATILE;
        const uint32_t vt_l = vt_h + AV_VTILE;
        #pragma unroll
        for (int ks = 0; ks < 4; ks++) {
            uint32_t ahf[2][4], alf[2][4];
            #pragma unroll
            for (int mt = 0; mt < 2; mt++) {
                const int r_ = wm + mt * 16 + er;
                const int cb = ks * 16 + ecb;
                float2 x0 = *(float2*)(sA + (size_t)r_ * AV_AROW + cb);
                float2 x1 = *(float2*)(sA + (size_t)(r_ + 8) * AV_AROW + cb);
                float2 x2 = *(float2*)(sA + (size_t)r_ * AV_AROW + cb + 8);
                float2 x3 = *(float2*)(sA + (size_t)(r_ + 8) * AV_AROW + cb + 8);
                pack_hilo(x0.x, x0.y, ahf[mt][0], alf[mt][0]);
                pack_hilo(x1.x, x1.y, ahf[mt][1], alf[mt][1]);
                pack_hilo(x2.x, x2.y, ahf[mt][2], alf[mt][2]);
                pack_hilo(x3.x, x3.y, ahf[mt][3], alf[mt][3]);
            }
            uint32_t badr[2];
            #pragma unroll
            for (int bt = 0; bt < 2; bt++) {
                const int row = ks * 16 + krow;
                const int c = (wn >> 3) + bt * 2 + colc;
                badr[bt] = row * 128 + ((c ^ (row & 7)) << 4);
            }
            uint32_t bhf[2][4], blf[2][4];
            #pragma unroll
            for (int bt = 0; bt < 2; bt++) LDSM_X4_T(bhf[bt], vt_h + badr[bt]);
            #pragma unroll
            for (int bt = 0; bt < 2; bt++) LDSM_X4_T(blf[bt], vt_l + badr[bt]);
            #pragma unroll
            for (int mt = 0; mt < 2; mt++)
                #pragma unroll
                for (int nt = 0; nt < 4; nt++)
                    mma_bf16(acc[mt][nt], ahf[mt],
                             bhf[nt >> 1][nt & 1], bhf[nt >> 1][(nt & 1) + 2]);
            #pragma unroll
            for (int mt = 0; mt < 2; mt++)
                #pragma unroll
                for (int nt = 0; nt < 4; nt++)
                    mma_bf16(acc[mt][nt], alf[mt],
                             bhf[nt >> 1][nt & 1], bhf[nt >> 1][(nt & 1) + 2]);
            #pragma unroll
            for (int mt = 0; mt < 2; mt++)
                #pragma unroll
                for (int nt = 0; nt < 4; nt++)
                    mma_bf16(acc[mt][nt], ahf[mt],
                             blf[nt >> 1][nt & 1], blf[nt >> 1][(nt & 1) + 2]);
        }
        __syncthreads();
    }

    const int ec = (lane & 3) * 2;
    #pragma unroll
    for (int mt = 0; mt < 2; mt++) {
        #pragma unroll
        for (int nt = 0; nt < 4; nt++) {
            const int row = i0 + wm + mt * 16 + er;
            const int col = h * 64 + wn + nt * 8 + ec;
            const size_t o0 = (size_t)(b * Sc + row) * Dc + col;
            const size_t o1 = (size_t)(b * Sc + row + 8) * Dc + col;
            split2(acc[mt][nt][0], acc[mt][nt][1], vh_out + o0, vl_out + o0);
            split2(acc[mt][nt][2], acc[mt][nt][3], vh_out + o1, vl_out + o1);
        }
    }
}

// ---------------------------------------------------------------------------
extern "C" void kernel_launch(void* const* d_in, const int* in_sizes, int n_in,
                              void* d_out, int out_size)
{
    const float* x     = (const float*)d_in[0];
    const float* qkv_w = (const float*)d_in[1];
    const float* qkv_b = (const float*)d_in[2];
    const float* out_w = (const float*)d_in[3];
    const float* out_b = (const float*)d_in[4];
    const float* rpe   = (const float*)d_in[5];

    float* attnscr;
    __nv_bfloat16 *ah, *al, *wqh, *wql, *woh, *wol, *qkvh, *qkvl;
    cudaGetSymbolAddress((void**)&attnscr, g_attn);
    cudaGetSymbolAddress((void**)&ah, g_ah);
    cudaGetSymbolAddress((void**)&al, g_al);
    cudaGetSymbolAddress((void**)&wqh, g_wqh);
    cudaGetSymbolAddress((void**)&wql, g_wql);
    cudaGetSymbolAddress((void**)&woh, g_woh);
    cudaGetSymbolAddress((void**)&wol, g_wol);
    cudaGetSymbolAddress((void**)&qkvh, g_qkvh);
    cudaGetSymbolAddress((void**)&qkvl, g_qkvl);

    float* out = (float*)d_out;
    const long OUT_E = (long)BSc * Dc;
    const long ATT_E = (long)Bc * Hc * Sc * Sc;
    float* attn = ((long)out_size >= OUT_E + ATT_E) ? (out + OUT_E) : attnscr;

    cudaFuncSetAttribute(mma_gemm_kernel,
                         cudaFuncAttributeMaxDynamicSharedMemorySize, GSMEM);
    cudaFuncSetAttribute(qk_mma_kernel,
                         cudaFuncAttributeMaxDynamicSharedMemorySize, QK_SMEM);
    cudaFuncSetAttribute(av_mma_kernel,
                         cudaFuncAttributeMaxDynamicSharedMemorySize, AV_SMEM);

    const int n4x = BSc * Dc / 4;
    split_kernel<<<(n4x + 255) / 256, 256>>>(x, ah, al, n4x);
    transpose_split_kernel<<<dim3(D3c / 32, Dc / 32), dim3(32, 8)>>>(qkv_w, wqh, wql, Dc, D3c);
    transpose_split_kernel<<<dim3(Dc / 32, Dc / 32), dim3(32, 8)>>>(out_w, woh, wol, Dc, Dc);

    // 1) qkv: emit bf16 hi/lo (q cols pre-scaled 1/8)
    mma_gemm_kernel<<<dim3(D3c / 128, BSc / 128), 256, GSMEM>>>(
        ah, al, wqh, wql, qkv_b, nullptr, qkvh, qkvl, 1, BSc, D3c, Dc);
    // 2) logits = (q/8) . k
    qk_mma_kernel<<<dim3(3, 3, Bc * Hc), 256, QK_SMEM>>>(qkvh, qkvl, attn);
    // 3+4) rpe bias + softmax (diagonal-fused, persistent 2 blocks/SM)
    rpe_softmax_kernel<<<296, 128>>>(qkvh, qkvl, rpe, attn);
    // 5) values = attn @ v -> bf16 hi/lo
    av_mma_kernel<<<dim3(3, Bc * Hc), 256, AV_SMEM>>>(attn, qkvh, qkvl, ah, al);
    // 6) out = values @ out_w + out_b
    mma_gemm_kernel<<<dim3(Dc / 128, BSc / 128), 256, GSMEM>>>(
        ah, al, woh, wol, out_b, out, nullptr, nullptr, 0, BSc, Dc, Dc);
}

// round 9
// speedup vs baseline: 1.0645x; 1.0645x over previous
#include <cuda_runtime.h>
#include <cuda_bf16.h>
#include <cstdint>

#define Bc 8
#define Sc 384
#define Dc 1024
#define Hc 16
#define HDc 64
#define D3c 3072
#define BSc 3072   // B*S

// ---------------------------------------------------------------------------
// Scratch (static device globals; no runtime allocation)
// ---------------------------------------------------------------------------
__device__ float g_attn[(size_t)Bc * Hc * Sc * Sc];   // fallback attn buffer
__device__ __align__(16) __nv_bfloat16 g_ah[(size_t)BSc * Dc];    // A hi (x, then vals)
__device__ __align__(16) __nv_bfloat16 g_al[(size_t)BSc * Dc];    // A lo
__device__ __align__(16) __nv_bfloat16 g_wqh[(size_t)D3c * Dc];   // qkv_w^T hi [N,K]
__device__ __align__(16) __nv_bfloat16 g_wql[(size_t)D3c * Dc];   // qkv_w^T lo
__device__ __align__(16) __nv_bfloat16 g_woh[(size_t)Dc * Dc];    // out_w^T hi
__device__ __align__(16) __nv_bfloat16 g_wol[(size_t)Dc * Dc];    // out_w^T lo
__device__ __align__(16) __nv_bfloat16 g_qkvh[(size_t)BSc * D3c]; // qkv hi (q pre-scaled /8)
__device__ __align__(16) __nv_bfloat16 g_qkvl[(size_t)BSc * D3c]; // qkv lo

// ---------------------------------------------------------------------------
// Baseline-PTX helpers
// ---------------------------------------------------------------------------
__device__ __forceinline__ uint32_t smem_u32(const void* p) {
    uint32_t a;
    asm("{ .reg .u64 t; cvta.to.shared.u64 t, %1; cvt.u32.u64 %0, t; }" : "=r"(a) : "l"(p));
    return a;
}
#define CP_ASYNC16(sm, gp) \
    asm volatile("cp.async.cg.shared.global [%0], [%1], 16;" :: "r"(sm), "l"(gp))
#define CP_COMMIT() asm volatile("cp.async.commit_group;" ::: "memory")
#define CP_WAIT0()  asm volatile("cp.async.wait_group 0;" ::: "memory")
#define CP_WAIT1()  asm volatile("cp.async.wait_group 1;" ::: "memory")

#define LDSM_X4(r, a) \
    asm volatile("ldmatrix.sync.aligned.m8n8.x4.shared.b16 {%0,%1,%2,%3}, [%4];" \
        : "=r"((r)[0]), "=r"((r)[1]), "=r"((r)[2]), "=r"((r)[3]) : "r"(a))
#define LDSM_X4_T(r, a) \
    asm volatile("ldmatrix.sync.aligned.m8n8.x4.trans.shared.b16 {%0,%1,%2,%3}, [%4];" \
        : "=r"((r)[0]), "=r"((r)[1]), "=r"((r)[2]), "=r"((r)[3]) : "r"(a))

__device__ __forceinline__ void mma_bf16(float* d, const uint32_t* a,
                                         uint32_t b0, uint32_t b1) {
    asm volatile(
        "mma.sync.aligned.m16n8k16.row.col.f32.bf16.bf16.f32 "
        "{%0,%1,%2,%3}, {%4,%5,%6,%7}, {%8,%9}, {%0,%1,%2,%3};"
        : "+f"(d[0]), "+f"(d[1]), "+f"(d[2]), "+f"(d[3])
        : "r"(a[0]), "r"(a[1]), "r"(a[2]), "r"(a[3]), "r"(b0), "r"(b1));
}

// packed f32x2 (Blackwell FFMA2; baseline sm_100+ PTX)
__device__ __forceinline__ unsigned long long packf2(float x, float y) {
    unsigned long long r;
    asm("mov.b64 %0, {%1, %2};" : "=l"(r) : "f"(x), "f"(y));
    return r;
}
#define FFMA2(acc, a, b) \
    asm("fma.rn.f32x2 %0, %1, %2, %0;" : "+l"(acc) : "l"(a), "l"(b))
__device__ __forceinline__ void unpackf2(unsigned long long v, float& lo, float& hi) {
    asm("mov.b64 {%0, %1}, %2;" : "=f"(lo), "=f"(hi) : "l"(v));
}

__device__ __forceinline__ void split2(float x, float y,
                                       __nv_bfloat16* ph, __nv_bfloat16* pl) {
    __nv_bfloat16 hx = __float2bfloat16(x), hy = __float2bfloat16(y);
    *(__nv_bfloat162*)ph = __nv_bfloat162(hx, hy);
    *(__nv_bfloat162*)pl = __nv_bfloat162(
        __float2bfloat16(x - __bfloat162float(hx)),
        __float2bfloat16(y - __bfloat162float(hy)));
}
__device__ __forceinline__ void pack_hilo(float x, float y,
                                          uint32_t& hi, uint32_t& lo) {
    __nv_bfloat16 hx = __float2bfloat16(x), hy = __float2bfloat16(y);
    __nv_bfloat162 h2(hx, hy);
    __nv_bfloat162 l2(__float2bfloat16(x - __bfloat162float(hx)),
                      __float2bfloat16(y - __bfloat162float(hy)));
    hi = *(uint32_t*)&h2;
    lo = *(uint32_t*)&l2;
}

// ---------------------------------------------------------------------------
// HMMA bf16-split GEMM: C = (Ah+Al)@(Bh+Bl)^T + bias
// Single-sync mainloop: wait group -> barrier -> issue(it+2) -> compute(it).
// ---------------------------------------------------------------------------
#define TILE_B 8192
#define BUF_B  (4 * TILE_B)
#define NSTAGE 3
#define GSMEM  (NSTAGE * BUF_B)   // 96 KB

__global__ __launch_bounds__(256, 2) void mma_gemm_kernel(
    const __nv_bfloat16* __restrict__ Ah, const __nv_bfloat16* __restrict__ Al,
    const __nv_bfloat16* __restrict__ Bh, const __nv_bfloat16* __restrict__ Bl,
    const float* __restrict__ bias, float* __restrict__ C,
    __nv_bfloat16* __restrict__ Ch, __nv_bfloat16* __restrict__ Cl,
    int qkv_mode, int M, int N, int K)
{
    extern __shared__ char smem[];
    const uint32_t sbase = smem_u32(smem);
    const int tid  = threadIdx.x;
    const int wid  = tid >> 5;
    const int lane = tid & 31;
    const int m0 = blockIdx.y * 128;
    const int n0 = blockIdx.x * 128;
    const int mw = (wid & 1) * 64;
    const int nw = (wid >> 1) * 32;

    const int lrow = tid >> 1;
    const int c0   = (tid & 1) * 2;
    const int sw0  = (lrow >> 1) & 3;
    const __nv_bfloat16* gAh = Ah + (size_t)(m0 + lrow) * K;
    const __nv_bfloat16* gAl = Al + (size_t)(m0 + lrow) * K;
    const __nv_bfloat16* gBh = Bh + (size_t)(n0 + lrow) * K;
    const __nv_bfloat16* gBl = Bl + (size_t)(n0 + lrow) * K;
    const uint32_t soff0 = lrow * 64 + (((c0 + 0) ^ sw0) << 4);
    const uint32_t soff1 = lrow * 64 + (((c0 + 1) ^ sw0) << 4);

    const int NK = K >> 5;

    auto issue = [&](int it) {
        if (it < NK) {
            const uint32_t tb = sbase + (it % NSTAGE) * BUF_B;
            const int k0 = it << 5;
            CP_ASYNC16(tb + 0 * TILE_B + soff0, gAh + k0 + (c0 + 0) * 8);
            CP_ASYNC16(tb + 0 * TILE_B + soff1, gAh + k0 + (c0 + 1) * 8);
            CP_ASYNC16(tb + 1 * TILE_B + soff0, gAl + k0 + (c0 + 0) * 8);
            CP_ASYNC16(tb + 1 * TILE_B + soff1, gAl + k0 + (c0 + 1) * 8);
            CP_ASYNC16(tb + 2 * TILE_B + soff0, gBh + k0 + (c0 + 0) * 8);
            CP_ASYNC16(tb + 2 * TILE_B + soff1, gBh + k0 + (c0 + 1) * 8);
            CP_ASYNC16(tb + 3 * TILE_B + soff0, gBl + k0 + (c0 + 0) * 8);
            CP_ASYNC16(tb + 3 * TILE_B + soff1, gBl + k0 + (c0 + 1) * 8);
        }
        CP_COMMIT();
    };

    const int frow = lane & 15;
    const int fc   = lane >> 4;
    auto fr_addr = [&](int rbase) -> uint32_t {
        const int row = rbase + frow;
        return (uint32_t)(row * 64 + ((fc ^ ((row >> 1) & 3)) << 4));
    };
    const uint32_t aoff = fr_addr(mw);
    const uint32_t boff = fr_addr(nw);

    float acc[4][4][4];
    #pragma unroll
    for (int i = 0; i < 4; i++)
        #pragma unroll
        for (int j = 0; j < 4; j++)
            #pragma unroll
            for (int r = 0; r < 4; r++) acc[i][j][r] = 0.f;

    issue(0); issue(1);

    for (int it = 0; it < NK; it++) {
        CP_WAIT1();
        __syncthreads();
        issue(it + 2);   // buffer (it+2)%3 == (it-1)%3, consumed by all at the barrier
        const uint32_t tb = sbase + (it % NSTAGE) * BUF_B;
        #pragma unroll
        for (int ks = 0; ks < 2; ks++) {
            const uint32_t kx = ks ? 32u : 0u;
            uint32_t ahf[4][4], bhf[2][4];
            #pragma unroll
            for (int mt = 0; mt < 4; mt++)
                LDSM_X4(ahf[mt], tb + ((aoff + mt * 1024) ^ kx));
            #pragma unroll
            for (int bt = 0; bt < 2; bt++)
                LDSM_X4(bhf[bt], tb + 2 * TILE_B + ((boff + bt * 1024) ^ kx));
            // pass 0: Ah*Bh
            #pragma unroll
            for (int mt = 0; mt < 4; mt++)
                #pragma unroll
                for (int nt = 0; nt < 4; nt++)
                    mma_bf16(acc[mt][nt], ahf[mt],
                             bhf[nt >> 1][nt & 1], bhf[nt >> 1][(nt & 1) + 2]);
            // load Bl while pass0 drains
            uint32_t blf[2][4];
            #pragma unroll
            for (int bt = 0; bt < 2; bt++)
                LDSM_X4(blf[bt], tb + 3 * TILE_B + ((boff + bt * 1024) ^ kx));
            // pass 1: Ah*Bl
            #pragma unroll
            for (int mt = 0; mt < 4; mt++)
                #pragma unroll
                for (int nt = 0; nt < 4; nt++)
                    mma_bf16(acc[mt][nt], ahf[mt],
                             blf[nt >> 1][nt & 1], blf[nt >> 1][(nt & 1) + 2]);
            // load Al while pass1 drains
            uint32_t alf[4][4];
            #pragma unroll
            for (int mt = 0; mt < 4; mt++)
                LDSM_X4(alf[mt], tb + TILE_B + ((aoff + mt * 1024) ^ kx));
            // pass 2: Al*Bh
            #pragma unroll
            for (int mt = 0; mt < 4; mt++)
                #pragma unroll
                for (int nt = 0; nt < 4; nt++)
                    mma_bf16(acc[mt][nt], alf[mt],
                             bhf[nt >> 1][nt & 1], bhf[nt >> 1][(nt & 1) + 2]);
        }
    }

    const int er = lane >> 2;
    const int ec = (lane & 3) * 2;
    #pragma unroll
    for (int mt = 0; mt < 4; mt++) {
        #pragma unroll
        for (int nt = 0; nt < 4; nt++) {
            const int col = n0 + nw + nt * 8 + ec;
            const float bx = __ldg(&bias[col]);
            const float by = __ldg(&bias[col + 1]);
            const int r0 = m0 + mw + mt * 16 + er;
            float2 v0 = make_float2(acc[mt][nt][0] + bx, acc[mt][nt][1] + by);
            float2 v1 = make_float2(acc[mt][nt][2] + bx, acc[mt][nt][3] + by);
            if (C) {
                *(float2*)(C + (size_t)r0 * N + col) = v0;
                *(float2*)(C + (size_t)(r0 + 8) * N + col) = v1;
            }
            if (Ch) {
                const float s = (qkv_mode && (((col >> 6) % 3) == 0)) ? 0.125f : 1.0f;
                split2(v0.x * s, v0.y * s, Ch + (size_t)r0 * N + col,
                       Cl + (size_t)r0 * N + col);
                split2(v1.x * s, v1.y * s, Ch + (size_t)(r0 + 8) * N + col,
                       Cl + (size_t)(r0 + 8) * N + col);
            }
        }
    }
}

// ---------------------------------------------------------------------------
// fp32 -> bf16 hi/lo split (vectorized by 4)
// ---------------------------------------------------------------------------
__global__ __launch_bounds__(256) void split_kernel(
    const float* __restrict__ src, __nv_bfloat16* __restrict__ hi,
    __nv_bfloat16* __restrict__ lo, int n4)
{
    int i = blockIdx.x * blockDim.x + threadIdx.x;
    if (i >= n4) return;
    float4 v = ((const float4*)src)[i];
    split2(v.x, v.y, hi + 4 * (size_t)i, lo + 4 * (size_t)i);
    split2(v.z, v.w, hi + 4 * (size_t)i + 2, lo + 4 * (size_t)i + 2);
}

// ---------------------------------------------------------------------------
// W[K,N] -> Wt[N,K] with bf16 hi/lo split
// ---------------------------------------------------------------------------
__global__ __launch_bounds__(256) void transpose_split_kernel(
    const float* __restrict__ W, __nv_bfloat16* __restrict__ Th,
    __nv_bfloat16* __restrict__ Tl, int K, int N)
{
    __shared__ float t[32][33];
    const int n0 = blockIdx.x * 32, k0 = blockIdx.y * 32;
    const int tx = threadIdx.x, ty = threadIdx.y;
    #pragma unroll
    for (int r = 0; r < 4; r++)
        t[ty + 8 * r][tx] = W[(size_t)(k0 + ty + 8 * r) * N + n0 + tx];
    __syncthreads();
    #pragma unroll
    for (int r = 0; r < 4; r++) {
        float v = t[tx][ty + 8 * r];
        __nv_bfloat16 h = __float2bfloat16(v);
        __nv_bfloat16 l = __float2bfloat16(v - __bfloat162float(h));
        size_t o = (size_t)(n0 + ty + 8 * r) * K + k0 + tx;
        Th[o] = h; Tl[o] = l;
    }
}

// ---------------------------------------------------------------------------
// qk HMMA: logits = (scaled q).k, 3-pass bf16 split, interleaved LDSM.
// ---------------------------------------------------------------------------
#define QK_SMEM (4 * 16384)

__global__ __launch_bounds__(256, 2) void qk_mma_kernel(
    const __nv_bfloat16* __restrict__ qkvh, const __nv_bfloat16* __restrict__ qkvl,
    float* __restrict__ attn)
{
    extern __shared__ char smem[];
    const uint32_t sb = smem_u32(smem);
    const int tid = threadIdx.x, wid = tid >> 5, lane = tid & 31;
    const int bh = blockIdx.z, b = bh >> 4, h = bh & 15;
    const int i0 = blockIdx.y * 128, j0 = blockIdx.x * 128;

    #pragma unroll
    for (int t = 0; t < 4; t++) {
        const __nv_bfloat16* base = (t & 1) ? qkvl : qkvh;
        const int roff = (t < 2) ? i0 : j0;
        const int coff = h * 192 + ((t < 2) ? 0 : 64);
        for (int idx = tid; idx < 1024; idx += 256) {
            const int row = idx >> 3, c = idx & 7;
            const uint32_t dst = sb + t * 16384 + row * 128 + ((c ^ (row & 7)) << 4);
            CP_ASYNC16(dst, base + (size_t)(b * Sc + roff + row) * D3c + coff + c * 8);
        }
    }
    CP_COMMIT(); CP_WAIT0();
    __syncthreads();

    const int mw = (wid & 1) * 64;
    const int nw = (wid >> 1) * 32;
    const int frow = lane & 15, fc = lane >> 4;

    float acc[4][4][4];
    #pragma unroll
    for (int i = 0; i < 4; i++)
        #pragma unroll
        for (int j = 0; j < 4; j++)
            #pragma unroll
            for (int r = 0; r < 4; r++) acc[i][j][r] = 0.f;

    #pragma unroll
    for (int ks = 0; ks < 4; ks++) {
        uint32_t aadr[4], badr[2];
        #pragma unroll
        for (int mt = 0; mt < 4; mt++) {
            const int row = mw + mt * 16 + frow;
            aadr[mt] = row * 128 + (((2 * ks + fc) ^ (row & 7)) << 4);
        }
        #pragma unroll
        for (int bt = 0; bt < 2; bt++) {
            const int row = nw + bt * 16 + frow;
            badr[bt] = row * 128 + (((2 * ks + fc) ^ (row & 7)) << 4);
        }
        uint32_t ahf[4][4], bhf[2][4];
        #pragma unroll
        for (int mt = 0; mt < 4; mt++) LDSM_X4(ahf[mt], sb + aadr[mt]);
        #pragma unroll
        for (int bt = 0; bt < 2; bt++) LDSM_X4(bhf[bt], sb + 2 * 16384 + badr[bt]);
        #pragma unroll
        for (int mt = 0; mt < 4; mt++)
            #pragma unroll
            for (int nt = 0; nt < 4; nt++)
                mma_bf16(acc[mt][nt], ahf[mt],
                         bhf[nt >> 1][nt & 1], bhf[nt >> 1][(nt & 1) + 2]);
        uint32_t blf[2][4];
        #pragma unroll
        for (int bt = 0; bt < 2; bt++) LDSM_X4(blf[bt], sb + 3 * 16384 + badr[bt]);
        #pragma unroll
        for (int mt = 0; mt < 4; mt++)
            #pragma unroll
            for (int nt = 0; nt < 4; nt++)
                mma_bf16(acc[mt][nt], ahf[mt],
                         blf[nt >> 1][nt & 1], blf[nt >> 1][(nt & 1) + 2]);
        uint32_t alf[4][4];
        #pragma unroll
        for (int mt = 0; mt < 4; mt++) LDSM_X4(alf[mt], sb + 16384 + aadr[mt]);
        #pragma unroll
        for (int mt = 0; mt < 4; mt++)
            #pragma unroll
            for (int nt = 0; nt < 4; nt++)
                mma_bf16(acc[mt][nt], alf[mt],
                         bhf[nt >> 1][nt & 1], bhf[nt >> 1][(nt & 1) + 2]);
    }

    const int er = lane >> 2, ec = (lane & 3) * 2;
    float* ob = attn + (size_t)bh * Sc * Sc;
    #pragma unroll
    for (int mt = 0; mt < 4; mt++) {
        #pragma unroll
        for (int nt = 0; nt < 4; nt++) {
            const int r0 = i0 + mw + mt * 16 + er;
            const int col = j0 + nw + nt * 8 + ec;
            *(float2*)(ob + (size_t)r0 * Sc + col) =
                make_float2(acc[mt][nt][0], acc[mt][nt][1]);
            *(float2*)(ob + (size_t)(r0 + 8) * Sc + col) =
                make_float2(acc[mt][nt][2], acc[mt][nt][3]);
        }
    }
}

// ---------------------------------------------------------------------------
// Fused XL relative bias + row softmax — diagonal-chunked.
// r0 = 384 + 24*d - a with d=(i&15)-h, a=i>>4: all (h,i) on a diagonal share
// one 98KB slab. grid = (744 diagonals, 2 half-chains): each block does <=8
// chain items, so slab L2 traffic drops ~4-8x while ~1100 blocks keep
// residency high (~8+ blocks/SM), unlike R8's 296-block launch.
// ---------------------------------------------------------------------------
__global__ __launch_bounds__(128) void rpe_softmax_kernel(
    const __nv_bfloat16* __restrict__ qkvh, const __nv_bfloat16* __restrict__ qkvl,
    const float* __restrict__ rpe, float* __restrict__ attn)
{
    const int a = blockIdx.x / 31;
    const int d = blockIdx.x % 31 - 15;
    const int h_lo = d < 0 ? -d : 0;
    const int h_hi = d > 0 ? 15 - d : 15;
    const int hs = h_lo + 8 * blockIdx.y;
    const int he = (h_hi < hs + 7) ? h_hi : (hs + 7);
    if (hs > h_hi) return;
    const float* rbase = rpe + (size_t)(384 + 24 * d - a) * 1024;

    __shared__ unsigned long long Qp[256];   // [dd*4 + p] = (q[2p][dd], q[2p+1][dd])
    __shared__ float L[Bc][Sc];
    const int tid = threadIdx.x;
    const int wrp = tid >> 5, lane = tid & 31;

    for (int h = hs; h <= he; h++) {
        const int i = 16 * a + h + d;
        for (int t = tid; t < 256; t += 128) {
            const int p = t & 3, dd = t >> 2;
            const size_t i0x = (size_t)((2 * p) * Sc + i) * D3c + h * 192 + dd;
            const size_t i1x = (size_t)((2 * p + 1) * Sc + i) * D3c + h * 192 + dd;
            const float q0 = (__bfloat162float(qkvh[i0x]) + __bfloat162float(qkvl[i0x])) * 8.f;
            const float q1 = (__bfloat162float(qkvh[i1x]) + __bfloat162float(qkvl[i1x])) * 8.f;
            Qp[t] = packf2(q0, q1);
        }
        __syncthreads();

        unsigned long long acc2[3][4];
        #pragma unroll
        for (int jj = 0; jj < 3; jj++)
            #pragma unroll
            for (int p = 0; p < 4; p++) acc2[jj][p] = 0ull;

        #pragma unroll
        for (int c = 0; c < 16; c++) {
            unsigned long long qp[4][4];
            #pragma unroll
            for (int d2 = 0; d2 < 4; d2++)
                #pragma unroll
                for (int p = 0; p < 4; p++)
                    qp[d2][p] = Qp[(c * 4 + d2) * 4 + p];
            #pragma unroll
            for (int jj = 0; jj < 3; jj++) {
                const int j = tid + jj * 128;
                const float4 rv = *(const float4*)(rbase + (size_t)j * 64 + c * 4);
                const unsigned long long s0 = packf2(rv.x, rv.x);
                const unsigned long long s1 = packf2(rv.y, rv.y);
                const unsigned long long s2 = packf2(rv.z, rv.z);
                const unsigned long long s3 = packf2(rv.w, rv.w);
                #pragma unroll
                for (int p = 0; p < 4; p++) {
                    FFMA2(acc2[jj][p], qp[0][p], s0);
                    FFMA2(acc2[jj][p], qp[1][p], s1);
                    FFMA2(acc2[jj][p], qp[2][p], s2);
                    FFMA2(acc2[jj][p], qp[3][p], s3);
                }
            }
        }
        #pragma unroll
        for (int jj = 0; jj < 3; jj++) {
            const int j = tid + jj * 128;
            #pragma unroll
            for (int p = 0; p < 4; p++) {
                float lo, hi;
                unpackf2(acc2[jj][p], lo, hi);
                const int b0 = 2 * p, b1 = 2 * p + 1;
                L[b0][j] = attn[((size_t)(b0 * Hc + h) * Sc + i) * Sc + j] + lo;
                L[b1][j] = attn[((size_t)(b1 * Hc + h) * Sc + i) * Sc + j] + hi;
            }
        }
        __syncthreads();

        #pragma unroll
        for (int bb = 0; bb < 2; bb++) {
            const int b = wrp * 2 + bb;
            float v[12];
            float m = -1e30f;
            #pragma unroll
            for (int r = 0; r < 12; r++) { v[r] = L[b][lane + 32 * r]; m = fmaxf(m, v[r]); }
            #pragma unroll
            for (int o = 16; o > 0; o >>= 1) m = fmaxf(m, __shfl_xor_sync(0xffffffffu, m, o));
            float s = 0.f;
            #pragma unroll
            for (int r = 0; r < 12; r++) { v[r] = __expf(v[r] - m); s += v[r]; }
            #pragma unroll
            for (int o = 16; o > 0; o >>= 1) s += __shfl_xor_sync(0xffffffffu, s, o);
            const float inv = 1.0f / s;
            float* orow = attn + ((size_t)(b * Hc + h) * Sc + i) * Sc;
            #pragma unroll
            for (int r = 0; r < 12; r++) orow[lane + 32 * r] = v[r] * inv;
        }
        __syncthreads();
    }
}

// ---------------------------------------------------------------------------
// av HMMA: values = attn(fp32) @ v, 3-pass bf16 split. (unchanged)
// ---------------------------------------------------------------------------
#define AV_AROW 72
#define AV_ATILE (128 * AV_AROW * 4)
#define AV_VTILE 8192
#define AV_STAGE (AV_ATILE + 2 * AV_VTILE)
#define AV_SMEM  (2 * AV_STAGE)

__global__ __launch_bounds__(256, 2) void av_mma_kernel(
    const float* __restrict__ attn,
    const __nv_bfloat16* __restrict__ qkvh, const __nv_bfloat16* __restrict__ qkvl,
    __nv_bfloat16* __restrict__ vh_out, __nv_bfloat16* __restrict__ vl_out)
{
    extern __shared__ char smem[];
    const uint32_t sb = smem_u32(smem);
    float* sA_f = (float*)smem;
    const int tid = threadIdx.x, wid = tid >> 5, lane = tid & 31;
    const int bh = blockIdx.y, b = bh >> 4, h = bh & 15;
    const int i0 = blockIdx.x * 128;

    const float* abase = attn + ((size_t)bh * Sc + i0) * Sc;
    const __nv_bfloat16* vbase_h = qkvh + h * 192 + 128;
    const __nv_bfloat16* vbase_l = qkvl + h * 192 + 128;

    auto issue = [&](int ck) {
        if (ck >= 6) { CP_COMMIT(); return; }
        const uint32_t st = sb + (ck & 1) * AV_STAGE;
        const int j0 = ck * 64;
        for (int idx = tid; idx < 2048; idx += 256) {
            const int row = idx >> 4, c = idx & 15;
            CP_ASYNC16(st + row * (AV_AROW * 4) + c * 16,
                       abase + (size_t)row * Sc + j0 + c * 4);
        }
        for (int idx = tid; idx < 512; idx += 256) {
            const int row = idx >> 3, c = idx & 7;
            const uint32_t sw = row * 128 + ((c ^ (row & 7)) << 4);
            const size_t go = (size_t)(b * Sc + j0 + row) * D3c + c * 8;
            CP_ASYNC16(st + AV_ATILE + sw, vbase_h + go);
            CP_ASYNC16(st + AV_ATILE + AV_VTILE + sw, vbase_l + go);
        }
        CP_COMMIT();
    };

    const int wm = (wid & 3) * 32;
    const int wn = (wid >> 2) * 32;
    const int er = lane >> 2;
    const int ecb = (lane & 3) * 2;
    const int krow = (lane & 7) | ((lane & 16) >> 1);
    const int colc = (lane >> 3) & 1;

    float acc[2][4][4];
    #pragma unroll
    for (int i = 0; i < 2; i++)
        #pragma unroll
        for (int j = 0; j < 4; j++)
            #pragma unroll
            for (int r = 0; r < 4; r++) acc[i][j][r] = 0.f;

    issue(0);
    for (int ck = 0; ck < 6; ck++) {
        issue(ck + 1);
        CP_WAIT1();
        __syncthreads();
        const int stg = (ck & 1);
        float* sA = sA_f + stg * (AV_STAGE / 4);
        const uint32_t vt_h = sb + stg * AV_STAGE + AV_ATILE;
        const uint32_t vt_l = vt_h + AV_VTILE;
        #pragma unroll
        for (int ks = 0; ks < 4; ks++) {
            uint32_t ahf[2][4], alf[2][4];
            #pragma unroll
            for (int mt = 0; mt < 2; mt++) {
                const int r_ = wm + mt * 16 + er;
                const int cb = ks * 16 + ecb;
                float2 x0 = *(float2*)(sA + (size_t)r_ * AV_AROW + cb);
                float2 x1 = *(float2*)(sA + (size_t)(r_ + 8) * AV_AROW + cb);
                float2 x2 = *(float2*)(sA + (size_t)r_ * AV_AROW + cb + 8);
                float2 x3 = *(float2*)(sA + (size_t)(r_ + 8) * AV_AROW + cb + 8);
                pack_hilo(x0.x, x0.y, ahf[mt][0], alf[mt][0]);
                pack_hilo(x1.x, x1.y, ahf[mt][1], alf[mt][1]);
                pack_hilo(x2.x, x2.y, ahf[mt][2], alf[mt][2]);
                pack_hilo(x3.x, x3.y, ahf[mt][3], alf[mt][3]);
            }
            uint32_t badr[2];
            #pragma unroll
            for (int bt = 0; bt < 2; bt++) {
                const int row = ks * 16 + krow;
                const int c = (wn >> 3) + bt * 2 + colc;
                badr[bt] = row * 128 + ((c ^ (row & 7)) << 4);
            }
            uint32_t bhf[2][4], blf[2][4];
            #pragma unroll
            for (int bt = 0; bt < 2; bt++) LDSM_X4_T(bhf[bt], vt_h + badr[bt]);
            #pragma unroll
            for (int bt = 0; bt < 2; bt++) LDSM_X4_T(blf[bt], vt_l + badr[bt]);
            #pragma unroll
            for (int mt = 0; mt < 2; mt++)
                #pragma unroll
                for (int nt = 0; nt < 4; nt++)
                    mma_bf16(acc[mt][nt], ahf[mt],
                             bhf[nt >> 1][nt & 1], bhf[nt >> 1][(nt & 1) + 2]);
            #pragma unroll
            for (int mt = 0; mt < 2; mt++)
                #pragma unroll
                for (int nt = 0; nt < 4; nt++)
                    mma_bf16(acc[mt][nt], alf[mt],
                             bhf[nt >> 1][nt & 1], bhf[nt >> 1][(nt & 1) + 2]);
            #pragma unroll
            for (int mt = 0; mt < 2; mt++)
                #pragma unroll
                for (int nt = 0; nt < 4; nt++)
                    mma_bf16(acc[mt][nt], ahf[mt],
                             blf[nt >> 1][nt & 1], blf[nt >> 1][(nt & 1) + 2]);
        }
        __syncthreads();
    }

    const int ec = (lane & 3) * 2;
    #pragma unroll
    for (int mt = 0; mt < 2; mt++) {
        #pragma unroll
        for (int nt = 0; nt < 4; nt++) {
            const int row = i0 + wm + mt * 16 + er;
            const int col = h * 64 + wn + nt * 8 + ec;
            const size_t o0 = (size_t)(b * Sc + row) * Dc + col;
            const size_t o1 = (size_t)(b * Sc + row + 8) * Dc + col;
            split2(acc[mt][nt][0], acc[mt][nt][1], vh_out + o0, vl_out + o0);
            split2(acc[mt][nt][2], acc[mt][nt][3], vh_out + o1, vl_out + o1);
        }
    }
}

// ---------------------------------------------------------------------------
extern "C" void kernel_launch(void* const* d_in, const int* in_sizes, int n_in,
                              void* d_out, int out_size)
{
    const float* x     = (const float*)d_in[0];
    const float* qkv_w = (const float*)d_in[1];
    const float* qkv_b = (const float*)d_in[2];
    const float* out_w = (const float*)d_in[3];
    const float* out_b = (const float*)d_in[4];
    const float* rpe   = (const float*)d_in[5];

    float* attnscr;
    __nv_bfloat16 *ah, *al, *wqh, *wql, *woh, *wol, *qkvh, *qkvl;
    cudaGetSymbolAddress((void**)&attnscr, g_attn);
    cudaGetSymbolAddress((void**)&ah, g_ah);
    cudaGetSymbolAddress((void**)&al, g_al);
    cudaGetSymbolAddress((void**)&wqh, g_wqh);
    cudaGetSymbolAddress((void**)&wql, g_wql);
    cudaGetSymbolAddress((void**)&woh, g_woh);
    cudaGetSymbolAddress((void**)&wol, g_wol);
    cudaGetSymbolAddress((void**)&qkvh, g_qkvh);
    cudaGetSymbolAddress((void**)&qkvl, g_qkvl);

    float* out = (float*)d_out;
    const long OUT_E = (long)BSc * Dc;
    const long ATT_E = (long)Bc * Hc * Sc * Sc;
    float* attn = ((long)out_size >= OUT_E + ATT_E) ? (out + OUT_E) : attnscr;

    cudaFuncSetAttribute(mma_gemm_kernel,
                         cudaFuncAttributeMaxDynamicSharedMemorySize, GSMEM);
    cudaFuncSetAttribute(qk_mma_kernel,
                         cudaFuncAttributeMaxDynamicSharedMemorySize, QK_SMEM);
    cudaFuncSetAttribute(av_mma_kernel,
                         cudaFuncAttributeMaxDynamicSharedMemorySize, AV_SMEM);

    const int n4x = BSc * Dc / 4;
    split_kernel<<<(n4x + 255) / 256, 256>>>(x, ah, al, n4x);
    transpose_split_kernel<<<dim3(D3c / 32, Dc / 32), dim3(32, 8)>>>(qkv_w, wqh, wql, Dc, D3c);
    transpose_split_kernel<<<dim3(Dc / 32, Dc / 32), dim3(32, 8)>>>(out_w, woh, wol, Dc, Dc);

    // 1) qkv: emit bf16 hi/lo (q cols pre-scaled 1/8)
    mma_gemm_kernel<<<dim3(D3c / 128, BSc / 128), 256, GSMEM>>>(
        ah, al, wqh, wql, qkv_b, nullptr, qkvh, qkvl, 1, BSc, D3c, Dc);
    // 2) logits = (q/8) . k
    qk_mma_kernel<<<dim3(3, 3, Bc * Hc), 256, QK_SMEM>>>(qkvh, qkvl, attn);
    // 3+4) rpe bias + softmax (diagonal-chunked: 744 diags x 2 half-chains)
    rpe_softmax_kernel<<<dim3(24 * 31, 2), 128>>>(qkvh, qkvl, rpe, attn);
    // 5) values = attn @ v -> bf16 hi/lo
    av_mma_kernel<<<dim3(3, Bc * Hc), 256, AV_SMEM>>>(attn, qkvh, qkvl, ah, al);
    // 6) out = values @ out_w + out_b
    mma_gemm_kernel<<<dim3(Dc / 128, BSc / 128), 256, GSMEM>>>(
        ah, al, woh, wol, out_b, out, nullptr, nullptr, 0, BSc, Dc, Dc);
}

// round 10
// speedup vs baseline: 1.1904x; 1.1183x over previous
#include <cuda_runtime.h>
#include <cuda_bf16.h>
#include <cstdint>

#define Bc 8
#define Sc 384
#define Dc 1024
#define Hc 16
#define HDc 64
#define D3c 3072
#define BSc 3072   // B*S

// ---------------------------------------------------------------------------
// Scratch (static device globals; no runtime allocation)
// ---------------------------------------------------------------------------
__device__ float g_attn[(size_t)Bc * Hc * Sc * Sc];   // fallback attn buffer
__device__ __align__(16) __nv_bfloat16 g_ah[(size_t)BSc * Dc];    // A hi (x, then vals)
__device__ __align__(16) __nv_bfloat16 g_al[(size_t)BSc * Dc];    // A lo
__device__ __align__(16) __nv_bfloat16 g_wqh[(size_t)D3c * Dc];   // qkv_w^T hi [N,K]
__device__ __align__(16) __nv_bfloat16 g_wql[(size_t)D3c * Dc];   // qkv_w^T lo
__device__ __align__(16) __nv_bfloat16 g_woh[(size_t)Dc * Dc];    // out_w^T hi
__device__ __align__(16) __nv_bfloat16 g_wol[(size_t)Dc * Dc];    // out_w^T lo
__device__ __align__(16) __nv_bfloat16 g_qkvh[(size_t)BSc * D3c]; // qkv hi (q pre-scaled /8)
__device__ __align__(16) __nv_bfloat16 g_qkvl[(size_t)BSc * D3c]; // qkv lo

// ---------------------------------------------------------------------------
// Baseline-PTX helpers
// ---------------------------------------------------------------------------
__device__ __forceinline__ uint32_t smem_u32(const void* p) {
    uint32_t a;
    asm("{ .reg .u64 t; cvta.to.shared.u64 t, %1; cvt.u32.u64 %0, t; }" : "=r"(a) : "l"(p));
    return a;
}
#define CP_ASYNC16(sm, gp) \
    asm volatile("cp.async.cg.shared.global [%0], [%1], 16;" :: "r"(sm), "l"(gp))
#define CP_COMMIT() asm volatile("cp.async.commit_group;" ::: "memory")
#define CP_WAIT0()  asm volatile("cp.async.wait_group 0;" ::: "memory")
#define CP_WAIT1()  asm volatile("cp.async.wait_group 1;" ::: "memory")

#define LDSM_X4(r, a) \
    asm volatile("ldmatrix.sync.aligned.m8n8.x4.shared.b16 {%0,%1,%2,%3}, [%4];" \
        : "=r"((r)[0]), "=r"((r)[1]), "=r"((r)[2]), "=r"((r)[3]) : "r"(a))
#define LDSM_X4_T(r, a) \
    asm volatile("ldmatrix.sync.aligned.m8n8.x4.trans.shared.b16 {%0,%1,%2,%3}, [%4];" \
        : "=r"((r)[0]), "=r"((r)[1]), "=r"((r)[2]), "=r"((r)[3]) : "r"(a))

__device__ __forceinline__ void mma_bf16(float* d, const uint32_t* a,
                                         uint32_t b0, uint32_t b1) {
    asm volatile(
        "mma.sync.aligned.m16n8k16.row.col.f32.bf16.bf16.f32 "
        "{%0,%1,%2,%3}, {%4,%5,%6,%7}, {%8,%9}, {%0,%1,%2,%3};"
        : "+f"(d[0]), "+f"(d[1]), "+f"(d[2]), "+f"(d[3])
        : "r"(a[0]), "r"(a[1]), "r"(a[2]), "r"(a[3]), "r"(b0), "r"(b1));
}

// packed f32x2 (Blackwell FFMA2; baseline sm_100+ PTX)
__device__ __forceinline__ unsigned long long packf2(float x, float y) {
    unsigned long long r;
    asm("mov.b64 %0, {%1, %2};" : "=l"(r) : "f"(x), "f"(y));
    return r;
}
#define FFMA2(acc, a, b) \
    asm("fma.rn.f32x2 %0, %1, %2, %0;" : "+l"(acc) : "l"(a), "l"(b))
__device__ __forceinline__ void unpackf2(unsigned long long v, float& lo, float& hi) {
    asm("mov.b64 {%0, %1}, %2;" : "=f"(lo), "=f"(hi) : "l"(v));
}

__device__ __forceinline__ void split2(float x, float y,
                                       __nv_bfloat16* ph, __nv_bfloat16* pl) {
    __nv_bfloat16 hx = __float2bfloat16(x), hy = __float2bfloat16(y);
    *(__nv_bfloat162*)ph = __nv_bfloat162(hx, hy);
    *(__nv_bfloat162*)pl = __nv_bfloat162(
        __float2bfloat16(x - __bfloat162float(hx)),
        __float2bfloat16(y - __bfloat162float(hy)));
}
__device__ __forceinline__ void pack_hilo(float x, float y,
                                          uint32_t& hi, uint32_t& lo) {
    __nv_bfloat16 hx = __float2bfloat16(x), hy = __float2bfloat16(y);
    __nv_bfloat162 h2(hx, hy);
    __nv_bfloat162 l2(__float2bfloat16(x - __bfloat162float(hx)),
                      __float2bfloat16(y - __bfloat162float(hy)));
    hi = *(uint32_t*)&h2;
    lo = *(uint32_t*)&l2;
}

// ---------------------------------------------------------------------------
// HMMA bf16-split GEMM: C = (Ah+Al)@(Bh+Bl)^T + bias
// Single-sync mainloop: wait group -> barrier -> issue(it+2) -> compute(it).
// ---------------------------------------------------------------------------
#define TILE_B 8192
#define BUF_B  (4 * TILE_B)
#define NSTAGE 3
#define GSMEM  (NSTAGE * BUF_B)   // 96 KB

__global__ __launch_bounds__(256, 2) void mma_gemm_kernel(
    const __nv_bfloat16* __restrict__ Ah, const __nv_bfloat16* __restrict__ Al,
    const __nv_bfloat16* __restrict__ Bh, const __nv_bfloat16* __restrict__ Bl,
    const float* __restrict__ bias, float* __restrict__ C,
    __nv_bfloat16* __restrict__ Ch, __nv_bfloat16* __restrict__ Cl,
    int qkv_mode, int M, int N, int K)
{
    extern __shared__ char smem[];
    const uint32_t sbase = smem_u32(smem);
    const int tid  = threadIdx.x;
    const int wid  = tid >> 5;
    const int lane = tid & 31;
    const int m0 = blockIdx.y * 128;
    const int n0 = blockIdx.x * 128;
    const int mw = (wid & 1) * 64;
    const int nw = (wid >> 1) * 32;

    const int lrow = tid >> 1;
    const int c0   = (tid & 1) * 2;
    const int sw0  = (lrow >> 1) & 3;
    const __nv_bfloat16* gAh = Ah + (size_t)(m0 + lrow) * K;
    const __nv_bfloat16* gAl = Al + (size_t)(m0 + lrow) * K;
    const __nv_bfloat16* gBh = Bh + (size_t)(n0 + lrow) * K;
    const __nv_bfloat16* gBl = Bl + (size_t)(n0 + lrow) * K;
    const uint32_t soff0 = lrow * 64 + (((c0 + 0) ^ sw0) << 4);
    const uint32_t soff1 = lrow * 64 + (((c0 + 1) ^ sw0) << 4);

    const int NK = K >> 5;

    auto issue = [&](int it) {
        if (it < NK) {
            const uint32_t tb = sbase + (it % NSTAGE) * BUF_B;
            const int k0 = it << 5;
            CP_ASYNC16(tb + 0 * TILE_B + soff0, gAh + k0 + (c0 + 0) * 8);
            CP_ASYNC16(tb + 0 * TILE_B + soff1, gAh + k0 + (c0 + 1) * 8);
            CP_ASYNC16(tb + 1 * TILE_B + soff0, gAl + k0 + (c0 + 0) * 8);
            CP_ASYNC16(tb + 1 * TILE_B + soff1, gAl + k0 + (c0 + 1) * 8);
            CP_ASYNC16(tb + 2 * TILE_B + soff0, gBh + k0 + (c0 + 0) * 8);
            CP_ASYNC16(tb + 2 * TILE_B + soff1, gBh + k0 + (c0 + 1) * 8);
            CP_ASYNC16(tb + 3 * TILE_B + soff0, gBl + k0 + (c0 + 0) * 8);
            CP_ASYNC16(tb + 3 * TILE_B + soff1, gBl + k0 + (c0 + 1) * 8);
        }
        CP_COMMIT();
    };

    const int frow = lane & 15;
    const int fc   = lane >> 4;
    auto fr_addr = [&](int rbase) -> uint32_t {
        const int row = rbase + frow;
        return (uint32_t)(row * 64 + ((fc ^ ((row >> 1) & 3)) << 4));
    };
    const uint32_t aoff = fr_addr(mw);
    const uint32_t boff = fr_addr(nw);

    float acc[4][4][4];
    #pragma unroll
    for (int i = 0; i < 4; i++)
        #pragma unroll
        for (int j = 0; j < 4; j++)
            #pragma unroll
            for (int r = 0; r < 4; r++) acc[i][j][r] = 0.f;

    issue(0); issue(1);

    for (int it = 0; it < NK; it++) {
        CP_WAIT1();
        __syncthreads();
        issue(it + 2);   // buffer (it+2)%3 == (it-1)%3, consumed by all at the barrier
        const uint32_t tb = sbase + (it % NSTAGE) * BUF_B;
        #pragma unroll
        for (int ks = 0; ks < 2; ks++) {
            const uint32_t kx = ks ? 32u : 0u;
            uint32_t ahf[4][4], bhf[2][4];
            #pragma unroll
            for (int mt = 0; mt < 4; mt++)
                LDSM_X4(ahf[mt], tb + ((aoff + mt * 1024) ^ kx));
            #pragma unroll
            for (int bt = 0; bt < 2; bt++)
                LDSM_X4(bhf[bt], tb + 2 * TILE_B + ((boff + bt * 1024) ^ kx));
            // pass 0: Ah*Bh
            #pragma unroll
            for (int mt = 0; mt < 4; mt++)
                #pragma unroll
                for (int nt = 0; nt < 4; nt++)
                    mma_bf16(acc[mt][nt], ahf[mt],
                             bhf[nt >> 1][nt & 1], bhf[nt >> 1][(nt & 1) + 2]);
            // load Bl while pass0 drains
            uint32_t blf[2][4];
            #pragma unroll
            for (int bt = 0; bt < 2; bt++)
                LDSM_X4(blf[bt], tb + 3 * TILE_B + ((boff + bt * 1024) ^ kx));
            // pass 1: Ah*Bl
            #pragma unroll
            for (int mt = 0; mt < 4; mt++)
                #pragma unroll
                for (int nt = 0; nt < 4; nt++)
                    mma_bf16(acc[mt][nt], ahf[mt],
                             blf[nt >> 1][nt & 1], blf[nt >> 1][(nt & 1) + 2]);
            // load Al while pass1 drains
            uint32_t alf[4][4];
            #pragma unroll
            for (int mt = 0; mt < 4; mt++)
                LDSM_X4(alf[mt], tb + TILE_B + ((aoff + mt * 1024) ^ kx));
            // pass 2: Al*Bh
            #pragma unroll
            for (int mt = 0; mt < 4; mt++)
                #pragma unroll
                for (int nt = 0; nt < 4; nt++)
                    mma_bf16(acc[mt][nt], alf[mt],
                             bhf[nt >> 1][nt & 1], bhf[nt >> 1][(nt & 1) + 2]);
        }
    }

    const int er = lane >> 2;
    const int ec = (lane & 3) * 2;
    #pragma unroll
    for (int mt = 0; mt < 4; mt++) {
        #pragma unroll
        for (int nt = 0; nt < 4; nt++) {
            const int col = n0 + nw + nt * 8 + ec;
            const float bx = __ldg(&bias[col]);
            const float by = __ldg(&bias[col + 1]);
            const int r0 = m0 + mw + mt * 16 + er;
            float2 v0 = make_float2(acc[mt][nt][0] + bx, acc[mt][nt][1] + by);
            float2 v1 = make_float2(acc[mt][nt][2] + bx, acc[mt][nt][3] + by);
            if (C) {
                *(float2*)(C + (size_t)r0 * N + col) = v0;
                *(float2*)(C + (size_t)(r0 + 8) * N + col) = v1;
            }
            if (Ch) {
                const float s = (qkv_mode && (((col >> 6) % 3) == 0)) ? 0.125f : 1.0f;
                split2(v0.x * s, v0.y * s, Ch + (size_t)r0 * N + col,
                       Cl + (size_t)r0 * N + col);
                split2(v1.x * s, v1.y * s, Ch + (size_t)(r0 + 8) * N + col,
                       Cl + (size_t)(r0 + 8) * N + col);
            }
        }
    }
}

// ---------------------------------------------------------------------------
// fp32 -> bf16 hi/lo split (vectorized by 4)
// ---------------------------------------------------------------------------
__global__ __launch_bounds__(256) void split_kernel(
    const float* __restrict__ src, __nv_bfloat16* __restrict__ hi,
    __nv_bfloat16* __restrict__ lo, int n4)
{
    int i = blockIdx.x * blockDim.x + threadIdx.x;
    if (i >= n4) return;
    float4 v = ((const float4*)src)[i];
    split2(v.x, v.y, hi + 4 * (size_t)i, lo + 4 * (size_t)i);
    split2(v.z, v.w, hi + 4 * (size_t)i + 2, lo + 4 * (size_t)i + 2);
}

// ---------------------------------------------------------------------------
// W[K,N] -> Wt[N,K] with bf16 hi/lo split
// ---------------------------------------------------------------------------
__global__ __launch_bounds__(256) void transpose_split_kernel(
    const float* __restrict__ W, __nv_bfloat16* __restrict__ Th,
    __nv_bfloat16* __restrict__ Tl, int K, int N)
{
    __shared__ float t[32][33];
    const int n0 = blockIdx.x * 32, k0 = blockIdx.y * 32;
    const int tx = threadIdx.x, ty = threadIdx.y;
    #pragma unroll
    for (int r = 0; r < 4; r++)
        t[ty + 8 * r][tx] = W[(size_t)(k0 + ty + 8 * r) * N + n0 + tx];
    __syncthreads();
    #pragma unroll
    for (int r = 0; r < 4; r++) {
        float v = t[tx][ty + 8 * r];
        __nv_bfloat16 h = __float2bfloat16(v);
        __nv_bfloat16 l = __float2bfloat16(v - __bfloat162float(h));
        size_t o = (size_t)(n0 + ty + 8 * r) * K + k0 + tx;
        Th[o] = h; Tl[o] = l;
    }
}

// ---------------------------------------------------------------------------
// qk HMMA: logits = (scaled q).k, 3-pass bf16 split, interleaved LDSM.
// ---------------------------------------------------------------------------
#define QK_SMEM (4 * 16384)

__global__ __launch_bounds__(256, 2) void qk_mma_kernel(
    const __nv_bfloat16* __restrict__ qkvh, const __nv_bfloat16* __restrict__ qkvl,
    float* __restrict__ attn)
{
    extern __shared__ char smem[];
    const uint32_t sb = smem_u32(smem);
    const int tid = threadIdx.x, wid = tid >> 5, lane = tid & 31;
    const int bh = blockIdx.z, b = bh >> 4, h = bh & 15;
    const int i0 = blockIdx.y * 128, j0 = blockIdx.x * 128;

    #pragma unroll
    for (int t = 0; t < 4; t++) {
        const __nv_bfloat16* base = (t & 1) ? qkvl : qkvh;
        const int roff = (t < 2) ? i0 : j0;
        const int coff = h * 192 + ((t < 2) ? 0 : 64);
        for (int idx = tid; idx < 1024; idx += 256) {
            const int row = idx >> 3, c = idx & 7;
            const uint32_t dst = sb + t * 16384 + row * 128 + ((c ^ (row & 7)) << 4);
            CP_ASYNC16(dst, base + (size_t)(b * Sc + roff + row) * D3c + coff + c * 8);
        }
    }
    CP_COMMIT(); CP_WAIT0();
    __syncthreads();

    const int mw = (wid & 1) * 64;
    const int nw = (wid >> 1) * 32;
    const int frow = lane & 15, fc = lane >> 4;

    float acc[4][4][4];
    #pragma unroll
    for (int i = 0; i < 4; i++)
        #pragma unroll
        for (int j = 0; j < 4; j++)
            #pragma unroll
            for (int r = 0; r < 4; r++) acc[i][j][r] = 0.f;

    #pragma unroll
    for (int ks = 0; ks < 4; ks++) {
        uint32_t aadr[4], badr[2];
        #pragma unroll
        for (int mt = 0; mt < 4; mt++) {
            const int row = mw + mt * 16 + frow;
            aadr[mt] = row * 128 + (((2 * ks + fc) ^ (row & 7)) << 4);
        }
        #pragma unroll
        for (int bt = 0; bt < 2; bt++) {
            const int row = nw + bt * 16 + frow;
            badr[bt] = row * 128 + (((2 * ks + fc) ^ (row & 7)) << 4);
        }
        uint32_t ahf[4][4], bhf[2][4];
        #pragma unroll
        for (int mt = 0; mt < 4; mt++) LDSM_X4(ahf[mt], sb + aadr[mt]);
        #pragma unroll
        for (int bt = 0; bt < 2; bt++) LDSM_X4(bhf[bt], sb + 2 * 16384 + badr[bt]);
        #pragma unroll
        for (int mt = 0; mt < 4; mt++)
            #pragma unroll
            for (int nt = 0; nt < 4; nt++)
                mma_bf16(acc[mt][nt], ahf[mt],
                         bhf[nt >> 1][nt & 1], bhf[nt >> 1][(nt & 1) + 2]);
        uint32_t blf[2][4];
        #pragma unroll
        for (int bt = 0; bt < 2; bt++) LDSM_X4(blf[bt], sb + 3 * 16384 + badr[bt]);
        #pragma unroll
        for (int mt = 0; mt < 4; mt++)
            #pragma unroll
            for (int nt = 0; nt < 4; nt++)
                mma_bf16(acc[mt][nt], ahf[mt],
                         blf[nt >> 1][nt & 1], blf[nt >> 1][(nt & 1) + 2]);
        uint32_t alf[4][4];
        #pragma unroll
        for (int mt = 0; mt < 4; mt++) LDSM_X4(alf[mt], sb + 16384 + aadr[mt]);
        #pragma unroll
        for (int mt = 0; mt < 4; mt++)
            #pragma unroll
            for (int nt = 0; nt < 4; nt++)
                mma_bf16(acc[mt][nt], alf[mt],
                         bhf[nt >> 1][nt & 1], bhf[nt >> 1][(nt & 1) + 2]);
    }

    const int er = lane >> 2, ec = (lane & 3) * 2;
    float* ob = attn + (size_t)bh * Sc * Sc;
    #pragma unroll
    for (int mt = 0; mt < 4; mt++) {
        #pragma unroll
        for (int nt = 0; nt < 4; nt++) {
            const int r0 = i0 + mw + mt * 16 + er;
            const int col = j0 + nw + nt * 8 + ec;
            *(float2*)(ob + (size_t)r0 * Sc + col) =
                make_float2(acc[mt][nt][0], acc[mt][nt][1]);
            *(float2*)(ob + (size_t)(r0 + 8) * Sc + col) =
                make_float2(acc[mt][nt][2], acc[mt][nt][3]);
        }
    }
}

// ---------------------------------------------------------------------------
// Fused XL relative bias + row softmax (R7 layout: one block per (h,i)).
// q pairs (b even, b odd) packed into u64 smem; each slab value packed once
// and driven through 4 FFMA2 (covers all 8 batches in half the FMA issues).
// ---------------------------------------------------------------------------
__global__ __launch_bounds__(128) void rpe_softmax_kernel(
    const __nv_bfloat16* __restrict__ qkvh, const __nv_bfloat16* __restrict__ qkvl,
    const float* __restrict__ rpe, float* __restrict__ attn)
{
    const int h = blockIdx.x / Sc;
    const int i = blockIdx.x % Sc;
    const int r0 = 384 + 24 * (i & 15) - 24 * h - (i >> 4);
    const float* rbase = rpe + (size_t)r0 * 1024;
    __shared__ unsigned long long Qp[256];   // [dd*4 + p] = (q[2p][dd], q[2p+1][dd])
    __shared__ float L[Bc][Sc];
    const int tid = threadIdx.x;
    for (int t = tid; t < 256; t += 128) {
        const int p = t & 3, dd = t >> 2;
        const size_t i0x = (size_t)((2 * p) * Sc + i) * D3c + h * 192 + dd;
        const size_t i1x = (size_t)((2 * p + 1) * Sc + i) * D3c + h * 192 + dd;
        const float q0 = (__bfloat162float(qkvh[i0x]) + __bfloat162float(qkvl[i0x])) * 8.f;
        const float q1 = (__bfloat162float(qkvh[i1x]) + __bfloat162float(qkvl[i1x])) * 8.f;
        Qp[t] = packf2(q0, q1);
    }
    __syncthreads();

    unsigned long long acc2[3][4];
    #pragma unroll
    for (int jj = 0; jj < 3; jj++)
        #pragma unroll
        for (int p = 0; p < 4; p++) acc2[jj][p] = 0ull;

    #pragma unroll
    for (int c = 0; c < 16; c++) {
        unsigned long long qp[4][4];
        #pragma unroll
        for (int d2 = 0; d2 < 4; d2++)
            #pragma unroll
            for (int p = 0; p < 4; p++)
                qp[d2][p] = Qp[(c * 4 + d2) * 4 + p];
        #pragma unroll
        for (int jj = 0; jj < 3; jj++) {
            const int j = tid + jj * 128;
            const float4 rv = *(const float4*)(rbase + (size_t)j * 64 + c * 4);
            const unsigned long long s0 = packf2(rv.x, rv.x);
            const unsigned long long s1 = packf2(rv.y, rv.y);
            const unsigned long long s2 = packf2(rv.z, rv.z);
            const unsigned long long s3 = packf2(rv.w, rv.w);
            #pragma unroll
            for (int p = 0; p < 4; p++) {
                FFMA2(acc2[jj][p], qp[0][p], s0);
                FFMA2(acc2[jj][p], qp[1][p], s1);
                FFMA2(acc2[jj][p], qp[2][p], s2);
                FFMA2(acc2[jj][p], qp[3][p], s3);
            }
        }
    }
    #pragma unroll
    for (int jj = 0; jj < 3; jj++) {
        const int j = tid + jj * 128;
        #pragma unroll
        for (int p = 0; p < 4; p++) {
            float lo, hi;
            unpackf2(acc2[jj][p], lo, hi);
            const int b0 = 2 * p, b1 = 2 * p + 1;
            L[b0][j] = attn[((size_t)(b0 * Hc + h) * Sc + i) * Sc + j] + lo;
            L[b1][j] = attn[((size_t)(b1 * Hc + h) * Sc + i) * Sc + j] + hi;
        }
    }
    __syncthreads();

    const int wrp = tid >> 5, lane = tid & 31;
    #pragma unroll
    for (int bb = 0; bb < 2; bb++) {
        const int b = wrp * 2 + bb;
        float v[12];
        float m = -1e30f;
        #pragma unroll
        for (int r = 0; r < 12; r++) { v[r] = L[b][lane + 32 * r]; m = fmaxf(m, v[r]); }
        #pragma unroll
        for (int o = 16; o > 0; o >>= 1) m = fmaxf(m, __shfl_xor_sync(0xffffffffu, m, o));
        float s = 0.f;
        #pragma unroll
        for (int r = 0; r < 12; r++) { v[r] = __expf(v[r] - m); s += v[r]; }
        #pragma unroll
        for (int o = 16; o > 0; o >>= 1) s += __shfl_xor_sync(0xffffffffu, s, o);
        const float inv = 1.0f / s;
        float* orow = attn + ((size_t)(b * Hc + h) * Sc + i) * Sc;
        #pragma unroll
        for (int r = 0; r < 12; r++) orow[lane + 32 * r] = v[r] * inv;
    }
}

// ---------------------------------------------------------------------------
// av HMMA: values = attn(fp32) @ v, 3-pass bf16 split.
// ---------------------------------------------------------------------------
#define AV_AROW 72
#define AV_ATILE (128 * AV_AROW * 4)
#define AV_VTILE 8192
#define AV_STAGE (AV_ATILE + 2 * AV_VTILE)
#define AV_SMEM  (2 * AV_STAGE)

__global__ __launch_bounds__(256, 2) void av_mma_kernel(
    const float* __restrict__ attn,
    const __nv_bfloat16* __restrict__ qkvh, const __nv_bfloat16* __restrict__ qkvl,
    __nv_bfloat16* __restrict__ vh_out, __nv_bfloat16* __restrict__ vl_out)
{
    extern __shared__ char smem[];
    const uint32_t sb = smem_u32(smem);
    float* sA_f = (float*)smem;
    const int tid = threadIdx.x, wid = tid >> 5, lane = tid & 31;
    const int bh = blockIdx.y, b = bh >> 4, h = bh & 15;
    const int i0 = blockIdx.x * 128;

    const float* abase = attn + ((size_t)bh * Sc + i0) * Sc;
    const __nv_bfloat16* vbase_h = qkvh + h * 192 + 128;
    const __nv_bfloat16* vbase_l = qkvl + h * 192 + 128;

    auto issue = [&](int ck) {
        if (ck >= 6) { CP_COMMIT(); return; }
        const uint32_t st = sb + (ck & 1) * AV_STAGE;
        const int j0 = ck * 64;
        for (int idx = tid; idx < 2048; idx += 256) {
            const int row = idx >> 4, c = idx & 15;
            CP_ASYNC16(st + row * (AV_AROW * 4) + c * 16,
                       abase + (size_t)row * Sc + j0 + c * 4);
        }
        for (int idx = tid; idx < 512; idx += 256) {
            const int row = idx >> 3, c = idx & 7;
            const uint32_t sw = row * 128 + ((c ^ (row & 7)) << 4);
            const size_t go = (size_t)(b * Sc + j0 + row) * D3c + c * 8;
            CP_ASYNC16(st + AV_ATILE + sw, vbase_h + go);
            CP_ASYNC16(st + AV_ATILE + AV_VTILE + sw, vbase_l + go);
        }
        CP_COMMIT();
    };

    const int wm = (wid & 3) * 32;
    const int wn = (wid >> 2) * 32;
    const int er = lane >> 2;
    const int ecb = (lane & 3) * 2;
    const int krow = (lane & 7) | ((lane & 16) >> 1);
    const int colc = (lane >> 3) & 1;

    float acc[2][4][4];
    #pragma unroll
    for (int i = 0; i < 2; i++)
        #pragma unroll
        for (int j = 0; j < 4; j++)
            #pragma unroll
            for (int r = 0; r < 4; r++) acc[i][j][r] = 0.f;

    issue(0);
    for (int ck = 0; ck < 6; ck++) {
        issue(ck + 1);
        CP_WAIT1();
        __syncthreads();
        const int stg = (ck & 1);
        float* sA = sA_f + stg * (AV_STAGE / 4);
        const uint32_t vt_h = sb + stg * AV_STAGE + AV_ATILE;
        const uint32_t vt_l = vt_h + AV_VTILE;
        #pragma unroll
        for (int ks = 0; ks < 4; ks++) {
            uint32_t ahf[2][4], alf[2][4];
            #pragma unroll
            for (int mt = 0; mt < 2; mt++) {
                const int r_ = wm + mt * 16 + er;
                const int cb = ks * 16 + ecb;
                float2 x0 = *(float2*)(sA + (size_t)r_ * AV_AROW + cb);
                float2 x1 = *(float2*)(sA + (size_t)(r_ + 8) * AV_AROW + cb);
                float2 x2 = *(float2*)(sA + (size_t)r_ * AV_AROW + cb + 8);
                float2 x3 = *(float2*)(sA + (size_t)(r_ + 8) * AV_AROW + cb + 8);
                pack_hilo(x0.x, x0.y, ahf[mt][0], alf[mt][0]);
                pack_hilo(x1.x, x1.y, ahf[mt][1], alf[mt][1]);
                pack_hilo(x2.x, x2.y, ahf[mt][2], alf[mt][2]);
                pack_hilo(x3.x, x3.y, ahf[mt][3], alf[mt][3]);
            }
            uint32_t badr[2];
            #pragma unroll
            for (int bt = 0; bt < 2; bt++) {
                const int row = ks * 16 + krow;
                const int c = (wn >> 3) + bt * 2 + colc;
                badr[bt] = row * 128 + ((c ^ (row & 7)) << 4);
            }
            uint32_t bhf[2][4], blf[2][4];
            #pragma unroll
            for (int bt = 0; bt < 2; bt++) LDSM_X4_T(bhf[bt], vt_h + badr[bt]);
            #pragma unroll
            for (int bt = 0; bt < 2; bt++) LDSM_X4_T(blf[bt], vt_l + badr[bt]);
            #pragma unroll
            for (int mt = 0; mt < 2; mt++)
                #pragma unroll
                for (int nt = 0; nt < 4; nt++)
                    mma_bf16(acc[mt][nt], ahf[mt],
                             bhf[nt >> 1][nt & 1], bhf[nt >> 1][(nt & 1) + 2]);
            #pragma unroll
            for (int mt = 0; mt < 2; mt++)
                #pragma unroll
                for (int nt = 0; nt < 4; nt++)
                    mma_bf16(acc[mt][nt], alf[mt],
                             bhf[nt >> 1][nt & 1], bhf[nt >> 1][(nt & 1) + 2]);
            #pragma unroll
            for (int mt = 0; mt < 2; mt++)
                #pragma unroll
                for (int nt = 0; nt < 4; nt++)
                    mma_bf16(acc[mt][nt], ahf[mt],
                             blf[nt >> 1][nt & 1], blf[nt >> 1][(nt & 1) + 2]);
        }
        __syncthreads();
    }

    const int ec = (lane & 3) * 2;
    #pragma unroll
    for (int mt = 0; mt < 2; mt++) {
        #pragma unroll
        for (int nt = 0; nt < 4; nt++) {
            const int row = i0 + wm + mt * 16 + er;
            const int col = h * 64 + wn + nt * 8 + ec;
            const size_t o0 = (size_t)(b * Sc + row) * Dc + col;
            const size_t o1 = (size_t)(b * Sc + row + 8) * Dc + col;
            split2(acc[mt][nt][0], acc[mt][nt][1], vh_out + o0, vl_out + o0);
            split2(acc[mt][nt][2], acc[mt][nt][3], vh_out + o1, vl_out + o1);
        }
    }
}

// ---------------------------------------------------------------------------
extern "C" void kernel_launch(void* const* d_in, const int* in_sizes, int n_in,
                              void* d_out, int out_size)
{
    const float* x     = (const float*)d_in[0];
    const float* qkv_w = (const float*)d_in[1];
    const float* qkv_b = (const float*)d_in[2];
    const float* out_w = (const float*)d_in[3];
    const float* out_b = (const float*)d_in[4];
    const float* rpe   = (const float*)d_in[5];

    float* attnscr;
    __nv_bfloat16 *ah, *al, *wqh, *wql, *woh, *wol, *qkvh, *qkvl;
    cudaGetSymbolAddress((void**)&attnscr, g_attn);
    cudaGetSymbolAddress((void**)&ah, g_ah);
    cudaGetSymbolAddress((void**)&al, g_al);
    cudaGetSymbolAddress((void**)&wqh, g_wqh);
    cudaGetSymbolAddress((void**)&wql, g_wql);
    cudaGetSymbolAddress((void**)&woh, g_woh);
    cudaGetSymbolAddress((void**)&wol, g_wol);
    cudaGetSymbolAddress((void**)&qkvh, g_qkvh);
    cudaGetSymbolAddress((void**)&qkvl, g_qkvl);

    float* out = (float*)d_out;
    const long OUT_E = (long)BSc * Dc;
    const long ATT_E = (long)Bc * Hc * Sc * Sc;
    float* attn = ((long)out_size >= OUT_E + ATT_E) ? (out + OUT_E) : attnscr;

    cudaFuncSetAttribute(mma_gemm_kernel,
                         cudaFuncAttributeMaxDynamicSharedMemorySize, GSMEM);
    cudaFuncSetAttribute(qk_mma_kernel,
                         cudaFuncAttributeMaxDynamicSharedMemorySize, QK_SMEM);
    cudaFuncSetAttribute(av_mma_kernel,
                         cudaFuncAttributeMaxDynamicSharedMemorySize, AV_SMEM);

    const int n4x = BSc * Dc / 4;
    split_kernel<<<(n4x + 255) / 256, 256>>>(x, ah, al, n4x);
    transpose_split_kernel<<<dim3(D3c / 32, Dc / 32), dim3(32, 8)>>>(qkv_w, wqh, wql, Dc, D3c);
    transpose_split_kernel<<<dim3(Dc / 32, Dc / 32), dim3(32, 8)>>>(out_w, woh, wol, Dc, Dc);

    // 1) qkv: emit bf16 hi/lo (q cols pre-scaled 1/8)
    mma_gemm_kernel<<<dim3(D3c / 128, BSc / 128), 256, GSMEM>>>(
        ah, al, wqh, wql, qkv_b, nullptr, qkvh, qkvl, 1, BSc, D3c, Dc);
    // 2) logits = (q/8) . k
    qk_mma_kernel<<<dim3(3, 3, Bc * Hc), 256, QK_SMEM>>>(qkvh, qkvl, attn);
    // 3+4) rpe bias (f32x2) + softmax  (R7 per-(h,i) launch)
    rpe_softmax_kernel<<<Hc * Sc, 128>>>(qkvh, qkvl, rpe, attn);
    // 5) values = attn @ v -> bf16 hi/lo
    av_mma_kernel<<<dim3(3, Bc * Hc), 256, AV_SMEM>>>(attn, qkvh, qkvl, ah, al);
    // 6) out = values @ out_w + out_b
    mma_gemm_kernel<<<dim3(Dc / 128, BSc / 128), 256, GSMEM>>>(
        ah, al, woh, wol, out_b, out, nullptr, nullptr, 0, BSc, Dc, Dc);
}

// round 11
// speedup vs baseline: 1.1923x; 1.0016x over previous
#include <cuda_runtime.h>
#include <cuda_bf16.h>
#include <cstdint>

#define Bc 8
#define Sc 384
#define Dc 1024
#define Hc 16
#define HDc 64
#define D3c 3072
#define BSc 3072   // B*S

// ---------------------------------------------------------------------------
// Scratch (static device globals; no runtime allocation)
// ---------------------------------------------------------------------------
__device__ float g_attn[(size_t)Bc * Hc * Sc * Sc];   // fallback attn buffer
__device__ __align__(16) __nv_bfloat16 g_ah[(size_t)BSc * Dc];    // A hi (x, then vals)
__device__ __align__(16) __nv_bfloat16 g_al[(size_t)BSc * Dc];    // A lo
__device__ __align__(16) __nv_bfloat16 g_wqh[(size_t)D3c * Dc];   // qkv_w^T hi [N,K]
__device__ __align__(16) __nv_bfloat16 g_wql[(size_t)D3c * Dc];   // qkv_w^T lo
__device__ __align__(16) __nv_bfloat16 g_woh[(size_t)Dc * Dc];    // out_w^T hi
__device__ __align__(16) __nv_bfloat16 g_wol[(size_t)Dc * Dc];    // out_w^T lo
__device__ __align__(16) __nv_bfloat16 g_qkvh[(size_t)BSc * D3c]; // qkv hi (q pre-scaled /8)
__device__ __align__(16) __nv_bfloat16 g_qkvl[(size_t)BSc * D3c]; // qkv lo

// ---------------------------------------------------------------------------
// Baseline-PTX helpers
// ---------------------------------------------------------------------------
__device__ __forceinline__ uint32_t smem_u32(const void* p) {
    uint32_t a;
    asm("{ .reg .u64 t; cvta.to.shared.u64 t, %1; cvt.u32.u64 %0, t; }" : "=r"(a) : "l"(p));
    return a;
}
#define CP_ASYNC16(sm, gp) \
    asm volatile("cp.async.cg.shared.global [%0], [%1], 16;" :: "r"(sm), "l"(gp))
#define CP_COMMIT() asm volatile("cp.async.commit_group;" ::: "memory")
#define CP_WAIT0()  asm volatile("cp.async.wait_group 0;" ::: "memory")
#define CP_WAIT1()  asm volatile("cp.async.wait_group 1;" ::: "memory")

#define LDSM_X4(r, a) \
    asm volatile("ldmatrix.sync.aligned.m8n8.x4.shared.b16 {%0,%1,%2,%3}, [%4];" \
        : "=r"((r)[0]), "=r"((r)[1]), "=r"((r)[2]), "=r"((r)[3]) : "r"(a))
#define LDSM_X4_T(r, a) \
    asm volatile("ldmatrix.sync.aligned.m8n8.x4.trans.shared.b16 {%0,%1,%2,%3}, [%4];" \
        : "=r"((r)[0]), "=r"((r)[1]), "=r"((r)[2]), "=r"((r)[3]) : "r"(a))

__device__ __forceinline__ void mma_bf16(float* d, const uint32_t* a,
                                         uint32_t b0, uint32_t b1) {
    asm volatile(
        "mma.sync.aligned.m16n8k16.row.col.f32.bf16.bf16.f32 "
        "{%0,%1,%2,%3}, {%4,%5,%6,%7}, {%8,%9}, {%0,%1,%2,%3};"
        : "+f"(d[0]), "+f"(d[1]), "+f"(d[2]), "+f"(d[3])
        : "r"(a[0]), "r"(a[1]), "r"(a[2]), "r"(a[3]), "r"(b0), "r"(b1));
}

// packed f32x2 (Blackwell FFMA2; baseline sm_100+ PTX)
__device__ __forceinline__ unsigned long long packf2(float x, float y) {
    unsigned long long r;
    asm("mov.b64 %0, {%1, %2};" : "=l"(r) : "f"(x), "f"(y));
    return r;
}
#define FFMA2(acc, a, b) \
    asm("fma.rn.f32x2 %0, %1, %2, %0;" : "+l"(acc) : "l"(a), "l"(b))
__device__ __forceinline__ void unpackf2(unsigned long long v, float& lo, float& hi) {
    asm("mov.b64 {%0, %1}, %2;" : "=f"(lo), "=f"(hi) : "l"(v));
}

__device__ __forceinline__ void split2(float x, float y,
                                       __nv_bfloat16* ph, __nv_bfloat16* pl) {
    __nv_bfloat16 hx = __float2bfloat16(x), hy = __float2bfloat16(y);
    *(__nv_bfloat162*)ph = __nv_bfloat162(hx, hy);
    *(__nv_bfloat162*)pl = __nv_bfloat162(
        __float2bfloat16(x - __bfloat162float(hx)),
        __float2bfloat16(y - __bfloat162float(hy)));
}
__device__ __forceinline__ void pack_hilo(float x, float y,
                                          uint32_t& hi, uint32_t& lo) {
    __nv_bfloat16 hx = __float2bfloat16(x), hy = __float2bfloat16(y);
    __nv_bfloat162 h2(hx, hy);
    __nv_bfloat162 l2(__float2bfloat16(x - __bfloat162float(hx)),
                      __float2bfloat16(y - __bfloat162float(hy)));
    hi = *(uint32_t*)&h2;
    lo = *(uint32_t*)&l2;
}

// ---------------------------------------------------------------------------
// HMMA bf16-split GEMM: C = (Ah+Al)@(Bh+Bl)^T + bias
// Single-sync mainloop: wait group -> barrier -> issue(it+2) -> compute(it).
// ---------------------------------------------------------------------------
#define TILE_B 8192
#define BUF_B  (4 * TILE_B)
#define NSTAGE 3
#define GSMEM  (NSTAGE * BUF_B)   // 96 KB

__global__ __launch_bounds__(256, 2) void mma_gemm_kernel(
    const __nv_bfloat16* __restrict__ Ah, const __nv_bfloat16* __restrict__ Al,
    const __nv_bfloat16* __restrict__ Bh, const __nv_bfloat16* __restrict__ Bl,
    const float* __restrict__ bias, float* __restrict__ C,
    __nv_bfloat16* __restrict__ Ch, __nv_bfloat16* __restrict__ Cl,
    int qkv_mode, int M, int N, int K)
{
    extern __shared__ char smem[];
    const uint32_t sbase = smem_u32(smem);
    const int tid  = threadIdx.x;
    const int wid  = tid >> 5;
    const int lane = tid & 31;
    const int m0 = blockIdx.y * 128;
    const int n0 = blockIdx.x * 128;
    const int mw = (wid & 1) * 64;
    const int nw = (wid >> 1) * 32;

    const int lrow = tid >> 1;
    const int c0   = (tid & 1) * 2;
    const int sw0  = (lrow >> 1) & 3;
    const __nv_bfloat16* gAh = Ah + (size_t)(m0 + lrow) * K;
    const __nv_bfloat16* gAl = Al + (size_t)(m0 + lrow) * K;
    const __nv_bfloat16* gBh = Bh + (size_t)(n0 + lrow) * K;
    const __nv_bfloat16* gBl = Bl + (size_t)(n0 + lrow) * K;
    const uint32_t soff0 = lrow * 64 + (((c0 + 0) ^ sw0) << 4);
    const uint32_t soff1 = lrow * 64 + (((c0 + 1) ^ sw0) << 4);

    const int NK = K >> 5;

    auto issue = [&](int it) {
        if (it < NK) {
            const uint32_t tb = sbase + (it % NSTAGE) * BUF_B;
            const int k0 = it << 5;
            CP_ASYNC16(tb + 0 * TILE_B + soff0, gAh + k0 + (c0 + 0) * 8);
            CP_ASYNC16(tb + 0 * TILE_B + soff1, gAh + k0 + (c0 + 1) * 8);
            CP_ASYNC16(tb + 1 * TILE_B + soff0, gAl + k0 + (c0 + 0) * 8);
            CP_ASYNC16(tb + 1 * TILE_B + soff1, gAl + k0 + (c0 + 1) * 8);
            CP_ASYNC16(tb + 2 * TILE_B + soff0, gBh + k0 + (c0 + 0) * 8);
            CP_ASYNC16(tb + 2 * TILE_B + soff1, gBh + k0 + (c0 + 1) * 8);
            CP_ASYNC16(tb + 3 * TILE_B + soff0, gBl + k0 + (c0 + 0) * 8);
            CP_ASYNC16(tb + 3 * TILE_B + soff1, gBl + k0 + (c0 + 1) * 8);
        }
        CP_COMMIT();
    };

    const int frow = lane & 15;
    const int fc   = lane >> 4;
    auto fr_addr = [&](int rbase) -> uint32_t {
        const int row = rbase + frow;
        return (uint32_t)(row * 64 + ((fc ^ ((row >> 1) & 3)) << 4));
    };
    const uint32_t aoff = fr_addr(mw);
    const uint32_t boff = fr_addr(nw);

    float acc[4][4][4];
    #pragma unroll
    for (int i = 0; i < 4; i++)
        #pragma unroll
        for (int j = 0; j < 4; j++)
            #pragma unroll
            for (int r = 0; r < 4; r++) acc[i][j][r] = 0.f;

    issue(0); issue(1);

    for (int it = 0; it < NK; it++) {
        CP_WAIT1();
        __syncthreads();
        issue(it + 2);   // buffer (it+2)%3 == (it-1)%3, consumed by all at the barrier
        const uint32_t tb = sbase + (it % NSTAGE) * BUF_B;
        #pragma unroll
        for (int ks = 0; ks < 2; ks++) {
            const uint32_t kx = ks ? 32u : 0u;
            uint32_t ahf[4][4], bhf[2][4];
            #pragma unroll
            for (int mt = 0; mt < 4; mt++)
                LDSM_X4(ahf[mt], tb + ((aoff + mt * 1024) ^ kx));
            #pragma unroll
            for (int bt = 0; bt < 2; bt++)
                LDSM_X4(bhf[bt], tb + 2 * TILE_B + ((boff + bt * 1024) ^ kx));
            // pass 0: Ah*Bh
            #pragma unroll
            for (int mt = 0; mt < 4; mt++)
                #pragma unroll
                for (int nt = 0; nt < 4; nt++)
                    mma_bf16(acc[mt][nt], ahf[mt],
                             bhf[nt >> 1][nt & 1], bhf[nt >> 1][(nt & 1) + 2]);
            // load Bl while pass0 drains
            uint32_t blf[2][4];
            #pragma unroll
            for (int bt = 0; bt < 2; bt++)
                LDSM_X4(blf[bt], tb + 3 * TILE_B + ((boff + bt * 1024) ^ kx));
            // pass 1: Ah*Bl
            #pragma unroll
            for (int mt = 0; mt < 4; mt++)
                #pragma unroll
                for (int nt = 0; nt < 4; nt++)
                    mma_bf16(acc[mt][nt], ahf[mt],
                             blf[nt >> 1][nt & 1], blf[nt >> 1][(nt & 1) + 2]);
            // load Al while pass1 drains
            uint32_t alf[4][4];
            #pragma unroll
            for (int mt = 0; mt < 4; mt++)
                LDSM_X4(alf[mt], tb + TILE_B + ((aoff + mt * 1024) ^ kx));
            // pass 2: Al*Bh
            #pragma unroll
            for (int mt = 0; mt < 4; mt++)
                #pragma unroll
                for (int nt = 0; nt < 4; nt++)
                    mma_bf16(acc[mt][nt], alf[mt],
                             bhf[nt >> 1][nt & 1], bhf[nt >> 1][(nt & 1) + 2]);
        }
    }

    const int er = lane >> 2;
    const int ec = (lane & 3) * 2;
    #pragma unroll
    for (int mt = 0; mt < 4; mt++) {
        #pragma unroll
        for (int nt = 0; nt < 4; nt++) {
            const int col = n0 + nw + nt * 8 + ec;
            const float bx = __ldg(&bias[col]);
            const float by = __ldg(&bias[col + 1]);
            const int r0 = m0 + mw + mt * 16 + er;
            float2 v0 = make_float2(acc[mt][nt][0] + bx, acc[mt][nt][1] + by);
            float2 v1 = make_float2(acc[mt][nt][2] + bx, acc[mt][nt][3] + by);
            if (C) {
                *(float2*)(C + (size_t)r0 * N + col) = v0;
                *(float2*)(C + (size_t)(r0 + 8) * N + col) = v1;
            }
            if (Ch) {
                const float s = (qkv_mode && (((col >> 6) % 3) == 0)) ? 0.125f : 1.0f;
                split2(v0.x * s, v0.y * s, Ch + (size_t)r0 * N + col,
                       Cl + (size_t)r0 * N + col);
                split2(v1.x * s, v1.y * s, Ch + (size_t)(r0 + 8) * N + col,
                       Cl + (size_t)(r0 + 8) * N + col);
            }
        }
    }
}

// ---------------------------------------------------------------------------
// Fused prep: split x (bf16 hi/lo) + transpose-split qkv_w + out_w.
// One launch; blockIdx range dispatch.
//   blocks [0, 3072)        : split x (256 float4 per block)
//   blocks [3072, 6144)     : qkv_w transpose tile (96 x 32 grid)
//   blocks [6144, 7168)     : out_w transpose tile (32 x 32 grid)
// ---------------------------------------------------------------------------
__global__ __launch_bounds__(256) void prep_kernel(
    const float* __restrict__ x,
    __nv_bfloat16* __restrict__ ah, __nv_bfloat16* __restrict__ al,
    const float* __restrict__ qkv_w,
    __nv_bfloat16* __restrict__ wqh, __nv_bfloat16* __restrict__ wql,
    const float* __restrict__ out_w,
    __nv_bfloat16* __restrict__ woh, __nv_bfloat16* __restrict__ wol)
{
    __shared__ float t[32][33];
    const int bid = blockIdx.x;
    const int tid = threadIdx.x;
    if (bid < 3072) {
        const int i = bid * 256 + tid;           // n4 = 786432 exact
        float4 v = ((const float4*)x)[i];
        split2(v.x, v.y, ah + 4 * (size_t)i, al + 4 * (size_t)i);
        split2(v.z, v.w, ah + 4 * (size_t)i + 2, al + 4 * (size_t)i + 2);
        return;
    }
    const float* W;
    __nv_bfloat16 *Th, *Tl;
    int N, bx, by;
    if (bid < 6144) {
        const int r = bid - 3072;
        W = qkv_w; Th = wqh; Tl = wql; N = D3c;
        bx = r % 96; by = r / 96;
    } else {
        const int r = bid - 6144;
        W = out_w; Th = woh; Tl = wol; N = Dc;
        bx = r % 32; by = r / 32;
    }
    const int K = Dc;
    const int n0 = bx * 32, k0 = by * 32;
    const int tx = tid & 31, ty = tid >> 5;
    #pragma unroll
    for (int r = 0; r < 4; r++)
        t[ty + 8 * r][tx] = W[(size_t)(k0 + ty + 8 * r) * N + n0 + tx];
    __syncthreads();
    #pragma unroll
    for (int r = 0; r < 4; r++) {
        float v = t[tx][ty + 8 * r];
        __nv_bfloat16 h = __float2bfloat16(v);
        __nv_bfloat16 l = __float2bfloat16(v - __bfloat162float(h));
        size_t o = (size_t)(n0 + ty + 8 * r) * K + k0 + tx;
        Th[o] = h; Tl[o] = l;
    }
}

// ---------------------------------------------------------------------------
// qk HMMA: logits = (scaled q).k, 3-pass bf16 split, interleaved LDSM.
// ---------------------------------------------------------------------------
#define QK_SMEM (4 * 16384)

__global__ __launch_bounds__(256, 2) void qk_mma_kernel(
    const __nv_bfloat16* __restrict__ qkvh, const __nv_bfloat16* __restrict__ qkvl,
    float* __restrict__ attn)
{
    extern __shared__ char smem[];
    const uint32_t sb = smem_u32(smem);
    const int tid = threadIdx.x, wid = tid >> 5, lane = tid & 31;
    const int bh = blockIdx.z, b = bh >> 4, h = bh & 15;
    const int i0 = blockIdx.y * 128, j0 = blockIdx.x * 128;

    #pragma unroll
    for (int t = 0; t < 4; t++) {
        const __nv_bfloat16* base = (t & 1) ? qkvl : qkvh;
        const int roff = (t < 2) ? i0 : j0;
        const int coff = h * 192 + ((t < 2) ? 0 : 64);
        for (int idx = tid; idx < 1024; idx += 256) {
            const int row = idx >> 3, c = idx & 7;
            const uint32_t dst = sb + t * 16384 + row * 128 + ((c ^ (row & 7)) << 4);
            CP_ASYNC16(dst, base + (size_t)(b * Sc + roff + row) * D3c + coff + c * 8);
        }
    }
    CP_COMMIT(); CP_WAIT0();
    __syncthreads();

    const int mw = (wid & 1) * 64;
    const int nw = (wid >> 1) * 32;
    const int frow = lane & 15, fc = lane >> 4;

    float acc[4][4][4];
    #pragma unroll
    for (int i = 0; i < 4; i++)
        #pragma unroll
        for (int j = 0; j < 4; j++)
            #pragma unroll
            for (int r = 0; r < 4; r++) acc[i][j][r] = 0.f;

    #pragma unroll
    for (int ks = 0; ks < 4; ks++) {
        uint32_t aadr[4], badr[2];
        #pragma unroll
        for (int mt = 0; mt < 4; mt++) {
            const int row = mw + mt * 16 + frow;
            aadr[mt] = row * 128 + (((2 * ks + fc) ^ (row & 7)) << 4);
        }
        #pragma unroll
        for (int bt = 0; bt < 2; bt++) {
            const int row = nw + bt * 16 + frow;
            badr[bt] = row * 128 + (((2 * ks + fc) ^ (row & 7)) << 4);
        }
        uint32_t ahf[4][4], bhf[2][4];
        #pragma unroll
        for (int mt = 0; mt < 4; mt++) LDSM_X4(ahf[mt], sb + aadr[mt]);
        #pragma unroll
        for (int bt = 0; bt < 2; bt++) LDSM_X4(bhf[bt], sb + 2 * 16384 + badr[bt]);
        #pragma unroll
        for (int mt = 0; mt < 4; mt++)
            #pragma unroll
            for (int nt = 0; nt < 4; nt++)
                mma_bf16(acc[mt][nt], ahf[mt],
                         bhf[nt >> 1][nt & 1], bhf[nt >> 1][(nt & 1) + 2]);
        uint32_t blf[2][4];
        #pragma unroll
        for (int bt = 0; bt < 2; bt++) LDSM_X4(blf[bt], sb + 3 * 16384 + badr[bt]);
        #pragma unroll
        for (int mt = 0; mt < 4; mt++)
            #pragma unroll
            for (int nt = 0; nt < 4; nt++)
                mma_bf16(acc[mt][nt], ahf[mt],
                         blf[nt >> 1][nt & 1], blf[nt >> 1][(nt & 1) + 2]);
        uint32_t alf[4][4];
        #pragma unroll
        for (int mt = 0; mt < 4; mt++) LDSM_X4(alf[mt], sb + 16384 + aadr[mt]);
        #pragma unroll
        for (int mt = 0; mt < 4; mt++)
            #pragma unroll
            for (int nt = 0; nt < 4; nt++)
                mma_bf16(acc[mt][nt], alf[mt],
                         bhf[nt >> 1][nt & 1], bhf[nt >> 1][(nt & 1) + 2]);
    }

    const int er = lane >> 2, ec = (lane & 3) * 2;
    float* ob = attn + (size_t)bh * Sc * Sc;
    #pragma unroll
    for (int mt = 0; mt < 4; mt++) {
        #pragma unroll
        for (int nt = 0; nt < 4; nt++) {
            const int r0 = i0 + mw + mt * 16 + er;
            const int col = j0 + nw + nt * 8 + ec;
            *(float2*)(ob + (size_t)r0 * Sc + col) =
                make_float2(acc[mt][nt][0], acc[mt][nt][1]);
            *(float2*)(ob + (size_t)(r0 + 8) * Sc + col) =
                make_float2(acc[mt][nt][2], acc[mt][nt][3]);
        }
    }
}

// ---------------------------------------------------------------------------
// Fused XL relative bias + row softmax (per-(h,i) block; best-known layout).
// R11: coalesced 16B q-gather via Qraw staging; attn rows prefetched into L
// with cp.async at kernel start, overlapping the FFMA phase.
// ---------------------------------------------------------------------------
__global__ __launch_bounds__(128) void rpe_softmax_kernel(
    const __nv_bfloat16* __restrict__ qkvh, const __nv_bfloat16* __restrict__ qkvl,
    const float* __restrict__ rpe, float* __restrict__ attn)
{
    const int h = blockIdx.x / Sc;
    const int i = blockIdx.x % Sc;
    const int r0 = 384 + 24 * (i & 15) - 24 * h - (i >> 4);
    const float* rbase = rpe + (size_t)r0 * 1024;
    __shared__ __align__(16) unsigned long long Qp[256]; // [dd*4+p] = (q[2p][dd], q[2p+1][dd])
    __shared__ __align__(16) float L[Bc][Sc];
    __shared__ __align__(16) __nv_bfloat16 Qraw[2][Bc][HDc];
    const int tid = threadIdx.x;

    // prefetch attn rows (8 x 384 fp32 = 768 x 16B) into L, async
    const uint32_t Lbase = smem_u32(&L[0][0]);
    #pragma unroll
    for (int r = 0; r < 6; r++) {
        const int idx = tid + r * 128;
        const int b = idx / 96;
        const int c = idx % 96;
        CP_ASYNC16(Lbase + (uint32_t)(b * Sc + c * 4) * 4,
                   attn + ((size_t)(b * Hc + h) * Sc + i) * Sc + c * 4);
    }
    CP_COMMIT();

    // coalesced q gather: one LDG.128 per thread into Qraw
    {
        const int arr = tid >> 6;            // 0 = hi, 1 = lo
        const int b   = (tid >> 3) & 7;
        const int c   = tid & 7;
        const __nv_bfloat16* src = arr ? qkvl : qkvh;
        const uint4 v = *(const uint4*)(src + (size_t)(b * Sc + i) * D3c + h * 192 + c * 8);
        *(uint4*)&Qraw[arr][b][c * 8] = v;
    }
    __syncthreads();
    // repack (x8 undoes qk pre-scale; exact pow2)
    for (int t = tid; t < 256; t += 128) {
        const int p = t & 3, dd = t >> 2;
        const float q0 = (__bfloat162float(Qraw[0][2 * p][dd]) +
                          __bfloat162float(Qraw[1][2 * p][dd])) * 8.f;
        const float q1 = (__bfloat162float(Qraw[0][2 * p + 1][dd]) +
                          __bfloat162float(Qraw[1][2 * p + 1][dd])) * 8.f;
        Qp[t] = packf2(q0, q1);
    }
    __syncthreads();

    unsigned long long acc2[3][4];
    #pragma unroll
    for (int jj = 0; jj < 3; jj++)
        #pragma unroll
        for (int p = 0; p < 4; p++) acc2[jj][p] = 0ull;

    #pragma unroll
    for (int c = 0; c < 16; c++) {
        unsigned long long qp[4][4];
        #pragma unroll
        for (int d2 = 0; d2 < 4; d2++)
            #pragma unroll
            for (int p = 0; p < 4; p++)
                qp[d2][p] = Qp[(c * 4 + d2) * 4 + p];
        #pragma unroll
        for (int jj = 0; jj < 3; jj++) {
            const int j = tid + jj * 128;
            const float4 rv = *(const float4*)(rbase + (size_t)j * 64 + c * 4);
            const unsigned long long s0 = packf2(rv.x, rv.x);
            const unsigned long long s1 = packf2(rv.y, rv.y);
            const unsigned long long s2 = packf2(rv.z, rv.z);
            const unsigned long long s3 = packf2(rv.w, rv.w);
            #pragma unroll
            for (int p = 0; p < 4; p++) {
                FFMA2(acc2[jj][p], qp[0][p], s0);
                FFMA2(acc2[jj][p], qp[1][p], s1);
                FFMA2(acc2[jj][p], qp[2][p], s2);
                FFMA2(acc2[jj][p], qp[3][p], s3);
            }
        }
    }
    // attn rows must be resident in L before in-smem add
    CP_WAIT0();
    __syncthreads();
    #pragma unroll
    for (int jj = 0; jj < 3; jj++) {
        const int j = tid + jj * 128;
        #pragma unroll
        for (int p = 0; p < 4; p++) {
            float lo, hi;
            unpackf2(acc2[jj][p], lo, hi);
            L[2 * p][j] += lo;
            L[2 * p + 1][j] += hi;
        }
    }
    __syncthreads();

    const int wrp = tid >> 5, lane = tid & 31;
    #pragma unroll
    for (int bb = 0; bb < 2; bb++) {
        const int b = wrp * 2 + bb;
        float v[12];
        float m = -1e30f;
        #pragma unroll
        for (int r = 0; r < 12; r++) { v[r] = L[b][lane + 32 * r]; m = fmaxf(m, v[r]); }
        #pragma unroll
        for (int o = 16; o > 0; o >>= 1) m = fmaxf(m, __shfl_xor_sync(0xffffffffu, m, o));
        float s = 0.f;
        #pragma unroll
        for (int r = 0; r < 12; r++) { v[r] = __expf(v[r] - m); s += v[r]; }
        #pragma unroll
        for (int o = 16; o > 0; o >>= 1) s += __shfl_xor_sync(0xffffffffu, s, o);
        const float inv = 1.0f / s;
        float* orow = attn + ((size_t)(b * Hc + h) * Sc + i) * Sc;
        #pragma unroll
        for (int r = 0; r < 12; r++) orow[lane + 32 * r] = v[r] * inv;
    }
}

// ---------------------------------------------------------------------------
// av HMMA: values = attn(fp32) @ v, 3-pass bf16 split.
// ---------------------------------------------------------------------------
#define AV_AROW 72
#define AV_ATILE (128 * AV_AROW * 4)
#define AV_VTILE 8192
#define AV_STAGE (AV_ATILE + 2 * AV_VTILE)
#define AV_SMEM  (2 * AV_STAGE)

__global__ __launch_bounds__(256, 2) void av_mma_kernel(
    const float* __restrict__ attn,
    const __nv_bfloat16* __restrict__ qkvh, const __nv_bfloat16* __restrict__ qkvl,
    __nv_bfloat16* __restrict__ vh_out, __nv_bfloat16* __restrict__ vl_out)
{
    extern __shared__ char smem[];
    const uint32_t sb = smem_u32(smem);
    float* sA_f = (float*)smem;
    const int tid = threadIdx.x, wid = tid >> 5, lane = tid & 31;
    const int bh = blockIdx.y, b = bh >> 4, h = bh & 15;
    const int i0 = blockIdx.x * 128;

    const float* abase = attn + ((size_t)bh * Sc + i0) * Sc;
    const __nv_bfloat16* vbase_h = qkvh + h * 192 + 128;
    const __nv_bfloat16* vbase_l = qkvl + h * 192 + 128;

    auto issue = [&](int ck) {
        if (ck >= 6) { CP_COMMIT(); return; }
        const uint32_t st = sb + (ck & 1) * AV_STAGE;
        const int j0 = ck * 64;
        for (int idx = tid; idx < 2048; idx += 256) {
            const int row = idx >> 4, c = idx & 15;
            CP_ASYNC16(st + row * (AV_AROW * 4) + c * 16,
                       abase + (size_t)row * Sc + j0 + c * 4);
        }
        for (int idx = tid; idx < 512; idx += 256) {
            const int row = idx >> 3, c = idx & 7;
            const uint32_t sw = row * 128 + ((c ^ (row & 7)) << 4);
            const size_t go = (size_t)(b * Sc + j0 + row) * D3c + c * 8;
            CP_ASYNC16(st + AV_ATILE + sw, vbase_h + go);
            CP_ASYNC16(st + AV_ATILE + AV_VTILE + sw, vbase_l + go);
        }
        CP_COMMIT();
    };

    const int wm = (wid & 3) * 32;
    const int wn = (wid >> 2) * 32;
    const int er = lane >> 2;
    const int ecb = (lane & 3) * 2;
    const int krow = (lane & 7) | ((lane & 16) >> 1);
    const int colc = (lane >> 3) & 1;

    float acc[2][4][4];
    #pragma unroll
    for (int i = 0; i < 2; i++)
        #pragma unroll
        for (int j = 0; j < 4; j++)
            #pragma unroll
            for (int r = 0; r < 4; r++) acc[i][j][r] = 0.f;

    issue(0);
    for (int ck = 0; ck < 6; ck++) {
        issue(ck + 1);
        CP_WAIT1();
        __syncthreads();
        const int stg = (ck & 1);
        float* sA = sA_f + stg * (AV_STAGE / 4);
        const uint32_t vt_h = sb + stg * AV_STAGE + AV_ATILE;
        const uint32_t vt_l = vt_h + AV_VTILE;
        #pragma unroll
        for (int ks = 0; ks < 4; ks++) {
            uint32_t ahf[2][4], alf[2][4];
            #pragma unroll
            for (int mt = 0; mt < 2; mt++) {
                const int r_ = wm + mt * 16 + er;
                const int cb = ks * 16 + ecb;
                float2 x0 = *(float2*)(sA + (size_t)r_ * AV_AROW + cb);
                float2 x1 = *(float2*)(sA + (size_t)(r_ + 8) * AV_AROW + cb);
                float2 x2 = *(float2*)(sA + (size_t)r_ * AV_AROW + cb + 8);
                float2 x3 = *(float2*)(sA + (size_t)(r_ + 8) * AV_AROW + cb + 8);
                pack_hilo(x0.x, x0.y, ahf[mt][0], alf[mt][0]);
                pack_hilo(x1.x, x1.y, ahf[mt][1], alf[mt][1]);
                pack_hilo(x2.x, x2.y, ahf[mt][2], alf[mt][2]);
                pack_hilo(x3.x, x3.y, ahf[mt][3], alf[mt][3]);
            }
            uint32_t badr[2];
            #pragma unroll
            for (int bt = 0; bt < 2; bt++) {
                const int row = ks * 16 + krow;
                const int c = (wn >> 3) + bt * 2 + colc;
                badr[bt] = row * 128 + ((c ^ (row & 7)) << 4);
            }
            uint32_t bhf[2][4], blf[2][4];
            #pragma unroll
            for (int bt = 0; bt < 2; bt++) LDSM_X4_T(bhf[bt], vt_h + badr[bt]);
            #pragma unroll
            for (int bt = 0; bt < 2; bt++) LDSM_X4_T(blf[bt], vt_l + badr[bt]);
            #pragma unroll
            for (int mt = 0; mt < 2; mt++)
                #pragma unroll
                for (int nt = 0; nt < 4; nt++)
                    mma_bf16(acc[mt][nt], ahf[mt],
                             bhf[nt >> 1][nt & 1], bhf[nt >> 1][(nt & 1) + 2]);
            #pragma unroll
            for (int mt = 0; mt < 2; mt++)
                #pragma unroll
                for (int nt = 0; nt < 4; nt++)
                    mma_bf16(acc[mt][nt], alf[mt],
                             bhf[nt >> 1][nt & 1], bhf[nt >> 1][(nt & 1) + 2]);
            #pragma unroll
            for (int mt = 0; mt < 2; mt++)
                #pragma unroll
                for (int nt = 0; nt < 4; nt++)
                    mma_bf16(acc[mt][nt], ahf[mt],
                             blf[nt >> 1][nt & 1], blf[nt >> 1][(nt & 1) + 2]);
        }
        __syncthreads();
    }

    const int ec = (lane & 3) * 2;
    #pragma unroll
    for (int mt = 0; mt < 2; mt++) {
        #pragma unroll
        for (int nt = 0; nt < 4; nt++) {
            const int row = i0 + wm + mt * 16 + er;
            const int col = h * 64 + wn + nt * 8 + ec;
            const size_t o0 = (size_t)(b * Sc + row) * Dc + col;
            const size_t o1 = (size_t)(b * Sc + row + 8) * Dc + col;
            split2(acc[mt][nt][0], acc[mt][nt][1], vh_out + o0, vl_out + o0);
            split2(acc[mt][nt][2], acc[mt][nt][3], vh_out + o1, vl_out + o1);
        }
    }
}

// ---------------------------------------------------------------------------
extern "C" void kernel_launch(void* const* d_in, const int* in_sizes, int n_in,
                              void* d_out, int out_size)
{
    const float* x     = (const float*)d_in[0];
    const float* qkv_w = (const float*)d_in[1];
    const float* qkv_b = (const float*)d_in[2];
    const float* out_w = (const float*)d_in[3];
    const float* out_b = (const float*)d_in[4];
    const float* rpe   = (const float*)d_in[5];

    float* attnscr;
    __nv_bfloat16 *ah, *al, *wqh, *wql, *woh, *wol, *qkvh, *qkvl;
    cudaGetSymbolAddress((void**)&attnscr, g_attn);
    cudaGetSymbolAddress((void**)&ah, g_ah);
    cudaGetSymbolAddress((void**)&al, g_al);
    cudaGetSymbolAddress((void**)&wqh, g_wqh);
    cudaGetSymbolAddress((void**)&wql, g_wql);
    cudaGetSymbolAddress((void**)&woh, g_woh);
    cudaGetSymbolAddress((void**)&wol, g_wol);
    cudaGetSymbolAddress((void**)&qkvh, g_qkvh);
    cudaGetSymbolAddress((void**)&qkvl, g_qkvl);

    float* out = (float*)d_out;
    const long OUT_E = (long)BSc * Dc;
    const long ATT_E = (long)Bc * Hc * Sc * Sc;
    float* attn = ((long)out_size >= OUT_E + ATT_E) ? (out + OUT_E) : attnscr;

    cudaFuncSetAttribute(mma_gemm_kernel,
                         cudaFuncAttributeMaxDynamicSharedMemorySize, GSMEM);
    cudaFuncSetAttribute(qk_mma_kernel,
                         cudaFuncAttributeMaxDynamicSharedMemorySize, QK_SMEM);
    cudaFuncSetAttribute(av_mma_kernel,
                         cudaFuncAttributeMaxDynamicSharedMemorySize, AV_SMEM);

    // 0) fused prep: split x + transpose-split both weights (one launch)
    prep_kernel<<<7168, 256>>>(x, ah, al, qkv_w, wqh, wql, out_w, woh, wol);

    // 1) qkv: emit bf16 hi/lo (q cols pre-scaled 1/8)
    mma_gemm_kernel<<<dim3(D3c / 128, BSc / 128), 256, GSMEM>>>(
        ah, al, wqh, wql, qkv_b, nullptr, qkvh, qkvl, 1, BSc, D3c, Dc);
    // 2) logits = (q/8) . k
    qk_mma_kernel<<<dim3(3, 3, Bc * Hc), 256, QK_SMEM>>>(qkvh, qkvl, attn);
    // 3+4) rpe bias (f32x2, coalesced gather, attn prefetch) + softmax
    rpe_softmax_kernel<<<Hc * Sc, 128>>>(qkvh, qkvl, rpe, attn);
    // 5) values = attn @ v -> bf16 hi/lo
    av_mma_kernel<<<dim3(3, Bc * Hc), 256, AV_SMEM>>>(attn, qkvh, qkvl, ah, al);
    // 6) out = values @ out_w + out_b
    mma_gemm_kernel<<<dim3(Dc / 128, BSc / 128), 256, GSMEM>>>(
        ah, al, woh, wol, out_b, out, nullptr, nullptr, 0, BSc, Dc, Dc);
}

// round 12
// speedup vs baseline: 1.3048x; 1.0943x over previous
#include <cuda_runtime.h>
#include <cuda_bf16.h>
#include <cstdint>

#define Bc 8
#define Sc 384
#define Dc 1024
#define Hc 16
#define HDc 64
#define D3c 3072
#define BSc 3072   // B*S

// ---------------------------------------------------------------------------
// Scratch (static device globals; no runtime allocation)
// ---------------------------------------------------------------------------
__device__ float g_attn[(size_t)Bc * Hc * Sc * Sc];   // fallback attn buffer
__device__ __align__(16) __nv_bfloat16 g_ah[(size_t)BSc * Dc];    // A hi (x, then vals)
__device__ __align__(16) __nv_bfloat16 g_al[(size_t)BSc * Dc];    // A lo
__device__ __align__(16) __nv_bfloat16 g_wqh[(size_t)D3c * Dc];   // qkv_w^T hi [N,K]
__device__ __align__(16) __nv_bfloat16 g_wql[(size_t)D3c * Dc];   // qkv_w^T lo
__device__ __align__(16) __nv_bfloat16 g_woh[(size_t)Dc * Dc];    // out_w^T hi
__device__ __align__(16) __nv_bfloat16 g_wol[(size_t)Dc * Dc];    // out_w^T lo
__device__ __align__(16) __nv_bfloat16 g_qkvh[(size_t)BSc * D3c]; // qkv hi (q pre-scaled /8)
__device__ __align__(16) __nv_bfloat16 g_qkvl[(size_t)BSc * D3c]; // qkv lo

// ---------------------------------------------------------------------------
// Baseline-PTX helpers
// ---------------------------------------------------------------------------
__device__ __forceinline__ uint32_t smem_u32(const void* p) {
    uint32_t a;
    asm("{ .reg .u64 t; cvta.to.shared.u64 t, %1; cvt.u32.u64 %0, t; }" : "=r"(a) : "l"(p));
    return a;
}
#define CP_ASYNC16(sm, gp) \
    asm volatile("cp.async.cg.shared.global [%0], [%1], 16;" :: "r"(sm), "l"(gp))
#define CP_COMMIT() asm volatile("cp.async.commit_group;" ::: "memory")
#define CP_WAIT0()  asm volatile("cp.async.wait_group 0;" ::: "memory")
#define CP_WAIT1()  asm volatile("cp.async.wait_group 1;" ::: "memory")

#define LDSM_X4(r, a) \
    asm volatile("ldmatrix.sync.aligned.m8n8.x4.shared.b16 {%0,%1,%2,%3}, [%4];" \
        : "=r"((r)[0]), "=r"((r)[1]), "=r"((r)[2]), "=r"((r)[3]) : "r"(a))
#define LDSM_X4_T(r, a) \
    asm volatile("ldmatrix.sync.aligned.m8n8.x4.trans.shared.b16 {%0,%1,%2,%3}, [%4];" \
        : "=r"((r)[0]), "=r"((r)[1]), "=r"((r)[2]), "=r"((r)[3]) : "r"(a))

__device__ __forceinline__ void mma_bf16(float* d, const uint32_t* a,
                                         uint32_t b0, uint32_t b1) {
    asm volatile(
        "mma.sync.aligned.m16n8k16.row.col.f32.bf16.bf16.f32 "
        "{%0,%1,%2,%3}, {%4,%5,%6,%7}, {%8,%9}, {%0,%1,%2,%3};"
        : "+f"(d[0]), "+f"(d[1]), "+f"(d[2]), "+f"(d[3])
        : "r"(a[0]), "r"(a[1]), "r"(a[2]), "r"(a[3]), "r"(b0), "r"(b1));
}

// packed f32x2 (Blackwell FFMA2; baseline sm_100+ PTX)
__device__ __forceinline__ unsigned long long packf2(float x, float y) {
    unsigned long long r;
    asm("mov.b64 %0, {%1, %2};" : "=l"(r) : "f"(x), "f"(y));
    return r;
}
#define FFMA2(acc, a, b) \
    asm("fma.rn.f32x2 %0, %1, %2, %0;" : "+l"(acc) : "l"(a), "l"(b))
__device__ __forceinline__ void unpackf2(unsigned long long v, float& lo, float& hi) {
    asm("mov.b64 {%0, %1}, %2;" : "=f"(lo), "=f"(hi) : "l"(v));
}

__device__ __forceinline__ void split2(float x, float y,
                                       __nv_bfloat16* ph, __nv_bfloat16* pl) {
    __nv_bfloat16 hx = __float2bfloat16(x), hy = __float2bfloat16(y);
    *(__nv_bfloat162*)ph = __nv_bfloat162(hx, hy);
    *(__nv_bfloat162*)pl = __nv_bfloat162(
        __float2bfloat16(x - __bfloat162float(hx)),
        __float2bfloat16(y - __bfloat162float(hy)));
}
__device__ __forceinline__ void pack_hilo(float x, float y,
                                          uint32_t& hi, uint32_t& lo) {
    __nv_bfloat16 hx = __float2bfloat16(x), hy = __float2bfloat16(y);
    __nv_bfloat162 h2(hx, hy);
    __nv_bfloat162 l2(__float2bfloat16(x - __bfloat162float(hx)),
                      __float2bfloat16(y - __bfloat162float(hy)));
    hi = *(uint32_t*)&h2;
    lo = *(uint32_t*)&l2;
}

// ---------------------------------------------------------------------------
// HMMA bf16-split GEMM: C = (Ah+Al)@(Bh+Bl)^T + bias
// Single-sync mainloop: wait group -> barrier -> issue(it+2) -> compute(it).
// ---------------------------------------------------------------------------
#define TILE_B 8192
#define BUF_B  (4 * TILE_B)
#define NSTAGE 3
#define GSMEM  (NSTAGE * BUF_B)   // 96 KB

__global__ __launch_bounds__(256, 2) void mma_gemm_kernel(
    const __nv_bfloat16* __restrict__ Ah, const __nv_bfloat16* __restrict__ Al,
    const __nv_bfloat16* __restrict__ Bh, const __nv_bfloat16* __restrict__ Bl,
    const float* __restrict__ bias, float* __restrict__ C,
    __nv_bfloat16* __restrict__ Ch, __nv_bfloat16* __restrict__ Cl,
    int qkv_mode, int M, int N, int K)
{
    extern __shared__ char smem[];
    const uint32_t sbase = smem_u32(smem);
    const int tid  = threadIdx.x;
    const int wid  = tid >> 5;
    const int lane = tid & 31;
    const int m0 = blockIdx.y * 128;
    const int n0 = blockIdx.x * 128;
    const int mw = (wid & 1) * 64;
    const int nw = (wid >> 1) * 32;

    const int lrow = tid >> 1;
    const int c0   = (tid & 1) * 2;
    const int sw0  = (lrow >> 1) & 3;
    const __nv_bfloat16* gAh = Ah + (size_t)(m0 + lrow) * K;
    const __nv_bfloat16* gAl = Al + (size_t)(m0 + lrow) * K;
    const __nv_bfloat16* gBh = Bh + (size_t)(n0 + lrow) * K;
    const __nv_bfloat16* gBl = Bl + (size_t)(n0 + lrow) * K;
    const uint32_t soff0 = lrow * 64 + (((c0 + 0) ^ sw0) << 4);
    const uint32_t soff1 = lrow * 64 + (((c0 + 1) ^ sw0) << 4);

    const int NK = K >> 5;

    auto issue = [&](int it) {
        if (it < NK) {
            const uint32_t tb = sbase + (it % NSTAGE) * BUF_B;
            const int k0 = it << 5;
            CP_ASYNC16(tb + 0 * TILE_B + soff0, gAh + k0 + (c0 + 0) * 8);
            CP_ASYNC16(tb + 0 * TILE_B + soff1, gAh + k0 + (c0 + 1) * 8);
            CP_ASYNC16(tb + 1 * TILE_B + soff0, gAl + k0 + (c0 + 0) * 8);
            CP_ASYNC16(tb + 1 * TILE_B + soff1, gAl + k0 + (c0 + 1) * 8);
            CP_ASYNC16(tb + 2 * TILE_B + soff0, gBh + k0 + (c0 + 0) * 8);
            CP_ASYNC16(tb + 2 * TILE_B + soff1, gBh + k0 + (c0 + 1) * 8);
            CP_ASYNC16(tb + 3 * TILE_B + soff0, gBl + k0 + (c0 + 0) * 8);
            CP_ASYNC16(tb + 3 * TILE_B + soff1, gBl + k0 + (c0 + 1) * 8);
        }
        CP_COMMIT();
    };

    const int frow = lane & 15;
    const int fc   = lane >> 4;
    auto fr_addr = [&](int rbase) -> uint32_t {
        const int row = rbase + frow;
        return (uint32_t)(row * 64 + ((fc ^ ((row >> 1) & 3)) << 4));
    };
    const uint32_t aoff = fr_addr(mw);
    const uint32_t boff = fr_addr(nw);

    float acc[4][4][4];
    #pragma unroll
    for (int i = 0; i < 4; i++)
        #pragma unroll
        for (int j = 0; j < 4; j++)
            #pragma unroll
            for (int r = 0; r < 4; r++) acc[i][j][r] = 0.f;

    issue(0); issue(1);

    for (int it = 0; it < NK; it++) {
        CP_WAIT1();
        __syncthreads();
        issue(it + 2);
        const uint32_t tb = sbase + (it % NSTAGE) * BUF_B;
        #pragma unroll
        for (int ks = 0; ks < 2; ks++) {
            const uint32_t kx = ks ? 32u : 0u;
            uint32_t ahf[4][4], bhf[2][4];
            #pragma unroll
            for (int mt = 0; mt < 4; mt++)
                LDSM_X4(ahf[mt], tb + ((aoff + mt * 1024) ^ kx));
            #pragma unroll
            for (int bt = 0; bt < 2; bt++)
                LDSM_X4(bhf[bt], tb + 2 * TILE_B + ((boff + bt * 1024) ^ kx));
            #pragma unroll
            for (int mt = 0; mt < 4; mt++)
                #pragma unroll
                for (int nt = 0; nt < 4; nt++)
                    mma_bf16(acc[mt][nt], ahf[mt],
                             bhf[nt >> 1][nt & 1], bhf[nt >> 1][(nt & 1) + 2]);
            uint32_t blf[2][4];
            #pragma unroll
            for (int bt = 0; bt < 2; bt++)
                LDSM_X4(blf[bt], tb + 3 * TILE_B + ((boff + bt * 1024) ^ kx));
            #pragma unroll
            for (int mt = 0; mt < 4; mt++)
                #pragma unroll
                for (int nt = 0; nt < 4; nt++)
                    mma_bf16(acc[mt][nt], ahf[mt],
                             blf[nt >> 1][nt & 1], blf[nt >> 1][(nt & 1) + 2]);
            uint32_t alf[4][4];
            #pragma unroll
            for (int mt = 0; mt < 4; mt++)
                LDSM_X4(alf[mt], tb + TILE_B + ((aoff + mt * 1024) ^ kx));
            #pragma unroll
            for (int mt = 0; mt < 4; mt++)
                #pragma unroll
                for (int nt = 0; nt < 4; nt++)
                    mma_bf16(acc[mt][nt], alf[mt],
                             bhf[nt >> 1][nt & 1], bhf[nt >> 1][(nt & 1) + 2]);
        }
    }

    const int er = lane >> 2;
    const int ec = (lane & 3) * 2;
    #pragma unroll
    for (int mt = 0; mt < 4; mt++) {
        #pragma unroll
        for (int nt = 0; nt < 4; nt++) {
            const int col = n0 + nw + nt * 8 + ec;
            const float bx = __ldg(&bias[col]);
            const float by = __ldg(&bias[col + 1]);
            const int r0 = m0 + mw + mt * 16 + er;
            float2 v0 = make_float2(acc[mt][nt][0] + bx, acc[mt][nt][1] + by);
            float2 v1 = make_float2(acc[mt][nt][2] + bx, acc[mt][nt][3] + by);
            if (C) {
                *(float2*)(C + (size_t)r0 * N + col) = v0;
                *(float2*)(C + (size_t)(r0 + 8) * N + col) = v1;
            }
            if (Ch) {
                const float s = (qkv_mode && (((col >> 6) % 3) == 0)) ? 0.125f : 1.0f;
                split2(v0.x * s, v0.y * s, Ch + (size_t)r0 * N + col,
                       Cl + (size_t)r0 * N + col);
                split2(v1.x * s, v1.y * s, Ch + (size_t)(r0 + 8) * N + col,
                       Cl + (size_t)(r0 + 8) * N + col);
            }
        }
    }
}

// ---------------------------------------------------------------------------
// Fused prep: split x + transpose-split qkv_w + out_w (one launch).
// ---------------------------------------------------------------------------
__global__ __launch_bounds__(256) void prep_kernel(
    const float* __restrict__ x,
    __nv_bfloat16* __restrict__ ah, __nv_bfloat16* __restrict__ al,
    const float* __restrict__ qkv_w,
    __nv_bfloat16* __restrict__ wqh, __nv_bfloat16* __restrict__ wql,
    const float* __restrict__ out_w,
    __nv_bfloat16* __restrict__ woh, __nv_bfloat16* __restrict__ wol)
{
    __shared__ float t[32][33];
    const int bid = blockIdx.x;
    const int tid = threadIdx.x;
    if (bid < 3072) {
        const int i = bid * 256 + tid;
        float4 v = ((const float4*)x)[i];
        split2(v.x, v.y, ah + 4 * (size_t)i, al + 4 * (size_t)i);
        split2(v.z, v.w, ah + 4 * (size_t)i + 2, al + 4 * (size_t)i + 2);
        return;
    }
    const float* W;
    __nv_bfloat16 *Th, *Tl;
    int N, bx, by;
    if (bid < 6144) {
        const int r = bid - 3072;
        W = qkv_w; Th = wqh; Tl = wql; N = D3c;
        bx = r % 96; by = r / 96;
    } else {
        const int r = bid - 6144;
        W = out_w; Th = woh; Tl = wol; N = Dc;
        bx = r % 32; by = r / 32;
    }
    const int K = Dc;
    const int n0 = bx * 32, k0 = by * 32;
    const int tx = tid & 31, ty = tid >> 5;
    #pragma unroll
    for (int r = 0; r < 4; r++)
        t[ty + 8 * r][tx] = W[(size_t)(k0 + ty + 8 * r) * N + n0 + tx];
    __syncthreads();
    #pragma unroll
    for (int r = 0; r < 4; r++) {
        float v = t[tx][ty + 8 * r];
        __nv_bfloat16 h = __float2bfloat16(v);
        __nv_bfloat16 l = __float2bfloat16(v - __bfloat162float(h));
        size_t o = (size_t)(n0 + ty + 8 * r) * K + k0 + tx;
        Th[o] = h; Tl[o] = l;
    }
}

// ---------------------------------------------------------------------------
// qk HMMA: logits = (scaled q).k, 3-pass bf16 split, interleaved LDSM.
// ---------------------------------------------------------------------------
#define QK_SMEM (4 * 16384)

__global__ __launch_bounds__(256, 2) void qk_mma_kernel(
    const __nv_bfloat16* __restrict__ qkvh, const __nv_bfloat16* __restrict__ qkvl,
    float* __restrict__ attn)
{
    extern __shared__ char smem[];
    const uint32_t sb = smem_u32(smem);
    const int tid = threadIdx.x, wid = tid >> 5, lane = tid & 31;
    const int bh = blockIdx.z, b = bh >> 4, h = bh & 15;
    const int i0 = blockIdx.y * 128, j0 = blockIdx.x * 128;

    #pragma unroll
    for (int t = 0; t < 4; t++) {
        const __nv_bfloat16* base = (t & 1) ? qkvl : qkvh;
        const int roff = (t < 2) ? i0 : j0;
        const int coff = h * 192 + ((t < 2) ? 0 : 64);
        for (int idx = tid; idx < 1024; idx += 256) {
            const int row = idx >> 3, c = idx & 7;
            const uint32_t dst = sb + t * 16384 + row * 128 + ((c ^ (row & 7)) << 4);
            CP_ASYNC16(dst, base + (size_t)(b * Sc + roff + row) * D3c + coff + c * 8);
        }
    }
    CP_COMMIT(); CP_WAIT0();
    __syncthreads();

    const int mw = (wid & 1) * 64;
    const int nw = (wid >> 1) * 32;
    const int frow = lane & 15, fc = lane >> 4;

    float acc[4][4][4];
    #pragma unroll
    for (int i = 0; i < 4; i++)
        #pragma unroll
        for (int j = 0; j < 4; j++)
            #pragma unroll
            for (int r = 0; r < 4; r++) acc[i][j][r] = 0.f;

    #pragma unroll
    for (int ks = 0; ks < 4; ks++) {
        uint32_t aadr[4], badr[2];
        #pragma unroll
        for (int mt = 0; mt < 4; mt++) {
            const int row = mw + mt * 16 + frow;
            aadr[mt] = row * 128 + (((2 * ks + fc) ^ (row & 7)) << 4);
        }
        #pragma unroll
        for (int bt = 0; bt < 2; bt++) {
            const int row = nw + bt * 16 + frow;
            badr[bt] = row * 128 + (((2 * ks + fc) ^ (row & 7)) << 4);
        }
        uint32_t ahf[4][4], bhf[2][4];
        #pragma unroll
        for (int mt = 0; mt < 4; mt++) LDSM_X4(ahf[mt], sb + aadr[mt]);
        #pragma unroll
        for (int bt = 0; bt < 2; bt++) LDSM_X4(bhf[bt], sb + 2 * 16384 + badr[bt]);
        #pragma unroll
        for (int mt = 0; mt < 4; mt++)
            #pragma unroll
            for (int nt = 0; nt < 4; nt++)
                mma_bf16(acc[mt][nt], ahf[mt],
                         bhf[nt >> 1][nt & 1], bhf[nt >> 1][(nt & 1) + 2]);
        uint32_t blf[2][4];
        #pragma unroll
        for (int bt = 0; bt < 2; bt++) LDSM_X4(blf[bt], sb + 3 * 16384 + badr[bt]);
        #pragma unroll
        for (int mt = 0; mt < 4; mt++)
            #pragma unroll
            for (int nt = 0; nt < 4; nt++)
                mma_bf16(acc[mt][nt], ahf[mt],
                         blf[nt >> 1][nt & 1], blf[nt >> 1][(nt & 1) + 2]);
        uint32_t alf[4][4];
        #pragma unroll
        for (int mt = 0; mt < 4; mt++) LDSM_X4(alf[mt], sb + 16384 + aadr[mt]);
        #pragma unroll
        for (int mt = 0; mt < 4; mt++)
            #pragma unroll
            for (int nt = 0; nt < 4; nt++)
                mma_bf16(acc[mt][nt], alf[mt],
                         bhf[nt >> 1][nt & 1], bhf[nt >> 1][(nt & 1) + 2]);
    }

    const int er = lane >> 2, ec = (lane & 3) * 2;
    float* ob = attn + (size_t)bh * Sc * Sc;
    #pragma unroll
    for (int mt = 0; mt < 4; mt++) {
        #pragma unroll
        for (int nt = 0; nt < 4; nt++) {
            const int r0 = i0 + mw + mt * 16 + er;
            const int col = j0 + nw + nt * 8 + ec;
            *(float2*)(ob + (size_t)r0 * Sc + col) =
                make_float2(acc[mt][nt][0], acc[mt][nt][1]);
            *(float2*)(ob + (size_t)(r0 + 8) * Sc + col) =
                make_float2(acc[mt][nt][2], acc[mt][nt][3]);
        }
    }
}

// ---------------------------------------------------------------------------
// Fused XL relative bias + row softmax — 2 diagonal-adjacent items per block,
// processed IN PARALLEL in the same loop (slab LDG shared by both items).
// r0 = 384 + 24*d - a is h-independent on a diagonal, so (h, h+1) share it.
// grid = (744 diagonals, 8 pair slots); invalid slots exit; odd tails
// duplicate item0 (identical redundant stores, benign).
// ---------------------------------------------------------------------------
__global__ __launch_bounds__(128) void rpe_softmax_kernel(
    const __nv_bfloat16* __restrict__ qkvh, const __nv_bfloat16* __restrict__ qkvl,
    const float* __restrict__ rpe, float* __restrict__ attn)
{
    const int a = blockIdx.x / 31;
    const int d = blockIdx.x % 31 - 15;
    const int h_lo = d < 0 ? -d : 0;
    const int h_hi = d > 0 ? 15 - d : 15;
    const int h0 = h_lo + 2 * (int)blockIdx.y;
    if (h0 > h_hi) return;
    const int h1 = (h0 + 1 <= h_hi) ? (h0 + 1) : h0;
    const int hh[2] = { h0, h1 };
    const int ii[2] = { 16 * a + h0 + d, 16 * a + h1 + d };
    const float* rbase = rpe + (size_t)(384 + 24 * d - a) * 1024;

    __shared__ __align__(16) unsigned long long Qp[2][256];
    __shared__ __align__(16) float L[2][Bc][Sc];
    __shared__ __align__(16) __nv_bfloat16 Qraw[2][2][Bc][HDc];
    const int tid = threadIdx.x;

    // prefetch attn rows for both items (async, overlaps FFMA phase)
    const uint32_t Lbase = smem_u32(&L[0][0][0]);
    #pragma unroll
    for (int it = 0; it < 2; it++) {
        #pragma unroll
        for (int r = 0; r < 6; r++) {
            const int idx = tid + r * 128;
            const int b = idx / 96;
            const int c = idx % 96;
            CP_ASYNC16(Lbase + (uint32_t)((it * Bc + b) * Sc + c * 4) * 4,
                       attn + ((size_t)(b * Hc + hh[it]) * Sc + ii[it]) * Sc + c * 4);
        }
    }
    CP_COMMIT();

    // coalesced q gather (one LDG.128 per thread per item)
    #pragma unroll
    for (int it = 0; it < 2; it++) {
        const int arr = tid >> 6;
        const int b   = (tid >> 3) & 7;
        const int c   = tid & 7;
        const __nv_bfloat16* src = arr ? qkvl : qkvh;
        const uint4 v = *(const uint4*)(src + (size_t)(b * Sc + ii[it]) * D3c
                                        + hh[it] * 192 + c * 8);
        *(uint4*)&Qraw[it][arr][b][c * 8] = v;
    }
    __syncthreads();
    // repack (x8 undoes qk pre-scale; exact pow2)
    #pragma unroll
    for (int it = 0; it < 2; it++) {
        for (int t = tid; t < 256; t += 128) {
            const int p = t & 3, dd = t >> 2;
            const float q0 = (__bfloat162float(Qraw[it][0][2 * p][dd]) +
                              __bfloat162float(Qraw[it][1][2 * p][dd])) * 8.f;
            const float q1 = (__bfloat162float(Qraw[it][0][2 * p + 1][dd]) +
                              __bfloat162float(Qraw[it][1][2 * p + 1][dd])) * 8.f;
            Qp[it][t] = packf2(q0, q1);
        }
    }
    __syncthreads();

    unsigned long long acc2[2][3][4];
    #pragma unroll
    for (int it = 0; it < 2; it++)
        #pragma unroll
        for (int jj = 0; jj < 3; jj++)
            #pragma unroll
            for (int p = 0; p < 4; p++) acc2[it][jj][p] = 0ull;

    #pragma unroll
    for (int c = 0; c < 16; c++) {
        // slab values: 3 LDG.128, packed once, shared by BOTH items
        unsigned long long s[3][4];
        #pragma unroll
        for (int jj = 0; jj < 3; jj++) {
            const int j = tid + jj * 128;
            const float4 rv = *(const float4*)(rbase + (size_t)j * 64 + c * 4);
            s[jj][0] = packf2(rv.x, rv.x);
            s[jj][1] = packf2(rv.y, rv.y);
            s[jj][2] = packf2(rv.z, rv.z);
            s[jj][3] = packf2(rv.w, rv.w);
        }
        #pragma unroll
        for (int it = 0; it < 2; it++) {
            // qp via LDS.128 (pairs p={0,1},{2,3} contiguous)
            ulonglong2 qp2[4][2];
            #pragma unroll
            for (int d2 = 0; d2 < 4; d2++) {
                qp2[d2][0] = *(const ulonglong2*)&Qp[it][(c * 4 + d2) * 4 + 0];
                qp2[d2][1] = *(const ulonglong2*)&Qp[it][(c * 4 + d2) * 4 + 2];
            }
            #pragma unroll
            for (int jj = 0; jj < 3; jj++) {
                #pragma unroll
                for (int d2 = 0; d2 < 4; d2++) {
                    FFMA2(acc2[it][jj][0], qp2[d2][0].x, s[jj][d2]);
                    FFMA2(acc2[it][jj][1], qp2[d2][0].y, s[jj][d2]);
                    FFMA2(acc2[it][jj][2], qp2[d2][1].x, s[jj][d2]);
                    FFMA2(acc2[it][jj][3], qp2[d2][1].y, s[jj][d2]);
                }
            }
        }
    }
    // attn rows resident before in-smem add
    CP_WAIT0();
    __syncthreads();
    #pragma unroll
    for (int it = 0; it < 2; it++) {
        #pragma unroll
        for (int jj = 0; jj < 3; jj++) {
            const int j = tid + jj * 128;
            #pragma unroll
            for (int p = 0; p < 4; p++) {
                float lo, hi;
                unpackf2(acc2[it][jj][p], lo, hi);
                L[it][2 * p][j] += lo;
                L[it][2 * p + 1][j] += hi;
            }
        }
    }
    __syncthreads();

    // softmax: 16 (it,b) rows over 4 warps -> 4 rows per warp
    const int wrp = tid >> 5, lane = tid & 31;
    #pragma unroll
    for (int rr = 0; rr < 4; rr++) {
        const int row = wrp * 4 + rr;
        const int it = row >> 3, b = row & 7;
        float v[12];
        float m = -1e30f;
        #pragma unroll
        for (int r = 0; r < 12; r++) { v[r] = L[it][b][lane + 32 * r]; m = fmaxf(m, v[r]); }
        #pragma unroll
        for (int o = 16; o > 0; o >>= 1) m = fmaxf(m, __shfl_xor_sync(0xffffffffu, m, o));
        float s = 0.f;
        #pragma unroll
        for (int r = 0; r < 12; r++) { v[r] = __expf(v[r] - m); s += v[r]; }
        #pragma unroll
        for (int o = 16; o > 0; o >>= 1) s += __shfl_xor_sync(0xffffffffu, s, o);
        const float inv = 1.0f / s;
        float* orow = attn + ((size_t)(b * Hc + hh[it]) * Sc + ii[it]) * Sc;
        #pragma unroll
        for (int r = 0; r < 12; r++) orow[lane + 32 * r] = v[r] * inv;
    }
}

// ---------------------------------------------------------------------------
// av HMMA: values = attn(fp32) @ v, 3-pass bf16 split.
// ---------------------------------------------------------------------------
#define AV_AROW 72
#define AV_ATILE (128 * AV_AROW * 4)
#define AV_VTILE 8192
#define AV_STAGE (AV_ATILE + 2 * AV_VTILE)
#define AV_SMEM  (2 * AV_STAGE)

__global__ __launch_bounds__(256, 2) void av_mma_kernel(
    const float* __restrict__ attn,
    const __nv_bfloat16* __restrict__ qkvh, const __nv_bfloat16* __restrict__ qkvl,
    __nv_bfloat16* __restrict__ vh_out, __nv_bfloat16* __restrict__ vl_out)
{
    extern __shared__ char smem[];
    const uint32_t sb = smem_u32(smem);
    float* sA_f = (float*)smem;
    const int tid = threadIdx.x, wid = tid >> 5, lane = tid & 31;
    const int bh = blockIdx.y, b = bh >> 4, h = bh & 15;
    const int i0 = blockIdx.x * 128;

    const float* abase = attn + ((size_t)bh * Sc + i0) * Sc;
    const __nv_bfloat16* vbase_h = qkvh + h * 192 + 128;
    const __nv_bfloat16* vbase_l = qkvl + h * 192 + 128;

    auto issue = [&](int ck) {
        if (ck >= 6) { CP_COMMIT(); return; }
        const uint32_t st = sb + (ck & 1) * AV_STAGE;
        const int j0 = ck * 64;
        for (int idx = tid; idx < 2048; idx += 256) {
            const int row = idx >> 4, c = idx & 15;
            CP_ASYNC16(st + row * (AV_AROW * 4) + c * 16,
                       abase + (size_t)row * Sc + j0 + c * 4);
        }
        for (int idx = tid; idx < 512; idx += 256) {
            const int row = idx >> 3, c = idx & 7;
            const uint32_t sw = row * 128 + ((c ^ (row & 7)) << 4);
            const size_t go = (size_t)(b * Sc + j0 + row) * D3c + c * 8;
            CP_ASYNC16(st + AV_ATILE + sw, vbase_h + go);
            CP_ASYNC16(st + AV_ATILE + AV_VTILE + sw, vbase_l + go);
        }
        CP_COMMIT();
    };

    const int wm = (wid & 3) * 32;
    const int wn = (wid >> 2) * 32;
    const int er = lane >> 2;
    const int ecb = (lane & 3) * 2;
    const int krow = (lane & 7) | ((lane & 16) >> 1);
    const int colc = (lane >> 3) & 1;

    float acc[2][4][4];
    #pragma unroll
    for (int i = 0; i < 2; i++)
        #pragma unroll
        for (int j = 0; j < 4; j++)
            #pragma unroll
            for (int r = 0; r < 4; r++) acc[i][j][r] = 0.f;

    issue(0);
    for (int ck = 0; ck < 6; ck++) {
        issue(ck + 1);
        CP_WAIT1();
        __syncthreads();
        const int stg = (ck & 1);
        float* sA = sA_f + stg * (AV_STAGE / 4);
        const uint32_t vt_h = sb + stg * AV_STAGE + AV_ATILE;
        const uint32_t vt_l = vt_h + AV_VTILE;
        #pragma unroll
        for (int ks = 0; ks < 4; ks++) {
            uint32_t ahf[2][4], alf[2][4];
            #pragma unroll
            for (int mt = 0; mt < 2; mt++) {
                const int r_ = wm + mt * 16 + er;
                const int cb = ks * 16 + ecb;
                float2 x0 = *(float2*)(sA + (size_t)r_ * AV_AROW + cb);
                float2 x1 = *(float2*)(sA + (size_t)(r_ + 8) * AV_AROW + cb);
                float2 x2 = *(float2*)(sA + (size_t)r_ * AV_AROW + cb + 8);
                float2 x3 = *(float2*)(sA + (size_t)(r_ + 8) * AV_AROW + cb + 8);
                pack_hilo(x0.x, x0.y, ahf[mt][0], alf[mt][0]);
                pack_hilo(x1.x, x1.y, ahf[mt][1], alf[mt][1]);
                pack_hilo(x2.x, x2.y, ahf[mt][2], alf[mt][2]);
                pack_hilo(x3.x, x3.y, ahf[mt][3], alf[mt][3]);
            }
            uint32_t badr[2];
            #pragma unroll
            for (int bt = 0; bt < 2; bt++) {
                const int row = ks * 16 + krow;
                const int c = (wn >> 3) + bt * 2 + colc;
                badr[bt] = row * 128 + ((c ^ (row & 7)) << 4);
            }
            uint32_t bhf[2][4], blf[2][4];
            #pragma unroll
            for (int bt = 0; bt < 2; bt++) LDSM_X4_T(bhf[bt], vt_h + badr[bt]);
            #pragma unroll
            for (int bt = 0; bt < 2; bt++) LDSM_X4_T(blf[bt], vt_l + badr[bt]);
            #pragma unroll
            for (int mt = 0; mt < 2; mt++)
                #pragma unroll
                for (int nt = 0; nt < 4; nt++)
                    mma_bf16(acc[mt][nt], ahf[mt],
                             bhf[nt >> 1][nt & 1], bhf[nt >> 1][(nt & 1) + 2]);
            #pragma unroll
            for (int mt = 0; mt < 2; mt++)
                #pragma unroll
                for (int nt = 0; nt < 4; nt++)
                    mma_bf16(acc[mt][nt], alf[mt],
                             bhf[nt >> 1][nt & 1], bhf[nt >> 1][(nt & 1) + 2]);
            #pragma unroll
            for (int mt = 0; mt < 2; mt++)
                #pragma unroll
                for (int nt = 0; nt < 4; nt++)
                    mma_bf16(acc[mt][nt], ahf[mt],
                             blf[nt >> 1][nt & 1], blf[nt >> 1][(nt & 1) + 2]);
        }
        __syncthreads();
    }

    const int ec = (lane & 3) * 2;
    #pragma unroll
    for (int mt = 0; mt < 2; mt++) {
        #pragma unroll
        for (int nt = 0; nt < 4; nt++) {
            const int row = i0 + wm + mt * 16 + er;
            const int col = h * 64 + wn + nt * 8 + ec;
            const size_t o0 = (size_t)(b * Sc + row) * Dc + col;
            const size_t o1 = (size_t)(b * Sc + row + 8) * Dc + col;
            split2(acc[mt][nt][0], acc[mt][nt][1], vh_out + o0, vl_out + o0);
            split2(acc[mt][nt][2], acc[mt][nt][3], vh_out + o1, vl_out + o1);
        }
    }
}

// ---------------------------------------------------------------------------
extern "C" void kernel_launch(void* const* d_in, const int* in_sizes, int n_in,
                              void* d_out, int out_size)
{
    const float* x     = (const float*)d_in[0];
    const float* qkv_w = (const float*)d_in[1];
    const float* qkv_b = (const float*)d_in[2];
    const float* out_w = (const float*)d_in[3];
    const float* out_b = (const float*)d_in[4];
    const float* rpe   = (const float*)d_in[5];

    float* attnscr;
    __nv_bfloat16 *ah, *al, *wqh, *wql, *woh, *wol, *qkvh, *qkvl;
    cudaGetSymbolAddress((void**)&attnscr, g_attn);
    cudaGetSymbolAddress((void**)&ah, g_ah);
    cudaGetSymbolAddress((void**)&al, g_al);
    cudaGetSymbolAddress((void**)&wqh, g_wqh);
    cudaGetSymbolAddress((void**)&wql, g_wql);
    cudaGetSymbolAddress((void**)&woh, g_woh);
    cudaGetSymbolAddress((void**)&wol, g_wol);
    cudaGetSymbolAddress((void**)&qkvh, g_qkvh);
    cudaGetSymbolAddress((void**)&qkvl, g_qkvl);

    float* out = (float*)d_out;
    const long OUT_E = (long)BSc * Dc;
    const long ATT_E = (long)Bc * Hc * Sc * Sc;
    float* attn = ((long)out_size >= OUT_E + ATT_E) ? (out + OUT_E) : attnscr;

    cudaFuncSetAttribute(mma_gemm_kernel,
                         cudaFuncAttributeMaxDynamicSharedMemorySize, GSMEM);
    cudaFuncSetAttribute(qk_mma_kernel,
                         cudaFuncAttributeMaxDynamicSharedMemorySize, QK_SMEM);
    cudaFuncSetAttribute(av_mma_kernel,
                         cudaFuncAttributeMaxDynamicSharedMemorySize, AV_SMEM);

    // 0) fused prep
    prep_kernel<<<7168, 256>>>(x, ah, al, qkv_w, wqh, wql, out_w, woh, wol);
    // 1) qkv: emit bf16 hi/lo (q cols pre-scaled 1/8)
    mma_gemm_kernel<<<dim3(D3c / 128, BSc / 128), 256, GSMEM>>>(
        ah, al, wqh, wql, qkv_b, nullptr, qkvh, qkvl, 1, BSc, D3c, Dc);
    // 2) logits = (q/8) . k
    qk_mma_kernel<<<dim3(3, 3, Bc * Hc), 256, QK_SMEM>>>(qkvh, qkvl, attn);
    // 3+4) rpe bias + softmax (2 same-slab items per block, parallel)
    rpe_softmax_kernel<<<dim3(24 * 31, 8), 128>>>(qkvh, qkvl, rpe, attn);
    // 5) values = attn @ v -> bf16 hi/lo
    av_mma_kernel<<<dim3(3, Bc * Hc), 256, AV_SMEM>>>(attn, qkvh, qkvl, ah, al);
    // 6) out = values @ out_w + out_b
    mma_gemm_kernel<<<dim3(Dc / 128, BSc / 128), 256, GSMEM>>>(
        ah, al, woh, wol, out_b, out, nullptr, nullptr, 0, BSc, Dc, Dc);
}

// round 13
// speedup vs baseline: 1.4459x; 1.1082x over previous
#include <cuda_runtime.h>
#include <cuda_bf16.h>
#include <cstdint>

#define Bc 8
#define Sc 384
#define Dc 1024
#define Hc 16
#define HDc 64
#define D3c 3072
#define BSc 3072   // B*S
#define RPE_ROWS 1023

// ---------------------------------------------------------------------------
// Scratch (static device globals; no runtime allocation)
// ---------------------------------------------------------------------------
__device__ float g_attn[(size_t)Bc * Hc * Sc * Sc];   // fallback attn buffer
__device__ __align__(16) __nv_bfloat16 g_ah[(size_t)BSc * Dc];    // A hi (x, then vals)
__device__ __align__(16) __nv_bfloat16 g_al[(size_t)BSc * Dc];    // A lo
__device__ __align__(16) __nv_bfloat16 g_wqh[(size_t)D3c * Dc];   // qkv_w^T hi [N,K]
__device__ __align__(16) __nv_bfloat16 g_wql[(size_t)D3c * Dc];   // qkv_w^T lo
__device__ __align__(16) __nv_bfloat16 g_woh[(size_t)Dc * Dc];    // out_w^T hi
__device__ __align__(16) __nv_bfloat16 g_wol[(size_t)Dc * Dc];    // out_w^T lo
__device__ __align__(16) __nv_bfloat16 g_qkvh[(size_t)BSc * D3c]; // qkv hi (q pre-scaled /8)
__device__ __align__(16) __nv_bfloat16 g_qkvl[(size_t)BSc * D3c]; // qkv lo
__device__ __align__(16) __nv_bfloat16 g_rpeh[(size_t)RPE_ROWS * Dc]; // rpe hi
__device__ __align__(16) __nv_bfloat16 g_rpel[(size_t)RPE_ROWS * Dc]; // rpe lo

// ---------------------------------------------------------------------------
// Baseline-PTX helpers
// ---------------------------------------------------------------------------
__device__ __forceinline__ uint32_t smem_u32(const void* p) {
    uint32_t a;
    asm("{ .reg .u64 t; cvta.to.shared.u64 t, %1; cvt.u32.u64 %0, t; }" : "=r"(a) : "l"(p));
    return a;
}
#define CP_ASYNC16(sm, gp) \
    asm volatile("cp.async.cg.shared.global [%0], [%1], 16;" :: "r"(sm), "l"(gp))
#define CP_COMMIT() asm volatile("cp.async.commit_group;" ::: "memory")
#define CP_WAIT0()  asm volatile("cp.async.wait_group 0;" ::: "memory")
#define CP_WAIT1()  asm volatile("cp.async.wait_group 1;" ::: "memory")

#define LDSM_X4(r, a) \
    asm volatile("ldmatrix.sync.aligned.m8n8.x4.shared.b16 {%0,%1,%2,%3}, [%4];" \
        : "=r"((r)[0]), "=r"((r)[1]), "=r"((r)[2]), "=r"((r)[3]) : "r"(a))
#define LDSM_X4_T(r, a) \
    asm volatile("ldmatrix.sync.aligned.m8n8.x4.trans.shared.b16 {%0,%1,%2,%3}, [%4];" \
        : "=r"((r)[0]), "=r"((r)[1]), "=r"((r)[2]), "=r"((r)[3]) : "r"(a))

__device__ __forceinline__ void mma_bf16(float* d, const uint32_t* a,
                                         uint32_t b0, uint32_t b1) {
    asm volatile(
        "mma.sync.aligned.m16n8k16.row.col.f32.bf16.bf16.f32 "
        "{%0,%1,%2,%3}, {%4,%5,%6,%7}, {%8,%9}, {%0,%1,%2,%3};"
        : "+f"(d[0]), "+f"(d[1]), "+f"(d[2]), "+f"(d[3])
        : "r"(a[0]), "r"(a[1]), "r"(a[2]), "r"(a[3]), "r"(b0), "r"(b1));
}

__device__ __forceinline__ void split2(float x, float y,
                                       __nv_bfloat16* ph, __nv_bfloat16* pl) {
    __nv_bfloat16 hx = __float2bfloat16(x), hy = __float2bfloat16(y);
    *(__nv_bfloat162*)ph = __nv_bfloat162(hx, hy);
    *(__nv_bfloat162*)pl = __nv_bfloat162(
        __float2bfloat16(x - __bfloat162float(hx)),
        __float2bfloat16(y - __bfloat162float(hy)));
}
__device__ __forceinline__ void pack_hilo(float x, float y,
                                          uint32_t& hi, uint32_t& lo) {
    __nv_bfloat16 hx = __float2bfloat16(x), hy = __float2bfloat16(y);
    __nv_bfloat162 h2(hx, hy);
    __nv_bfloat162 l2(__float2bfloat16(x - __bfloat162float(hx)),
                      __float2bfloat16(y - __bfloat162float(hy)));
    hi = *(uint32_t*)&h2;
    lo = *(uint32_t*)&l2;
}

// ---------------------------------------------------------------------------
// HMMA bf16-split GEMM: C = (Ah+Al)@(Bh+Bl)^T + bias
// Single-sync mainloop: wait group -> barrier -> issue(it+2) -> compute(it).
// ---------------------------------------------------------------------------
#define TILE_B 8192
#define BUF_B  (4 * TILE_B)
#define NSTAGE 3
#define GSMEM  (NSTAGE * BUF_B)   // 96 KB

__global__ __launch_bounds__(256, 2) void mma_gemm_kernel(
    const __nv_bfloat16* __restrict__ Ah, const __nv_bfloat16* __restrict__ Al,
    const __nv_bfloat16* __restrict__ Bh, const __nv_bfloat16* __restrict__ Bl,
    const float* __restrict__ bias, float* __restrict__ C,
    __nv_bfloat16* __restrict__ Ch, __nv_bfloat16* __restrict__ Cl,
    int qkv_mode, int M, int N, int K)
{
    extern __shared__ char smem[];
    const uint32_t sbase = smem_u32(smem);
    const int tid  = threadIdx.x;
    const int wid  = tid >> 5;
    const int lane = tid & 31;
    const int m0 = blockIdx.y * 128;
    const int n0 = blockIdx.x * 128;
    const int mw = (wid & 1) * 64;
    const int nw = (wid >> 1) * 32;

    const int lrow = tid >> 1;
    const int c0   = (tid & 1) * 2;
    const int sw0  = (lrow >> 1) & 3;
    const __nv_bfloat16* gAh = Ah + (size_t)(m0 + lrow) * K;
    const __nv_bfloat16* gAl = Al + (size_t)(m0 + lrow) * K;
    const __nv_bfloat16* gBh = Bh + (size_t)(n0 + lrow) * K;
    const __nv_bfloat16* gBl = Bl + (size_t)(n0 + lrow) * K;
    const uint32_t soff0 = lrow * 64 + (((c0 + 0) ^ sw0) << 4);
    const uint32_t soff1 = lrow * 64 + (((c0 + 1) ^ sw0) << 4);

    const int NK = K >> 5;

    auto issue = [&](int it) {
        if (it < NK) {
            const uint32_t tb = sbase + (it % NSTAGE) * BUF_B;
            const int k0 = it << 5;
            CP_ASYNC16(tb + 0 * TILE_B + soff0, gAh + k0 + (c0 + 0) * 8);
            CP_ASYNC16(tb + 0 * TILE_B + soff1, gAh + k0 + (c0 + 1) * 8);
            CP_ASYNC16(tb + 1 * TILE_B + soff0, gAl + k0 + (c0 + 0) * 8);
            CP_ASYNC16(tb + 1 * TILE_B + soff1, gAl + k0 + (c0 + 1) * 8);
            CP_ASYNC16(tb + 2 * TILE_B + soff0, gBh + k0 + (c0 + 0) * 8);
            CP_ASYNC16(tb + 2 * TILE_B + soff1, gBh + k0 + (c0 + 1) * 8);
            CP_ASYNC16(tb + 3 * TILE_B + soff0, gBl + k0 + (c0 + 0) * 8);
            CP_ASYNC16(tb + 3 * TILE_B + soff1, gBl + k0 + (c0 + 1) * 8);
        }
        CP_COMMIT();
    };

    const int frow = lane & 15;
    const int fc   = lane >> 4;
    auto fr_addr = [&](int rbase) -> uint32_t {
        const int row = rbase + frow;
        return (uint32_t)(row * 64 + ((fc ^ ((row >> 1) & 3)) << 4));
    };
    const uint32_t aoff = fr_addr(mw);
    const uint32_t boff = fr_addr(nw);

    float acc[4][4][4];
    #pragma unroll
    for (int i = 0; i < 4; i++)
        #pragma unroll
        for (int j = 0; j < 4; j++)
            #pragma unroll
            for (int r = 0; r < 4; r++) acc[i][j][r] = 0.f;

    issue(0); issue(1);

    for (int it = 0; it < NK; it++) {
        CP_WAIT1();
        __syncthreads();
        issue(it + 2);
        const uint32_t tb = sbase + (it % NSTAGE) * BUF_B;
        #pragma unroll
        for (int ks = 0; ks < 2; ks++) {
            const uint32_t kx = ks ? 32u : 0u;
            uint32_t ahf[4][4], bhf[2][4];
            #pragma unroll
            for (int mt = 0; mt < 4; mt++)
                LDSM_X4(ahf[mt], tb + ((aoff + mt * 1024) ^ kx));
            #pragma unroll
            for (int bt = 0; bt < 2; bt++)
                LDSM_X4(bhf[bt], tb + 2 * TILE_B + ((boff + bt * 1024) ^ kx));
            #pragma unroll
            for (int mt = 0; mt < 4; mt++)
                #pragma unroll
                for (int nt = 0; nt < 4; nt++)
                    mma_bf16(acc[mt][nt], ahf[mt],
                             bhf[nt >> 1][nt & 1], bhf[nt >> 1][(nt & 1) + 2]);
            uint32_t blf[2][4];
            #pragma unroll
            for (int bt = 0; bt < 2; bt++)
                LDSM_X4(blf[bt], tb + 3 * TILE_B + ((boff + bt * 1024) ^ kx));
            #pragma unroll
            for (int mt = 0; mt < 4; mt++)
                #pragma unroll
                for (int nt = 0; nt < 4; nt++)
                    mma_bf16(acc[mt][nt], ahf[mt],
                             blf[nt >> 1][nt & 1], blf[nt >> 1][(nt & 1) + 2]);
            uint32_t alf[4][4];
            #pragma unroll
            for (int mt = 0; mt < 4; mt++)
                LDSM_X4(alf[mt], tb + TILE_B + ((aoff + mt * 1024) ^ kx));
            #pragma unroll
            for (int mt = 0; mt < 4; mt++)
                #pragma unroll
                for (int nt = 0; nt < 4; nt++)
                    mma_bf16(acc[mt][nt], alf[mt],
                             bhf[nt >> 1][nt & 1], bhf[nt >> 1][(nt & 1) + 2]);
        }
    }

    const int er = lane >> 2;
    const int ec = (lane & 3) * 2;
    #pragma unroll
    for (int mt = 0; mt < 4; mt++) {
        #pragma unroll
        for (int nt = 0; nt < 4; nt++) {
            const int col = n0 + nw + nt * 8 + ec;
            const float bx = __ldg(&bias[col]);
            const float by = __ldg(&bias[col + 1]);
            const int r0 = m0 + mw + mt * 16 + er;
            float2 v0 = make_float2(acc[mt][nt][0] + bx, acc[mt][nt][1] + by);
            float2 v1 = make_float2(acc[mt][nt][2] + bx, acc[mt][nt][3] + by);
            if (C) {
                *(float2*)(C + (size_t)r0 * N + col) = v0;
                *(float2*)(C + (size_t)(r0 + 8) * N + col) = v1;
            }
            if (Ch) {
                const float s = (qkv_mode && (((col >> 6) % 3) == 0)) ? 0.125f : 1.0f;
                split2(v0.x * s, v0.y * s, Ch + (size_t)r0 * N + col,
                       Cl + (size_t)r0 * N + col);
                split2(v1.x * s, v1.y * s, Ch + (size_t)(r0 + 8) * N + col,
                       Cl + (size_t)(r0 + 8) * N + col);
            }
        }
    }
}

// ---------------------------------------------------------------------------
// Fused prep: split x + transpose-split qkv_w + out_w + split rpe table.
//   blocks [0, 3072)        : split x
//   blocks [3072, 6144)     : qkv_w transpose tiles
//   blocks [6144, 7168)     : out_w transpose tiles
//   blocks [7168, 8191)     : split rpe table (1023 rows x 1024)
// ---------------------------------------------------------------------------
__global__ __launch_bounds__(256) void prep_kernel(
    const float* __restrict__ x,
    __nv_bfloat16* __restrict__ ah, __nv_bfloat16* __restrict__ al,
    const float* __restrict__ qkv_w,
    __nv_bfloat16* __restrict__ wqh, __nv_bfloat16* __restrict__ wql,
    const float* __restrict__ out_w,
    __nv_bfloat16* __restrict__ woh, __nv_bfloat16* __restrict__ wol,
    const float* __restrict__ rpe,
    __nv_bfloat16* __restrict__ rpeh, __nv_bfloat16* __restrict__ rpel)
{
    __shared__ float t[32][33];
    const int bid = blockIdx.x;
    const int tid = threadIdx.x;
    if (bid < 3072) {
        const int i = bid * 256 + tid;
        float4 v = ((const float4*)x)[i];
        split2(v.x, v.y, ah + 4 * (size_t)i, al + 4 * (size_t)i);
        split2(v.z, v.w, ah + 4 * (size_t)i + 2, al + 4 * (size_t)i + 2);
        return;
    }
    if (bid >= 7168) {
        const int i = (bid - 7168) * 256 + tid;   // 1023*256 = exactly rows*1024/4
        float4 v = ((const float4*)rpe)[i];
        split2(v.x, v.y, rpeh + 4 * (size_t)i, rpel + 4 * (size_t)i);
        split2(v.z, v.w, rpeh + 4 * (size_t)i + 2, rpel + 4 * (size_t)i + 2);
        return;
    }
    const float* W;
    __nv_bfloat16 *Th, *Tl;
    int N, bx, by;
    if (bid < 6144) {
        const int r = bid - 3072;
        W = qkv_w; Th = wqh; Tl = wql; N = D3c;
        bx = r % 96; by = r / 96;
    } else {
        const int r = bid - 6144;
        W = out_w; Th = woh; Tl = wol; N = Dc;
        bx = r % 32; by = r / 32;
    }
    const int K = Dc;
    const int n0 = bx * 32, k0 = by * 32;
    const int tx = tid & 31, ty = tid >> 5;
    #pragma unroll
    for (int r = 0; r < 4; r++)
        t[ty + 8 * r][tx] = W[(size_t)(k0 + ty + 8 * r) * N + n0 + tx];
    __syncthreads();
    #pragma unroll
    for (int r = 0; r < 4; r++) {
        float v = t[tx][ty + 8 * r];
        __nv_bfloat16 h = __float2bfloat16(v);
        __nv_bfloat16 l = __float2bfloat16(v - __bfloat162float(h));
        size_t o = (size_t)(n0 + ty + 8 * r) * K + k0 + tx;
        Th[o] = h; Tl[o] = l;
    }
}

// ---------------------------------------------------------------------------
// qk HMMA: logits = (scaled q).k, 3-pass bf16 split, interleaved LDSM.
// ---------------------------------------------------------------------------
#define QK_SMEM (4 * 16384)

__global__ __launch_bounds__(256, 2) void qk_mma_kernel(
    const __nv_bfloat16* __restrict__ qkvh, const __nv_bfloat16* __restrict__ qkvl,
    float* __restrict__ attn)
{
    extern __shared__ char smem[];
    const uint32_t sb = smem_u32(smem);
    const int tid = threadIdx.x, wid = tid >> 5, lane = tid & 31;
    const int bh = blockIdx.z, b = bh >> 4, h = bh & 15;
    const int i0 = blockIdx.y * 128, j0 = blockIdx.x * 128;

    #pragma unroll
    for (int t = 0; t < 4; t++) {
        const __nv_bfloat16* base = (t & 1) ? qkvl : qkvh;
        const int roff = (t < 2) ? i0 : j0;
        const int coff = h * 192 + ((t < 2) ? 0 : 64);
        for (int idx = tid; idx < 1024; idx += 256) {
            const int row = idx >> 3, c = idx & 7;
            const uint32_t dst = sb + t * 16384 + row * 128 + ((c ^ (row & 7)) << 4);
            CP_ASYNC16(dst, base + (size_t)(b * Sc + roff + row) * D3c + coff + c * 8);
        }
    }
    CP_COMMIT(); CP_WAIT0();
    __syncthreads();

    const int mw = (wid & 1) * 64;
    const int nw = (wid >> 1) * 32;
    const int frow = lane & 15, fc = lane >> 4;

    float acc[4][4][4];
    #pragma unroll
    for (int i = 0; i < 4; i++)
        #pragma unroll
        for (int j = 0; j < 4; j++)
            #pragma unroll
            for (int r = 0; r < 4; r++) acc[i][j][r] = 0.f;

    #pragma unroll
    for (int ks = 0; ks < 4; ks++) {
        uint32_t aadr[4], badr[2];
        #pragma unroll
        for (int mt = 0; mt < 4; mt++) {
            const int row = mw + mt * 16 + frow;
            aadr[mt] = row * 128 + (((2 * ks + fc) ^ (row & 7)) << 4);
        }
        #pragma unroll
        for (int bt = 0; bt < 2; bt++) {
            const int row = nw + bt * 16 + frow;
            badr[bt] = row * 128 + (((2 * ks + fc) ^ (row & 7)) << 4);
        }
        uint32_t ahf[4][4], bhf[2][4];
        #pragma unroll
        for (int mt = 0; mt < 4; mt++) LDSM_X4(ahf[mt], sb + aadr[mt]);
        #pragma unroll
        for (int bt = 0; bt < 2; bt++) LDSM_X4(bhf[bt], sb + 2 * 16384 + badr[bt]);
        #pragma unroll
        for (int mt = 0; mt < 4; mt++)
            #pragma unroll
            for (int nt = 0; nt < 4; nt++)
                mma_bf16(acc[mt][nt], ahf[mt],
                         bhf[nt >> 1][nt & 1], bhf[nt >> 1][(nt & 1) + 2]);
        uint32_t blf[2][4];
        #pragma unroll
        for (int bt = 0; bt < 2; bt++) LDSM_X4(blf[bt], sb + 3 * 16384 + badr[bt]);
        #pragma unroll
        for (int mt = 0; mt < 4; mt++)
            #pragma unroll
            for (int nt = 0; nt < 4; nt++)
                mma_bf16(acc[mt][nt], ahf[mt],
                         blf[nt >> 1][nt & 1], blf[nt >> 1][(nt & 1) + 2]);
        uint32_t alf[4][4];
        #pragma unroll
        for (int mt = 0; mt < 4; mt++) LDSM_X4(alf[mt], sb + 16384 + aadr[mt]);
        #pragma unroll
        for (int mt = 0; mt < 4; mt++)
            #pragma unroll
            for (int nt = 0; nt < 4; nt++)
                mma_bf16(acc[mt][nt], alf[mt],
                         bhf[nt >> 1][nt & 1], bhf[nt >> 1][(nt & 1) + 2]);
    }

    const int er = lane >> 2, ec = (lane & 3) * 2;
    float* ob = attn + (size_t)bh * Sc * Sc;
    #pragma unroll
    for (int mt = 0; mt < 4; mt++) {
        #pragma unroll
        for (int nt = 0; nt < 4; nt++) {
            const int r0 = i0 + mw + mt * 16 + er;
            const int col = j0 + nw + nt * 8 + ec;
            *(float2*)(ob + (size_t)r0 * Sc + col) =
                make_float2(acc[mt][nt][0], acc[mt][nt][1]);
            *(float2*)(ob + (size_t)(r0 + 8) * Sc + col) =
                make_float2(acc[mt][nt][2], acc[mt][nt][3]);
        }
    }
}

// ---------------------------------------------------------------------------
// rpe bias via HMMA + fused softmax.
// bias[(it,b), j] = q[(it,b),:] . slab[j,:]  -- an M=16, N=384, K=64 GEMM.
// 2 diagonal-adjacent items (same slab) per block; slab (bf16 hi/lo) streamed
// in 3 chunks of 128 j rows, double-buffered cp.async; q staged as 16x128B
// hi/lo tiles; 3-pass HMMA (qh*sh + ql*sh + qh*sl), acc x8 (undoes q/8 exact).
// attn rows prefetched into smem L; bias added from D frags; softmax in-place.
// SMEM: q 4KB | slab 2x32KB | L 24KB = 94208 B -> 2 CTA/SM.
// ---------------------------------------------------------------------------
#define RPE_SMEM (4096 + 2 * 32768 + 16 * Sc * 4)   // 94208

__global__ __launch_bounds__(256, 2) void rpe_mma_softmax_kernel(
    const __nv_bfloat16* __restrict__ qkvh, const __nv_bfloat16* __restrict__ qkvl,
    const __nv_bfloat16* __restrict__ rpeh, const __nv_bfloat16* __restrict__ rpel,
    float* __restrict__ attn)
{
    extern __shared__ char smem[];
    const uint32_t sb = smem_u32(smem);
    float* L = (float*)(smem + 69632);            // [16][384]
    const uint32_t Lbase = sb + 69632;
    const int tid = threadIdx.x, wid = tid >> 5, lane = tid & 31;

    const int a = blockIdx.x / 31;
    const int d = blockIdx.x % 31 - 15;
    const int h_lo = d < 0 ? -d : 0;
    const int h_hi = d > 0 ? 15 - d : 15;
    const int h0 = h_lo + 2 * (int)blockIdx.y;
    if (h0 > h_hi) return;
    const int h1 = (h0 + 1 <= h_hi) ? (h0 + 1) : h0;
    const int hh[2] = { h0, h1 };
    const int ii[2] = { 16 * a + h0 + d, 16 * a + h1 + d };
    const size_t r0off = (size_t)(384 + 24 * d - a) * 1024;

    // ---- group A: q tiles + attn prefetch + slab chunk 0
    {
        const int arr = tid >> 7;          // 0=hi,1=lo
        const int r = (tid >> 3) & 15;     // q tile row = it*8+b
        const int c = tid & 7;
        const int it = r >> 3, b = r & 7;
        const __nv_bfloat16* src = arr ? qkvl : qkvh;
        CP_ASYNC16(sb + arr * 2048 + r * 128 + ((c ^ (r & 7)) << 4),
                   src + (size_t)(b * Sc + ii[it]) * D3c + hh[it] * 192 + c * 8);
        #pragma unroll
        for (int rr = 0; rr < 6; rr++) {
            const int idx = tid + rr * 256;
            const int row = idx / 96, cc = idx % 96;
            const int it2 = row >> 3, b2 = row & 7;
            CP_ASYNC16(Lbase + (uint32_t)(row * Sc + cc * 4) * 4,
                       attn + ((size_t)(b2 * Hc + hh[it2]) * Sc + ii[it2]) * Sc + cc * 4);
        }
        for (int idx = tid; idx < 1024; idx += 256) {
            const int row = idx >> 3, c2 = idx & 7;
            const uint32_t sw = row * 128 + ((c2 ^ (row & 7)) << 4);
            CP_ASYNC16(sb + 4096 + sw, rpeh + r0off + (size_t)row * 64 + c2 * 8);
            CP_ASYNC16(sb + 4096 + 16384 + sw, rpel + r0off + (size_t)row * 64 + c2 * 8);
        }
        CP_COMMIT();
        // group B: slab chunk 1
        for (int idx = tid; idx < 1024; idx += 256) {
            const int row = idx >> 3, c2 = idx & 7;
            const uint32_t sw = row * 128 + ((c2 ^ (row & 7)) << 4);
            CP_ASYNC16(sb + 4096 + 32768 + sw, rpeh + r0off + (size_t)(128 + row) * 64 + c2 * 8);
            CP_ASYNC16(sb + 4096 + 32768 + 16384 + sw, rpel + r0off + (size_t)(128 + row) * 64 + c2 * 8);
        }
        CP_COMMIT();
    }

    const int frow = lane & 15, fc = lane >> 4;
    const int wn = wid * 16;                // warp's 16 j-rows within chunk
    const int er = lane >> 2, ec = (lane & 3) * 2;

    for (int ck = 0; ck < 3; ck++) {
        CP_WAIT1();
        __syncthreads();
        const uint32_t st = sb + 4096 + (ck & 1) * 32768;
        float acc[2][4];
        #pragma unroll
        for (int nt = 0; nt < 2; nt++)
            #pragma unroll
            for (int r = 0; r < 4; r++) acc[nt][r] = 0.f;

        #pragma unroll
        for (int ks = 0; ks < 4; ks++) {
            const uint32_t aadr = frow * 128 + (((2 * ks + fc) ^ (frow & 7)) << 4);
            const int brow = wn + frow;
            const uint32_t badr = brow * 128 + (((2 * ks + fc) ^ (brow & 7)) << 4);
            uint32_t ah4[4], al4[4], bh4[4], bl4[4];
            LDSM_X4(ah4, sb + aadr);
            LDSM_X4(bh4, st + badr);
            #pragma unroll
            for (int nt = 0; nt < 2; nt++)
                mma_bf16(acc[nt], ah4, bh4[nt], bh4[nt + 2]);
            LDSM_X4(bl4, st + 16384 + badr);
            #pragma unroll
            for (int nt = 0; nt < 2; nt++)
                mma_bf16(acc[nt], ah4, bl4[nt], bl4[nt + 2]);
            LDSM_X4(al4, sb + 2048 + aadr);
            #pragma unroll
            for (int nt = 0; nt < 2; nt++)
                mma_bf16(acc[nt], al4, bh4[nt], bh4[nt + 2]);
        }
        __syncthreads();   // all reads of this stage done before refill
        if (ck + 2 < 3) {
            const int nc = ck + 2;
            const uint32_t st2 = sb + 4096 + (nc & 1) * 32768;
            for (int idx = tid; idx < 1024; idx += 256) {
                const int row = idx >> 3, c2 = idx & 7;
                const uint32_t sw = row * 128 + ((c2 ^ (row & 7)) << 4);
                CP_ASYNC16(st2 + sw, rpeh + r0off + (size_t)(nc * 128 + row) * 64 + c2 * 8);
                CP_ASYNC16(st2 + 16384 + sw, rpel + r0off + (size_t)(nc * 128 + row) * 64 + c2 * 8);
            }
        }
        CP_COMMIT();
        // add bias (x8 undoes q/8 pre-scale; exact pow2). attn resident: group A
        // drained at the first CP_WAIT1. Each (row,col) written by one thread.
        #pragma unroll
        for (int nt = 0; nt < 2; nt++) {
            const int col = ck * 128 + wn + nt * 8 + ec;
            L[er * Sc + col]           += 8.f * acc[nt][0];
            L[er * Sc + col + 1]       += 8.f * acc[nt][1];
            L[(er + 8) * Sc + col]     += 8.f * acc[nt][2];
            L[(er + 8) * Sc + col + 1] += 8.f * acc[nt][3];
        }
    }
    __syncthreads();

    // softmax: 16 (it,b) rows over 8 warps = 2 rows per warp
    #pragma unroll
    for (int rr = 0; rr < 2; rr++) {
        const int row = wid * 2 + rr;
        const int it = row >> 3, b = row & 7;
        float v[12];
        float m = -1e30f;
        #pragma unroll
        for (int r = 0; r < 12; r++) { v[r] = L[row * Sc + lane + 32 * r]; m = fmaxf(m, v[r]); }
        #pragma unroll
        for (int o = 16; o > 0; o >>= 1) m = fmaxf(m, __shfl_xor_sync(0xffffffffu, m, o));
        float s = 0.f;
        #pragma unroll
        for (int r = 0; r < 12; r++) { v[r] = __expf(v[r] - m); s += v[r]; }
        #pragma unroll
        for (int o = 16; o > 0; o >>= 1) s += __shfl_xor_sync(0xffffffffu, s, o);
        const float inv = 1.0f / s;
        float* orow = attn + ((size_t)(b * Hc + hh[it]) * Sc + ii[it]) * Sc;
        #pragma unroll
        for (int r = 0; r < 12; r++) orow[lane + 32 * r] = v[r] * inv;
    }
}

// ---------------------------------------------------------------------------
// av HMMA: values = attn(fp32) @ v, 3-pass bf16 split.
// ---------------------------------------------------------------------------
#define AV_AROW 72
#define AV_ATILE (128 * AV_AROW * 4)
#define AV_VTILE 8192
#define AV_STAGE (AV_ATILE + 2 * AV_VTILE)
#define AV_SMEM  (2 * AV_STAGE)

__global__ __launch_bounds__(256, 2) void av_mma_kernel(
    const float* __restrict__ attn,
    const __nv_bfloat16* __restrict__ qkvh, const __nv_bfloat16* __restrict__ qkvl,
    __nv_bfloat16* __restrict__ vh_out, __nv_bfloat16* __restrict__ vl_out)
{
    extern __shared__ char smem[];
    const uint32_t sb = smem_u32(smem);
    float* sA_f = (float*)smem;
    const int tid = threadIdx.x, wid = tid >> 5, lane = tid & 31;
    const int bh = blockIdx.y, b = bh >> 4, h = bh & 15;
    const int i0 = blockIdx.x * 128;

    const float* abase = attn + ((size_t)bh * Sc + i0) * Sc;
    const __nv_bfloat16* vbase_h = qkvh + h * 192 + 128;
    const __nv_bfloat16* vbase_l = qkvl + h * 192 + 128;

    auto issue = [&](int ck) {
        if (ck >= 6) { CP_COMMIT(); return; }
        const uint32_t st = sb + (ck & 1) * AV_STAGE;
        const int j0 = ck * 64;
        for (int idx = tid; idx < 2048; idx += 256) {
            const int row = idx >> 4, c = idx & 15;
            CP_ASYNC16(st + row * (AV_AROW * 4) + c * 16,
                       abase + (size_t)row * Sc + j0 + c * 4);
        }
        for (int idx = tid; idx < 512; idx += 256) {
            const int row = idx >> 3, c = idx & 7;
            const uint32_t sw = row * 128 + ((c ^ (row & 7)) << 4);
            const size_t go = (size_t)(b * Sc + j0 + row) * D3c + c * 8;
            CP_ASYNC16(st + AV_ATILE + sw, vbase_h + go);
            CP_ASYNC16(st + AV_ATILE + AV_VTILE + sw, vbase_l + go);
        }
        CP_COMMIT();
    };

    const int wm = (wid & 3) * 32;
    const int wn = (wid >> 2) * 32;
    const int er = lane >> 2;
    const int ecb = (lane & 3) * 2;
    const int krow = (lane & 7) | ((lane & 16) >> 1);
    const int colc = (lane >> 3) & 1;

    float acc[2][4][4];
    #pragma unroll
    for (int i = 0; i < 2; i++)
        #pragma unroll
        for (int j = 0; j < 4; j++)
            #pragma unroll
            for (int r = 0; r < 4; r++) acc[i][j][r] = 0.f;

    issue(0);
    for (int ck = 0; ck < 6; ck++) {
        issue(ck + 1);
        CP_WAIT1();
        __syncthreads();
        const int stg = (ck & 1);
        float* sA = sA_f + stg * (AV_STAGE / 4);
        const uint32_t vt_h = sb + stg * AV_STAGE + AV_ATILE;
        const uint32_t vt_l = vt_h + AV_VTILE;
        #pragma unroll
        for (int ks = 0; ks < 4; ks++) {
            uint32_t ahf[2][4], alf[2][4];
            #pragma unroll
            for (int mt = 0; mt < 2; mt++) {
                const int r_ = wm + mt * 16 + er;
                const int cb = ks * 16 + ecb;
                float2 x0 = *(float2*)(sA + (size_t)r_ * AV_AROW + cb);
                float2 x1 = *(float2*)(sA + (size_t)(r_ + 8) * AV_AROW + cb);
                float2 x2 = *(float2*)(sA + (size_t)r_ * AV_AROW + cb + 8);
                float2 x3 = *(float2*)(sA + (size_t)(r_ + 8) * AV_AROW + cb + 8);
                pack_hilo(x0.x, x0.y, ahf[mt][0], alf[mt][0]);
                pack_hilo(x1.x, x1.y, ahf[mt][1], alf[mt][1]);
                pack_hilo(x2.x, x2.y, ahf[mt][2], alf[mt][2]);
                pack_hilo(x3.x, x3.y, ahf[mt][3], alf[mt][3]);
            }
            uint32_t badr[2];
            #pragma unroll
            for (int bt = 0; bt < 2; bt++) {
                const int row = ks * 16 + krow;
                const int c = (wn >> 3) + bt * 2 + colc;
                badr[bt] = row * 128 + ((c ^ (row & 7)) << 4);
            }
            uint32_t bhf[2][4], blf[2][4];
            #pragma unroll
            for (int bt = 0; bt < 2; bt++) LDSM_X4_T(bhf[bt], vt_h + badr[bt]);
            #pragma unroll
            for (int bt = 0; bt < 2; bt++) LDSM_X4_T(blf[bt], vt_l + badr[bt]);
            #pragma unroll
            for (int mt = 0; mt < 2; mt++)
                #pragma unroll
                for (int nt = 0; nt < 4; nt++)
                    mma_bf16(acc[mt][nt], ahf[mt],
                             bhf[nt >> 1][nt & 1], bhf[nt >> 1][(nt & 1) + 2]);
            #pragma unroll
            for (int mt = 0; mt < 2; mt++)
                #pragma unroll
                for (int nt = 0; nt < 4; nt++)
                    mma_bf16(acc[mt][nt], alf[mt],
                             bhf[nt >> 1][nt & 1], bhf[nt >> 1][(nt & 1) + 2]);
            #pragma unroll
            for (int mt = 0; mt < 2; mt++)
                #pragma unroll
                for (int nt = 0; nt < 4; nt++)
                    mma_bf16(acc[mt][nt], ahf[mt],
                             blf[nt >> 1][nt & 1], blf[nt >> 1][(nt & 1) + 2]);
        }
        __syncthreads();
    }

    const int ec = (lane & 3) * 2;
    #pragma unroll
    for (int mt = 0; mt < 2; mt++) {
        #pragma unroll
        for (int nt = 0; nt < 4; nt++) {
            const int row = i0 + wm + mt * 16 + er;
            const int col = h * 64 + wn + nt * 8 + ec;
            const size_t o0 = (size_t)(b * Sc + row) * Dc + col;
            const size_t o1 = (size_t)(b * Sc + row + 8) * Dc + col;
            split2(acc[mt][nt][0], acc[mt][nt][1], vh_out + o0, vl_out + o0);
            split2(acc[mt][nt][2], acc[mt][nt][3], vh_out + o1, vl_out + o1);
        }
    }
}

// ---------------------------------------------------------------------------
extern "C" void kernel_launch(void* const* d_in, const int* in_sizes, int n_in,
                              void* d_out, int out_size)
{
    const float* x     = (const float*)d_in[0];
    const float* qkv_w = (const float*)d_in[1];
    const float* qkv_b = (const float*)d_in[2];
    const float* out_w = (const float*)d_in[3];
    const float* out_b = (const float*)d_in[4];
    const float* rpe   = (const float*)d_in[5];

    float* attnscr;
    __nv_bfloat16 *ah, *al, *wqh, *wql, *woh, *wol, *qkvh, *qkvl, *rpeh, *rpel;
    cudaGetSymbolAddress((void**)&attnscr, g_attn);
    cudaGetSymbolAddress((void**)&ah, g_ah);
    cudaGetSymbolAddress((void**)&al, g_al);
    cudaGetSymbolAddress((void**)&wqh, g_wqh);
    cudaGetSymbolAddress((void**)&wql, g_wql);
    cudaGetSymbolAddress((void**)&woh, g_woh);
    cudaGetSymbolAddress((void**)&wol, g_wol);
    cudaGetSymbolAddress((void**)&qkvh, g_qkvh);
    cudaGetSymbolAddress((void**)&qkvl, g_qkvl);
    cudaGetSymbolAddress((void**)&rpeh, g_rpeh);
    cudaGetSymbolAddress((void**)&rpel, g_rpel);

    float* out = (float*)d_out;
    const long OUT_E = (long)BSc * Dc;
    const long ATT_E = (long)Bc * Hc * Sc * Sc;
    float* attn = ((long)out_size >= OUT_E + ATT_E) ? (out + OUT_E) : attnscr;

    cudaFuncSetAttribute(mma_gemm_kernel,
                         cudaFuncAttributeMaxDynamicSharedMemorySize, GSMEM);
    cudaFuncSetAttribute(qk_mma_kernel,
                         cudaFuncAttributeMaxDynamicSharedMemorySize, QK_SMEM);
    cudaFuncSetAttribute(rpe_mma_softmax_kernel,
                         cudaFuncAttributeMaxDynamicSharedMemorySize, RPE_SMEM);
    cudaFuncSetAttribute(av_mma_kernel,
                         cudaFuncAttributeMaxDynamicSharedMemorySize, AV_SMEM);

    // 0) fused prep: split x + weights + rpe table
    prep_kernel<<<8191, 256>>>(x, ah, al, qkv_w, wqh, wql, out_w, woh, wol,
                               rpe, rpeh, rpel);
    // 1) qkv: emit bf16 hi/lo (q cols pre-scaled 1/8)
    mma_gemm_kernel<<<dim3(D3c / 128, BSc / 128), 256, GSMEM>>>(
        ah, al, wqh, wql, qkv_b, nullptr, qkvh, qkvl, 1, BSc, D3c, Dc);
    // 2) logits = (q/8) . k
    qk_mma_kernel<<<dim3(3, 3, Bc * Hc), 256, QK_SMEM>>>(qkvh, qkvl, attn);
    // 3+4) rpe bias via HMMA + softmax (2 same-slab items per block)
    rpe_mma_softmax_kernel<<<dim3(24 * 31, 8), 256, RPE_SMEM>>>(
        qkvh, qkvl, rpeh, rpel, attn);
    // 5) values = attn @ v -> bf16 hi/lo
    av_mma_kernel<<<dim3(3, Bc * Hc), 256, AV_SMEM>>>(attn, qkvh, qkvl, ah, al);
    // 6) out = values @ out_w + out_b
    mma_gemm_kernel<<<dim3(Dc / 128, BSc / 128), 256, GSMEM>>>(
        ah, al, woh, wol, out_b, out, nullptr, nullptr, 0, BSc, Dc, Dc);
}

// round 14
// speedup vs baseline: 1.4492x; 1.0023x over previous
#include <cuda_runtime.h>
#include <cuda_bf16.h>
#include <cstdint>

#define Bc 8
#define Sc 384
#define Dc 1024
#define Hc 16
#define HDc 64
#define D3c 3072
#define BSc 3072   // B*S
#define RPE_ROWS 1023

// ---------------------------------------------------------------------------
// Scratch (static device globals; no runtime allocation)
// ---------------------------------------------------------------------------
__device__ float g_attn[(size_t)Bc * Hc * Sc * Sc];   // fallback attn buffer
__device__ __align__(16) __nv_bfloat16 g_ah[(size_t)BSc * Dc];    // A hi (x, then vals)
__device__ __align__(16) __nv_bfloat16 g_al[(size_t)BSc * Dc];    // A lo
__device__ __align__(16) __nv_bfloat16 g_wqh[(size_t)D3c * Dc];   // qkv_w^T hi [N,K]
__device__ __align__(16) __nv_bfloat16 g_wql[(size_t)D3c * Dc];   // qkv_w^T lo
__device__ __align__(16) __nv_bfloat16 g_woh[(size_t)Dc * Dc];    // out_w^T hi
__device__ __align__(16) __nv_bfloat16 g_wol[(size_t)Dc * Dc];    // out_w^T lo
__device__ __align__(16) __nv_bfloat16 g_qkvh[(size_t)BSc * D3c]; // qkv hi (q pre-scaled /8)
__device__ __align__(16) __nv_bfloat16 g_qkvl[(size_t)BSc * D3c]; // qkv lo
__device__ __align__(16) __nv_bfloat16 g_rpeh[(size_t)RPE_ROWS * Dc]; // rpe hi
__device__ __align__(16) __nv_bfloat16 g_rpel[(size_t)RPE_ROWS * Dc]; // rpe lo

// ---------------------------------------------------------------------------
// Baseline-PTX helpers
// ---------------------------------------------------------------------------
__device__ __forceinline__ uint32_t smem_u32(const void* p) {
    uint32_t a;
    asm("{ .reg .u64 t; cvta.to.shared.u64 t, %1; cvt.u32.u64 %0, t; }" : "=r"(a) : "l"(p));
    return a;
}
#define CP_ASYNC16(sm, gp) \
    asm volatile("cp.async.cg.shared.global [%0], [%1], 16;" :: "r"(sm), "l"(gp))
#define CP_COMMIT() asm volatile("cp.async.commit_group;" ::: "memory")
#define CP_WAIT0()  asm volatile("cp.async.wait_group 0;" ::: "memory")
#define CP_WAIT1()  asm volatile("cp.async.wait_group 1;" ::: "memory")

#define LDSM_X4(r, a) \
    asm volatile("ldmatrix.sync.aligned.m8n8.x4.shared.b16 {%0,%1,%2,%3}, [%4];" \
        : "=r"((r)[0]), "=r"((r)[1]), "=r"((r)[2]), "=r"((r)[3]) : "r"(a))
#define LDSM_X4_T(r, a) \
    asm volatile("ldmatrix.sync.aligned.m8n8.x4.trans.shared.b16 {%0,%1,%2,%3}, [%4];" \
        : "=r"((r)[0]), "=r"((r)[1]), "=r"((r)[2]), "=r"((r)[3]) : "r"(a))

__device__ __forceinline__ void mma_bf16(float* d, const uint32_t* a,
                                         uint32_t b0, uint32_t b1) {
    asm volatile(
        "mma.sync.aligned.m16n8k16.row.col.f32.bf16.bf16.f32 "
        "{%0,%1,%2,%3}, {%4,%5,%6,%7}, {%8,%9}, {%0,%1,%2,%3};"
        : "+f"(d[0]), "+f"(d[1]), "+f"(d[2]), "+f"(d[3])
        : "r"(a[0]), "r"(a[1]), "r"(a[2]), "r"(a[3]), "r"(b0), "r"(b1));
}

__device__ __forceinline__ void split2(float x, float y,
                                       __nv_bfloat16* ph, __nv_bfloat16* pl) {
    __nv_bfloat16 hx = __float2bfloat16(x), hy = __float2bfloat16(y);
    *(__nv_bfloat162*)ph = __nv_bfloat162(hx, hy);
    *(__nv_bfloat162*)pl = __nv_bfloat162(
        __float2bfloat16(x - __bfloat162float(hx)),
        __float2bfloat16(y - __bfloat162float(hy)));
}
__device__ __forceinline__ void pack_hilo(float x, float y,
                                          uint32_t& hi, uint32_t& lo) {
    __nv_bfloat16 hx = __float2bfloat16(x), hy = __float2bfloat16(y);
    __nv_bfloat162 h2(hx, hy);
    __nv_bfloat162 l2(__float2bfloat16(x - __bfloat162float(hx)),
                      __float2bfloat16(y - __bfloat162float(hy)));
    hi = *(uint32_t*)&h2;
    lo = *(uint32_t*)&l2;
}

// ---------------------------------------------------------------------------
// HMMA bf16-split GEMM: C = (Ah+Al)@(Bh+Bl)^T + bias
// Single-sync mainloop: wait group -> barrier -> issue(it+2) -> compute(it).
// ---------------------------------------------------------------------------
#define TILE_B 8192
#define BUF_B  (4 * TILE_B)
#define NSTAGE 3
#define GSMEM  (NSTAGE * BUF_B)   // 96 KB

__global__ __launch_bounds__(256, 2) void mma_gemm_kernel(
    const __nv_bfloat16* __restrict__ Ah, const __nv_bfloat16* __restrict__ Al,
    const __nv_bfloat16* __restrict__ Bh, const __nv_bfloat16* __restrict__ Bl,
    const float* __restrict__ bias, float* __restrict__ C,
    __nv_bfloat16* __restrict__ Ch, __nv_bfloat16* __restrict__ Cl,
    int qkv_mode, int M, int N, int K)
{
    extern __shared__ char smem[];
    const uint32_t sbase = smem_u32(smem);
    const int tid  = threadIdx.x;
    const int wid  = tid >> 5;
    const int lane = tid & 31;
    const int m0 = blockIdx.y * 128;
    const int n0 = blockIdx.x * 128;
    const int mw = (wid & 1) * 64;
    const int nw = (wid >> 1) * 32;

    const int lrow = tid >> 1;
    const int c0   = (tid & 1) * 2;
    const int sw0  = (lrow >> 1) & 3;
    const __nv_bfloat16* gAh = Ah + (size_t)(m0 + lrow) * K;
    const __nv_bfloat16* gAl = Al + (size_t)(m0 + lrow) * K;
    const __nv_bfloat16* gBh = Bh + (size_t)(n0 + lrow) * K;
    const __nv_bfloat16* gBl = Bl + (size_t)(n0 + lrow) * K;
    const uint32_t soff0 = lrow * 64 + (((c0 + 0) ^ sw0) << 4);
    const uint32_t soff1 = lrow * 64 + (((c0 + 1) ^ sw0) << 4);

    const int NK = K >> 5;

    auto issue = [&](int it) {
        if (it < NK) {
            const uint32_t tb = sbase + (it % NSTAGE) * BUF_B;
            const int k0 = it << 5;
            CP_ASYNC16(tb + 0 * TILE_B + soff0, gAh + k0 + (c0 + 0) * 8);
            CP_ASYNC16(tb + 0 * TILE_B + soff1, gAh + k0 + (c0 + 1) * 8);
            CP_ASYNC16(tb + 1 * TILE_B + soff0, gAl + k0 + (c0 + 0) * 8);
            CP_ASYNC16(tb + 1 * TILE_B + soff1, gAl + k0 + (c0 + 1) * 8);
            CP_ASYNC16(tb + 2 * TILE_B + soff0, gBh + k0 + (c0 + 0) * 8);
            CP_ASYNC16(tb + 2 * TILE_B + soff1, gBh + k0 + (c0 + 1) * 8);
            CP_ASYNC16(tb + 3 * TILE_B + soff0, gBl + k0 + (c0 + 0) * 8);
            CP_ASYNC16(tb + 3 * TILE_B + soff1, gBl + k0 + (c0 + 1) * 8);
        }
        CP_COMMIT();
    };

    const int frow = lane & 15;
    const int fc   = lane >> 4;
    auto fr_addr = [&](int rbase) -> uint32_t {
        const int row = rbase + frow;
        return (uint32_t)(row * 64 + ((fc ^ ((row >> 1) & 3)) << 4));
    };
    const uint32_t aoff = fr_addr(mw);
    const uint32_t boff = fr_addr(nw);

    float acc[4][4][4];
    #pragma unroll
    for (int i = 0; i < 4; i++)
        #pragma unroll
        for (int j = 0; j < 4; j++)
            #pragma unroll
            for (int r = 0; r < 4; r++) acc[i][j][r] = 0.f;

    issue(0); issue(1);

    for (int it = 0; it < NK; it++) {
        CP_WAIT1();
        __syncthreads();
        issue(it + 2);
        const uint32_t tb = sbase + (it % NSTAGE) * BUF_B;
        #pragma unroll
        for (int ks = 0; ks < 2; ks++) {
            const uint32_t kx = ks ? 32u : 0u;
            uint32_t ahf[4][4], bhf[2][4];
            #pragma unroll
            for (int mt = 0; mt < 4; mt++)
                LDSM_X4(ahf[mt], tb + ((aoff + mt * 1024) ^ kx));
            #pragma unroll
            for (int bt = 0; bt < 2; bt++)
                LDSM_X4(bhf[bt], tb + 2 * TILE_B + ((boff + bt * 1024) ^ kx));
            #pragma unroll
            for (int mt = 0; mt < 4; mt++)
                #pragma unroll
                for (int nt = 0; nt < 4; nt++)
                    mma_bf16(acc[mt][nt], ahf[mt],
                             bhf[nt >> 1][nt & 1], bhf[nt >> 1][(nt & 1) + 2]);
            uint32_t blf[2][4];
            #pragma unroll
            for (int bt = 0; bt < 2; bt++)
                LDSM_X4(blf[bt], tb + 3 * TILE_B + ((boff + bt * 1024) ^ kx));
            #pragma unroll
            for (int mt = 0; mt < 4; mt++)
                #pragma unroll
                for (int nt = 0; nt < 4; nt++)
                    mma_bf16(acc[mt][nt], ahf[mt],
                             blf[nt >> 1][nt & 1], blf[nt >> 1][(nt & 1) + 2]);
            uint32_t alf[4][4];
            #pragma unroll
            for (int mt = 0; mt < 4; mt++)
                LDSM_X4(alf[mt], tb + TILE_B + ((aoff + mt * 1024) ^ kx));
            #pragma unroll
            for (int mt = 0; mt < 4; mt++)
                #pragma unroll
                for (int nt = 0; nt < 4; nt++)
                    mma_bf16(acc[mt][nt], alf[mt],
                             bhf[nt >> 1][nt & 1], bhf[nt >> 1][(nt & 1) + 2]);
        }
    }

    const int er = lane >> 2;
    const int ec = (lane & 3) * 2;
    #pragma unroll
    for (int mt = 0; mt < 4; mt++) {
        #pragma unroll
        for (int nt = 0; nt < 4; nt++) {
            const int col = n0 + nw + nt * 8 + ec;
            const float bx = __ldg(&bias[col]);
            const float by = __ldg(&bias[col + 1]);
            const int r0 = m0 + mw + mt * 16 + er;
            float2 v0 = make_float2(acc[mt][nt][0] + bx, acc[mt][nt][1] + by);
            float2 v1 = make_float2(acc[mt][nt][2] + bx, acc[mt][nt][3] + by);
            if (C) {
                *(float2*)(C + (size_t)r0 * N + col) = v0;
                *(float2*)(C + (size_t)(r0 + 8) * N + col) = v1;
            }
            if (Ch) {
                const float s = (qkv_mode && (((col >> 6) % 3) == 0)) ? 0.125f : 1.0f;
                split2(v0.x * s, v0.y * s, Ch + (size_t)r0 * N + col,
                       Cl + (size_t)r0 * N + col);
                split2(v1.x * s, v1.y * s, Ch + (size_t)(r0 + 8) * N + col,
                       Cl + (size_t)(r0 + 8) * N + col);
            }
        }
    }
}

// ---------------------------------------------------------------------------
// Fused prep: split x + transpose-split qkv_w + out_w + split rpe table.
// ---------------------------------------------------------------------------
__global__ __launch_bounds__(256) void prep_kernel(
    const float* __restrict__ x,
    __nv_bfloat16* __restrict__ ah, __nv_bfloat16* __restrict__ al,
    const float* __restrict__ qkv_w,
    __nv_bfloat16* __restrict__ wqh, __nv_bfloat16* __restrict__ wql,
    const float* __restrict__ out_w,
    __nv_bfloat16* __restrict__ woh, __nv_bfloat16* __restrict__ wol,
    const float* __restrict__ rpe,
    __nv_bfloat16* __restrict__ rpeh, __nv_bfloat16* __restrict__ rpel)
{
    __shared__ float t[32][33];
    const int bid = blockIdx.x;
    const int tid = threadIdx.x;
    if (bid < 3072) {
        const int i = bid * 256 + tid;
        float4 v = ((const float4*)x)[i];
        split2(v.x, v.y, ah + 4 * (size_t)i, al + 4 * (size_t)i);
        split2(v.z, v.w, ah + 4 * (size_t)i + 2, al + 4 * (size_t)i + 2);
        return;
    }
    if (bid >= 7168) {
        const int i = (bid - 7168) * 256 + tid;
        float4 v = ((const float4*)rpe)[i];
        split2(v.x, v.y, rpeh + 4 * (size_t)i, rpel + 4 * (size_t)i);
        split2(v.z, v.w, rpeh + 4 * (size_t)i + 2, rpel + 4 * (size_t)i + 2);
        return;
    }
    const float* W;
    __nv_bfloat16 *Th, *Tl;
    int N, bx, by;
    if (bid < 6144) {
        const int r = bid - 3072;
        W = qkv_w; Th = wqh; Tl = wql; N = D3c;
        bx = r % 96; by = r / 96;
    } else {
        const int r = bid - 6144;
        W = out_w; Th = woh; Tl = wol; N = Dc;
        bx = r % 32; by = r / 32;
    }
    const int K = Dc;
    const int n0 = bx * 32, k0 = by * 32;
    const int tx = tid & 31, ty = tid >> 5;
    #pragma unroll
    for (int r = 0; r < 4; r++)
        t[ty + 8 * r][tx] = W[(size_t)(k0 + ty + 8 * r) * N + n0 + tx];
    __syncthreads();
    #pragma unroll
    for (int r = 0; r < 4; r++) {
        float v = t[tx][ty + 8 * r];
        __nv_bfloat16 h = __float2bfloat16(v);
        __nv_bfloat16 l = __float2bfloat16(v - __bfloat162float(h));
        size_t o = (size_t)(n0 + ty + 8 * r) * K + k0 + tx;
        Th[o] = h; Tl[o] = l;
    }
}

// ---------------------------------------------------------------------------
// qk HMMA: logits = (scaled q).k, 3-pass bf16 split, interleaved LDSM.
// ---------------------------------------------------------------------------
#define QK_SMEM (4 * 16384)

__global__ __launch_bounds__(256, 2) void qk_mma_kernel(
    const __nv_bfloat16* __restrict__ qkvh, const __nv_bfloat16* __restrict__ qkvl,
    float* __restrict__ attn)
{
    extern __shared__ char smem[];
    const uint32_t sb = smem_u32(smem);
    const int tid = threadIdx.x, wid = tid >> 5, lane = tid & 31;
    const int bh = blockIdx.z, b = bh >> 4, h = bh & 15;
    const int i0 = blockIdx.y * 128, j0 = blockIdx.x * 128;

    #pragma unroll
    for (int t = 0; t < 4; t++) {
        const __nv_bfloat16* base = (t & 1) ? qkvl : qkvh;
        const int roff = (t < 2) ? i0 : j0;
        const int coff = h * 192 + ((t < 2) ? 0 : 64);
        for (int idx = tid; idx < 1024; idx += 256) {
            const int row = idx >> 3, c = idx & 7;
            const uint32_t dst = sb + t * 16384 + row * 128 + ((c ^ (row & 7)) << 4);
            CP_ASYNC16(dst, base + (size_t)(b * Sc + roff + row) * D3c + coff + c * 8);
        }
    }
    CP_COMMIT(); CP_WAIT0();
    __syncthreads();

    const int mw = (wid & 1) * 64;
    const int nw = (wid >> 1) * 32;
    const int frow = lane & 15, fc = lane >> 4;

    float acc[4][4][4];
    #pragma unroll
    for (int i = 0; i < 4; i++)
        #pragma unroll
        for (int j = 0; j < 4; j++)
            #pragma unroll
            for (int r = 0; r < 4; r++) acc[i][j][r] = 0.f;

    #pragma unroll
    for (int ks = 0; ks < 4; ks++) {
        uint32_t aadr[4], badr[2];
        #pragma unroll
        for (int mt = 0; mt < 4; mt++) {
            const int row = mw + mt * 16 + frow;
            aadr[mt] = row * 128 + (((2 * ks + fc) ^ (row & 7)) << 4);
        }
        #pragma unroll
        for (int bt = 0; bt < 2; bt++) {
            const int row = nw + bt * 16 + frow;
            badr[bt] = row * 128 + (((2 * ks + fc) ^ (row & 7)) << 4);
        }
        uint32_t ahf[4][4], bhf[2][4];
        #pragma unroll
        for (int mt = 0; mt < 4; mt++) LDSM_X4(ahf[mt], sb + aadr[mt]);
        #pragma unroll
        for (int bt = 0; bt < 2; bt++) LDSM_X4(bhf[bt], sb + 2 * 16384 + badr[bt]);
        #pragma unroll
        for (int mt = 0; mt < 4; mt++)
            #pragma unroll
            for (int nt = 0; nt < 4; nt++)
                mma_bf16(acc[mt][nt], ahf[mt],
                         bhf[nt >> 1][nt & 1], bhf[nt >> 1][(nt & 1) + 2]);
        uint32_t blf[2][4];
        #pragma unroll
        for (int bt = 0; bt < 2; bt++) LDSM_X4(blf[bt], sb + 3 * 16384 + badr[bt]);
        #pragma unroll
        for (int mt = 0; mt < 4; mt++)
            #pragma unroll
            for (int nt = 0; nt < 4; nt++)
                mma_bf16(acc[mt][nt], ahf[mt],
                         blf[nt >> 1][nt & 1], blf[nt >> 1][(nt & 1) + 2]);
        uint32_t alf[4][4];
        #pragma unroll
        for (int mt = 0; mt < 4; mt++) LDSM_X4(alf[mt], sb + 16384 + aadr[mt]);
        #pragma unroll
        for (int mt = 0; mt < 4; mt++)
            #pragma unroll
            for (int nt = 0; nt < 4; nt++)
                mma_bf16(acc[mt][nt], alf[mt],
                         bhf[nt >> 1][nt & 1], bhf[nt >> 1][(nt & 1) + 2]);
    }

    const int er = lane >> 2, ec = (lane & 3) * 2;
    float* ob = attn + (size_t)bh * Sc * Sc;
    #pragma unroll
    for (int mt = 0; mt < 4; mt++) {
        #pragma unroll
        for (int nt = 0; nt < 4; nt++) {
            const int r0 = i0 + mw + mt * 16 + er;
            const int col = j0 + nw + nt * 8 + ec;
            *(float2*)(ob + (size_t)r0 * Sc + col) =
                make_float2(acc[mt][nt][0], acc[mt][nt][1]);
            *(float2*)(ob + (size_t)(r0 + 8) * Sc + col) =
                make_float2(acc[mt][nt][2], acc[mt][nt][3]);
        }
    }
}

// ---------------------------------------------------------------------------
// rpe bias via HMMA + fused softmax — 4 same-slab items per block.
// bias[(it,b), j] = q[(it,b),:] . slab[j,:]  (M=32, N=384, K=64 GEMM).
// Slab (bf16 hi/lo) streamed in 6 chunks of 64 j rows, double-buffered.
// SMEM: q 8KB | slab 2x16KB | L 48KB = 90112 B -> 2 CTA/SM.
// grid = (744 diagonals, 4 quad slots); tails duplicate last item (benign).
// ---------------------------------------------------------------------------
#define RPE_SMEM (8192 + 2 * 16384 + 32 * Sc * 4)   // 90112

__global__ __launch_bounds__(256, 2) void rpe_mma_softmax_kernel(
    const __nv_bfloat16* __restrict__ qkvh, const __nv_bfloat16* __restrict__ qkvl,
    const __nv_bfloat16* __restrict__ rpeh, const __nv_bfloat16* __restrict__ rpel,
    float* __restrict__ attn)
{
    extern __shared__ char smem[];
    const uint32_t sb = smem_u32(smem);
    const uint32_t slab0 = sb + 8192;
    float* L = (float*)(smem + 8192 + 32768);     // [32][384]
    const uint32_t Lbase = sb + 8192 + 32768;
    const int tid = threadIdx.x, wid = tid >> 5, lane = tid & 31;

    const int a = blockIdx.x / 31;
    const int d = blockIdx.x % 31 - 15;
    const int h_lo = d < 0 ? -d : 0;
    const int h_hi = d > 0 ? 15 - d : 15;
    const int h0 = h_lo + 4 * (int)blockIdx.y;
    if (h0 > h_hi) return;
    int hh[4], ii[4];
    #pragma unroll
    for (int it = 0; it < 4; it++) {
        const int hx = (h0 + it <= h_hi) ? (h0 + it) : h_hi;
        hh[it] = hx;
        ii[it] = 16 * a + hx + d;
    }
    const size_t r0off = (size_t)(384 + 24 * d - a) * 1024;

    // slab chunk loader: 64 rows x 128B, hi+lo
    auto slab_issue = [&](int nc) {
        const uint32_t st = slab0 + (nc & 1) * 16384;
        for (int idx = tid; idx < 512; idx += 256) {
            const int row = idx >> 3, c2 = idx & 7;
            const uint32_t sw = row * 128 + ((c2 ^ (row & 7)) << 4);
            const size_t go = r0off + (size_t)(nc * 64 + row) * 64 + c2 * 8;
            CP_ASYNC16(st + sw, rpeh + go);
            CP_ASYNC16(st + 8192 + sw, rpel + go);
        }
        CP_COMMIT();
    };

    // group A: q tiles (2 arrays x 32 rows x 8 chunks) + attn prefetch + chunk0
    for (int t = tid; t < 512; t += 256) {
        const int arr = t >> 8;          // 0=hi,1=lo
        const int r = (t >> 3) & 31;     // it*8+b
        const int c = t & 7;
        const int it = r >> 3, b = r & 7;
        const __nv_bfloat16* src = arr ? qkvl : qkvh;
        CP_ASYNC16(sb + arr * 4096 + r * 128 + ((c ^ (r & 7)) << 4),
                   src + (size_t)(b * Sc + ii[it]) * D3c + hh[it] * 192 + c * 8);
    }
    #pragma unroll
    for (int rr = 0; rr < 12; rr++) {
        const int idx = tid + rr * 256;
        const int row = idx / 96, cc = idx % 96;
        const int it2 = row >> 3, b2 = row & 7;
        CP_ASYNC16(Lbase + (uint32_t)(row * Sc + cc * 4) * 4,
                   attn + ((size_t)(b2 * Hc + hh[it2]) * Sc + ii[it2]) * Sc + cc * 4);
    }
    {
        const uint32_t st = slab0;
        for (int idx = tid; idx < 512; idx += 256) {
            const int row = idx >> 3, c2 = idx & 7;
            const uint32_t sw = row * 128 + ((c2 ^ (row & 7)) << 4);
            const size_t go = r0off + (size_t)row * 64 + c2 * 8;
            CP_ASYNC16(st + sw, rpeh + go);
            CP_ASYNC16(st + 8192 + sw, rpel + go);
        }
        CP_COMMIT();
    }
    slab_issue(1);

    const int frow = lane & 15, fc = lane >> 4;
    const int mt = wid >> 2;               // m16 tile 0/1
    const int wn = (wid & 3) * 16;         // warp's 16 j-rows within chunk
    const int er = lane >> 2, ec = (lane & 3) * 2;
    const uint32_t aq = sb + mt * 2048;    // row base mt*16 within 32-row tile
    // a-tile addresses: rows mt*16 + frow
    const int arow = mt * 16 + frow;

    for (int ck = 0; ck < 6; ck++) {
        CP_WAIT1();
        __syncthreads();
        const uint32_t st = slab0 + (ck & 1) * 16384;
        float acc[2][4];
        #pragma unroll
        for (int nt = 0; nt < 2; nt++)
            #pragma unroll
            for (int r = 0; r < 4; r++) acc[nt][r] = 0.f;

        #pragma unroll
        for (int ks = 0; ks < 4; ks++) {
            const uint32_t aadr = arow * 128 + (((2 * ks + fc) ^ (arow & 7)) << 4);
            const int brow = wn + frow;
            const uint32_t badr = brow * 128 + (((2 * ks + fc) ^ (brow & 7)) << 4);
            uint32_t ah4[4], al4[4], bh4[4], bl4[4];
            LDSM_X4(ah4, sb + aadr);
            LDSM_X4(bh4, st + badr);
            #pragma unroll
            for (int nt = 0; nt < 2; nt++)
                mma_bf16(acc[nt], ah4, bh4[nt], bh4[nt + 2]);
            LDSM_X4(bl4, st + 8192 + badr);
            #pragma unroll
            for (int nt = 0; nt < 2; nt++)
                mma_bf16(acc[nt], ah4, bl4[nt], bl4[nt + 2]);
            LDSM_X4(al4, sb + 4096 + aadr);
            #pragma unroll
            for (int nt = 0; nt < 2; nt++)
                mma_bf16(acc[nt], al4, bh4[nt], bh4[nt + 2]);
        }
        __syncthreads();
        if (ck + 2 < 6) slab_issue(ck + 2);
        else CP_COMMIT();
        // add bias (x8 undoes q/8 pre-scale; exact pow2); attn resident since
        // group A drained at first CP_WAIT1. Each (row,col) owned by 1 thread.
        #pragma unroll
        for (int nt = 0; nt < 2; nt++) {
            const int col = ck * 64 + wn + nt * 8 + ec;
            const int rbase = mt * 16;
            L[(rbase + er) * Sc + col]           += 8.f * acc[nt][0];
            L[(rbase + er) * Sc + col + 1]       += 8.f * acc[nt][1];
            L[(rbase + er + 8) * Sc + col]       += 8.f * acc[nt][2];
            L[(rbase + er + 8) * Sc + col + 1]   += 8.f * acc[nt][3];
        }
    }
    __syncthreads();

    // softmax: 32 (it,b) rows over 8 warps = 4 rows per warp
    #pragma unroll
    for (int rr = 0; rr < 4; rr++) {
        const int row = wid * 4 + rr;
        const int it = row >> 3, b = row & 7;
        float v[12];
        float m = -1e30f;
        #pragma unroll
        for (int r = 0; r < 12; r++) { v[r] = L[row * Sc + lane + 32 * r]; m = fmaxf(m, v[r]); }
        #pragma unroll
        for (int o = 16; o > 0; o >>= 1) m = fmaxf(m, __shfl_xor_sync(0xffffffffu, m, o));
        float s = 0.f;
        #pragma unroll
        for (int r = 0; r < 12; r++) { v[r] = __expf(v[r] - m); s += v[r]; }
        #pragma unroll
        for (int o = 16; o > 0; o >>= 1) s += __shfl_xor_sync(0xffffffffu, s, o);
        const float inv = 1.0f / s;
        float* orow = attn + ((size_t)(b * Hc + hh[it]) * Sc + ii[it]) * Sc;
        #pragma unroll
        for (int r = 0; r < 12; r++) orow[lane + 32 * r] = v[r] * inv;
    }
}

// ---------------------------------------------------------------------------
// av HMMA: values = attn(fp32) @ v, 3-pass bf16 split.
// ---------------------------------------------------------------------------
#define AV_AROW 72
#define AV_ATILE (128 * AV_AROW * 4)
#define AV_VTILE 8192
#define AV_STAGE (AV_ATILE + 2 * AV_VTILE)
#define AV_SMEM  (2 * AV_STAGE)

__global__ __launch_bounds__(256, 2) void av_mma_kernel(
    const float* __restrict__ attn,
    const __nv_bfloat16* __restrict__ qkvh, const __nv_bfloat16* __restrict__ qkvl,
    __nv_bfloat16* __restrict__ vh_out, __nv_bfloat16* __restrict__ vl_out)
{
    extern __shared__ char smem[];
    const uint32_t sb = smem_u32(smem);
    float* sA_f = (float*)smem;
    const int tid = threadIdx.x, wid = tid >> 5, lane = tid & 31;
    const int bh = blockIdx.y, b = bh >> 4, h = bh & 15;
    const int i0 = blockIdx.x * 128;

    const float* abase = attn + ((size_t)bh * Sc + i0) * Sc;
    const __nv_bfloat16* vbase_h = qkvh + h * 192 + 128;
    const __nv_bfloat16* vbase_l = qkvl + h * 192 + 128;

    auto issue = [&](int ck) {
        if (ck >= 6) { CP_COMMIT(); return; }
        const uint32_t st = sb + (ck & 1) * AV_STAGE;
        const int j0 = ck * 64;
        for (int idx = tid; idx < 2048; idx += 256) {
            const int row = idx >> 4, c = idx & 15;
            CP_ASYNC16(st + row * (AV_AROW * 4) + c * 16,
                       abase + (size_t)row * Sc + j0 + c * 4);
        }
        for (int idx = tid; idx < 512; idx += 256) {
            const int row = idx >> 3, c = idx & 7;
            const uint32_t sw = row * 128 + ((c ^ (row & 7)) << 4);
            const size_t go = (size_t)(b * Sc + j0 + row) * D3c + c * 8;
            CP_ASYNC16(st + AV_ATILE + sw, vbase_h + go);
            CP_ASYNC16(st + AV_ATILE + AV_VTILE + sw, vbase_l + go);
        }
        CP_COMMIT();
    };

    const int wm = (wid & 3) * 32;
    const int wn = (wid >> 2) * 32;
    const int er = lane >> 2;
    const int ecb = (lane & 3) * 2;
    const int krow = (lane & 7) | ((lane & 16) >> 1);
    const int colc = (lane >> 3) & 1;

    float acc[2][4][4];
    #pragma unroll
    for (int i = 0; i < 2; i++)
        #pragma unroll
        for (int j = 0; j < 4; j++)
            #pragma unroll
            for (int r = 0; r < 4; r++) acc[i][j][r] = 0.f;

    issue(0);
    for (int ck = 0; ck < 6; ck++) {
        issue(ck + 1);
        CP_WAIT1();
        __syncthreads();
        const int stg = (ck & 1);
        float* sA = sA_f + stg * (AV_STAGE / 4);
        const uint32_t vt_h = sb + stg * AV_STAGE + AV_ATILE;
        const uint32_t vt_l = vt_h + AV_VTILE;
        #pragma unroll
        for (int ks = 0; ks < 4; ks++) {
            uint32_t ahf[2][4], alf[2][4];
            #pragma unroll
            for (int mt = 0; mt < 2; mt++) {
                const int r_ = wm + mt * 16 + er;
                const int cb = ks * 16 + ecb;
                float2 x0 = *(float2*)(sA + (size_t)r_ * AV_AROW + cb);
                float2 x1 = *(float2*)(sA + (size_t)(r_ + 8) * AV_AROW + cb);
                float2 x2 = *(float2*)(sA + (size_t)r_ * AV_AROW + cb + 8);
                float2 x3 = *(float2*)(sA + (size_t)(r_ + 8) * AV_AROW + cb + 8);
                pack_hilo(x0.x, x0.y, ahf[mt][0], alf[mt][0]);
                pack_hilo(x1.x, x1.y, ahf[mt][1], alf[mt][1]);
                pack_hilo(x2.x, x2.y, ahf[mt][2], alf[mt][2]);
                pack_hilo(x3.x, x3.y, ahf[mt][3], alf[mt][3]);
            }
            uint32_t badr[2];
            #pragma unroll
            for (int bt = 0; bt < 2; bt++) {
                const int row = ks * 16 + krow;
                const int c = (wn >> 3) + bt * 2 + colc;
                badr[bt] = row * 128 + ((c ^ (row & 7)) << 4);
            }
            uint32_t bhf[2][4], blf[2][4];
            #pragma unroll
            for (int bt = 0; bt < 2; bt++) LDSM_X4_T(bhf[bt], vt_h + badr[bt]);
            #pragma unroll
            for (int bt = 0; bt < 2; bt++) LDSM_X4_T(blf[bt], vt_l + badr[bt]);
            #pragma unroll
            for (int mt = 0; mt < 2; mt++)
                #pragma unroll
                for (int nt = 0; nt < 4; nt++)
                    mma_bf16(acc[mt][nt], ahf[mt],
                             bhf[nt >> 1][nt & 1], bhf[nt >> 1][(nt & 1) + 2]);
            #pragma unroll
            for (int mt = 0; mt < 2; mt++)
                #pragma unroll
                for (int nt = 0; nt < 4; nt++)
                    mma_bf16(acc[mt][nt], alf[mt],
                             bhf[nt >> 1][nt & 1], bhf[nt >> 1][(nt & 1) + 2]);
            #pragma unroll
            for (int mt = 0; mt < 2; mt++)
                #pragma unroll
                for (int nt = 0; nt < 4; nt++)
                    mma_bf16(acc[mt][nt], ahf[mt],
                             blf[nt >> 1][nt & 1], blf[nt >> 1][(nt & 1) + 2]);
        }
        __syncthreads();
    }

    const int ec = (lane & 3) * 2;
    #pragma unroll
    for (int mt = 0; mt < 2; mt++) {
        #pragma unroll
        for (int nt = 0; nt < 4; nt++) {
            const int row = i0 + wm + mt * 16 + er;
            const int col = h * 64 + wn + nt * 8 + ec;
            const size_t o0 = (size_t)(b * Sc + row) * Dc + col;
            const size_t o1 = (size_t)(b * Sc + row + 8) * Dc + col;
            split2(acc[mt][nt][0], acc[mt][nt][1], vh_out + o0, vl_out + o0);
            split2(acc[mt][nt][2], acc[mt][nt][3], vh_out + o1, vl_out + o1);
        }
    }
}

// ---------------------------------------------------------------------------
extern "C" void kernel_launch(void* const* d_in, const int* in_sizes, int n_in,
                              void* d_out, int out_size)
{
    const float* x     = (const float*)d_in[0];
    const float* qkv_w = (const float*)d_in[1];
    const float* qkv_b = (const float*)d_in[2];
    const float* out_w = (const float*)d_in[3];
    const float* out_b = (const float*)d_in[4];
    const float* rpe   = (const float*)d_in[5];

    float* attnscr;
    __nv_bfloat16 *ah, *al, *wqh, *wql, *woh, *wol, *qkvh, *qkvl, *rpeh, *rpel;
    cudaGetSymbolAddress((void**)&attnscr, g_attn);
    cudaGetSymbolAddress((void**)&ah, g_ah);
    cudaGetSymbolAddress((void**)&al, g_al);
    cudaGetSymbolAddress((void**)&wqh, g_wqh);
    cudaGetSymbolAddress((void**)&wql, g_wql);
    cudaGetSymbolAddress((void**)&woh, g_woh);
    cudaGetSymbolAddress((void**)&wol, g_wol);
    cudaGetSymbolAddress((void**)&qkvh, g_qkvh);
    cudaGetSymbolAddress((void**)&qkvl, g_qkvl);
    cudaGetSymbolAddress((void**)&rpeh, g_rpeh);
    cudaGetSymbolAddress((void**)&rpel, g_rpel);

    float* out = (float*)d_out;
    const long OUT_E = (long)BSc * Dc;
    const long ATT_E = (long)Bc * Hc * Sc * Sc;
    float* attn = ((long)out_size >= OUT_E + ATT_E) ? (out + OUT_E) : attnscr;

    cudaFuncSetAttribute(mma_gemm_kernel,
                         cudaFuncAttributeMaxDynamicSharedMemorySize, GSMEM);
    cudaFuncSetAttribute(qk_mma_kernel,
                         cudaFuncAttributeMaxDynamicSharedMemorySize, QK_SMEM);
    cudaFuncSetAttribute(rpe_mma_softmax_kernel,
                         cudaFuncAttributeMaxDynamicSharedMemorySize, RPE_SMEM);
    cudaFuncSetAttribute(av_mma_kernel,
                         cudaFuncAttributeMaxDynamicSharedMemorySize, AV_SMEM);

    // 0) fused prep: split x + weights + rpe table
    prep_kernel<<<8191, 256>>>(x, ah, al, qkv_w, wqh, wql, out_w, woh, wol,
                               rpe, rpeh, rpel);
    // 1) qkv: emit bf16 hi/lo (q cols pre-scaled 1/8)
    mma_gemm_kernel<<<dim3(D3c / 128, BSc / 128), 256, GSMEM>>>(
        ah, al, wqh, wql, qkv_b, nullptr, qkvh, qkvl, 1, BSc, D3c, Dc);
    // 2) logits = (q/8) . k
    qk_mma_kernel<<<dim3(3, 3, Bc * Hc), 256, QK_SMEM>>>(qkvh, qkvl, attn);
    // 3+4) rpe bias via HMMA + softmax (4 same-slab items per block)
    rpe_mma_softmax_kernel<<<dim3(24 * 31, 4), 256, RPE_SMEM>>>(
        qkvh, qkvl, rpeh, rpel, attn);
    // 5) values = attn @ v -> bf16 hi/lo
    av_mma_kernel<<<dim3(3, Bc * Hc), 256, AV_SMEM>>>(attn, qkvh, qkvl, ah, al);
    // 6) out = values @ out_w + out_b
    mma_gemm_kernel<<<dim3(Dc / 128, BSc / 128), 256, GSMEM>>>(
        ah, al, woh, wol, out_b, out, nullptr, nullptr, 0, BSc, Dc, Dc);
}

// round 15
// speedup vs baseline: 1.4575x; 1.0057x over previous
#include <cuda_runtime.h>
#include <cuda_bf16.h>
#include <cstdint>

#define Bc 8
#define Sc 384
#define Dc 1024
#define Hc 16
#define HDc 64
#define D3c 3072
#define BSc 3072   // B*S
#define RPE_ROWS 1023

// ---------------------------------------------------------------------------
// Scratch (static device globals; no runtime allocation)
// ---------------------------------------------------------------------------
__device__ float g_attn[(size_t)Bc * Hc * Sc * Sc];   // fallback attn buffer
__device__ __align__(16) __nv_bfloat16 g_ah[(size_t)BSc * Dc];    // A hi (x, then vals)
__device__ __align__(16) __nv_bfloat16 g_al[(size_t)BSc * Dc];    // A lo
__device__ __align__(16) __nv_bfloat16 g_wqh[(size_t)D3c * Dc];   // qkv_w^T hi [N,K]
__device__ __align__(16) __nv_bfloat16 g_wql[(size_t)D3c * Dc];   // qkv_w^T lo
__device__ __align__(16) __nv_bfloat16 g_woh[(size_t)Dc * Dc];    // out_w^T hi
__device__ __align__(16) __nv_bfloat16 g_wol[(size_t)Dc * Dc];    // out_w^T lo
__device__ __align__(16) __nv_bfloat16 g_qkvh[(size_t)BSc * D3c]; // qkv hi (q pre-scaled /8)
__device__ __align__(16) __nv_bfloat16 g_qkvl[(size_t)BSc * D3c]; // qkv lo
__device__ __align__(16) __nv_bfloat16 g_rpeh[(size_t)RPE_ROWS * Dc]; // rpe hi
__device__ __align__(16) __nv_bfloat16 g_rpel[(size_t)RPE_ROWS * Dc]; // rpe lo

// ---------------------------------------------------------------------------
// Baseline-PTX helpers
// ---------------------------------------------------------------------------
__device__ __forceinline__ uint32_t smem_u32(const void* p) {
    uint32_t a;
    asm("{ .reg .u64 t; cvta.to.shared.u64 t, %1; cvt.u32.u64 %0, t; }" : "=r"(a) : "l"(p));
    return a;
}
#define CP_ASYNC16(sm, gp) \
    asm volatile("cp.async.cg.shared.global [%0], [%1], 16;" :: "r"(sm), "l"(gp))
#define CP_COMMIT() asm volatile("cp.async.commit_group;" ::: "memory")
#define CP_WAIT0()  asm volatile("cp.async.wait_group 0;" ::: "memory")
#define CP_WAIT1()  asm volatile("cp.async.wait_group 1;" ::: "memory")

#define LDSM_X4(r, a) \
    asm volatile("ldmatrix.sync.aligned.m8n8.x4.shared.b16 {%0,%1,%2,%3}, [%4];" \
        : "=r"((r)[0]), "=r"((r)[1]), "=r"((r)[2]), "=r"((r)[3]) : "r"(a))
#define LDSM_X4_T(r, a) \
    asm volatile("ldmatrix.sync.aligned.m8n8.x4.trans.shared.b16 {%0,%1,%2,%3}, [%4];" \
        : "=r"((r)[0]), "=r"((r)[1]), "=r"((r)[2]), "=r"((r)[3]) : "r"(a))

__device__ __forceinline__ void mma_bf16(float* d, const uint32_t* a,
                                         uint32_t b0, uint32_t b1) {
    asm volatile(
        "mma.sync.aligned.m16n8k16.row.col.f32.bf16.bf16.f32 "
        "{%0,%1,%2,%3}, {%4,%5,%6,%7}, {%8,%9}, {%0,%1,%2,%3};"
        : "+f"(d[0]), "+f"(d[1]), "+f"(d[2]), "+f"(d[3])
        : "r"(a[0]), "r"(a[1]), "r"(a[2]), "r"(a[3]), "r"(b0), "r"(b1));
}

__device__ __forceinline__ void split2(float x, float y,
                                       __nv_bfloat16* ph, __nv_bfloat16* pl) {
    __nv_bfloat16 hx = __float2bfloat16(x), hy = __float2bfloat16(y);
    *(__nv_bfloat162*)ph = __nv_bfloat162(hx, hy);
    *(__nv_bfloat162*)pl = __nv_bfloat162(
        __float2bfloat16(x - __bfloat162float(hx)),
        __float2bfloat16(y - __bfloat162float(hy)));
}
__device__ __forceinline__ void pack_hilo(float x, float y,
                                          uint32_t& hi, uint32_t& lo) {
    __nv_bfloat16 hx = __float2bfloat16(x), hy = __float2bfloat16(y);
    __nv_bfloat162 h2(hx, hy);
    __nv_bfloat162 l2(__float2bfloat16(x - __bfloat162float(hx)),
                      __float2bfloat16(y - __bfloat162float(hy)));
    hi = *(uint32_t*)&h2;
    lo = *(uint32_t*)&l2;
}

// ---------------------------------------------------------------------------
// HMMA bf16-split GEMM: C = (Ah+Al)@(Bh+Bl)^T + bias
// Single-sync mainloop: wait group -> barrier -> issue(it+2) -> compute(it).
// ---------------------------------------------------------------------------
#define TILE_B 8192
#define BUF_B  (4 * TILE_B)
#define NSTAGE 3
#define GSMEM  (NSTAGE * BUF_B)   // 96 KB

__global__ __launch_bounds__(256, 2) void mma_gemm_kernel(
    const __nv_bfloat16* __restrict__ Ah, const __nv_bfloat16* __restrict__ Al,
    const __nv_bfloat16* __restrict__ Bh, const __nv_bfloat16* __restrict__ Bl,
    const float* __restrict__ bias, float* __restrict__ C,
    __nv_bfloat16* __restrict__ Ch, __nv_bfloat16* __restrict__ Cl,
    int qkv_mode, int M, int N, int K)
{
    extern __shared__ char smem[];
    const uint32_t sbase = smem_u32(smem);
    const int tid  = threadIdx.x;
    const int wid  = tid >> 5;
    const int lane = tid & 31;
    const int m0 = blockIdx.y * 128;
    const int n0 = blockIdx.x * 128;
    const int mw = (wid & 1) * 64;
    const int nw = (wid >> 1) * 32;

    const int lrow = tid >> 1;
    const int c0   = (tid & 1) * 2;
    const int sw0  = (lrow >> 1) & 3;
    const __nv_bfloat16* gAh = Ah + (size_t)(m0 + lrow) * K;
    const __nv_bfloat16* gAl = Al + (size_t)(m0 + lrow) * K;
    const __nv_bfloat16* gBh = Bh + (size_t)(n0 + lrow) * K;
    const __nv_bfloat16* gBl = Bl + (size_t)(n0 + lrow) * K;
    const uint32_t soff0 = lrow * 64 + (((c0 + 0) ^ sw0) << 4);
    const uint32_t soff1 = lrow * 64 + (((c0 + 1) ^ sw0) << 4);

    const int NK = K >> 5;

    auto issue = [&](int it) {
        if (it < NK) {
            const uint32_t tb = sbase + (it % NSTAGE) * BUF_B;
            const int k0 = it << 5;
            CP_ASYNC16(tb + 0 * TILE_B + soff0, gAh + k0 + (c0 + 0) * 8);
            CP_ASYNC16(tb + 0 * TILE_B + soff1, gAh + k0 + (c0 + 1) * 8);
            CP_ASYNC16(tb + 1 * TILE_B + soff0, gAl + k0 + (c0 + 0) * 8);
            CP_ASYNC16(tb + 1 * TILE_B + soff1, gAl + k0 + (c0 + 1) * 8);
            CP_ASYNC16(tb + 2 * TILE_B + soff0, gBh + k0 + (c0 + 0) * 8);
            CP_ASYNC16(tb + 2 * TILE_B + soff1, gBh + k0 + (c0 + 1) * 8);
            CP_ASYNC16(tb + 3 * TILE_B + soff0, gBl + k0 + (c0 + 0) * 8);
            CP_ASYNC16(tb + 3 * TILE_B + soff1, gBl + k0 + (c0 + 1) * 8);
        }
        CP_COMMIT();
    };

    const int frow = lane & 15;
    const int fc   = lane >> 4;
    auto fr_addr = [&](int rbase) -> uint32_t {
        const int row = rbase + frow;
        return (uint32_t)(row * 64 + ((fc ^ ((row >> 1) & 3)) << 4));
    };
    const uint32_t aoff = fr_addr(mw);
    const uint32_t boff = fr_addr(nw);

    float acc[4][4][4];
    #pragma unroll
    for (int i = 0; i < 4; i++)
        #pragma unroll
        for (int j = 0; j < 4; j++)
            #pragma unroll
            for (int r = 0; r < 4; r++) acc[i][j][r] = 0.f;

    issue(0); issue(1);

    for (int it = 0; it < NK; it++) {
        CP_WAIT1();
        __syncthreads();
        issue(it + 2);
        const uint32_t tb = sbase + (it % NSTAGE) * BUF_B;
        #pragma unroll
        for (int ks = 0; ks < 2; ks++) {
            const uint32_t kx = ks ? 32u : 0u;
            uint32_t ahf[4][4], bhf[2][4];
            #pragma unroll
            for (int mt = 0; mt < 4; mt++)
                LDSM_X4(ahf[mt], tb + ((aoff + mt * 1024) ^ kx));
            #pragma unroll
            for (int bt = 0; bt < 2; bt++)
                LDSM_X4(bhf[bt], tb + 2 * TILE_B + ((boff + bt * 1024) ^ kx));
            #pragma unroll
            for (int mt = 0; mt < 4; mt++)
                #pragma unroll
                for (int nt = 0; nt < 4; nt++)
                    mma_bf16(acc[mt][nt], ahf[mt],
                             bhf[nt >> 1][nt & 1], bhf[nt >> 1][(nt & 1) + 2]);
            uint32_t blf[2][4];
            #pragma unroll
            for (int bt = 0; bt < 2; bt++)
                LDSM_X4(blf[bt], tb + 3 * TILE_B + ((boff + bt * 1024) ^ kx));
            #pragma unroll
            for (int mt = 0; mt < 4; mt++)
                #pragma unroll
                for (int nt = 0; nt < 4; nt++)
                    mma_bf16(acc[mt][nt], ahf[mt],
                             blf[nt >> 1][nt & 1], blf[nt >> 1][(nt & 1) + 2]);
            uint32_t alf[4][4];
            #pragma unroll
            for (int mt = 0; mt < 4; mt++)
                LDSM_X4(alf[mt], tb + TILE_B + ((aoff + mt * 1024) ^ kx));
            #pragma unroll
            for (int mt = 0; mt < 4; mt++)
                #pragma unroll
                for (int nt = 0; nt < 4; nt++)
                    mma_bf16(acc[mt][nt], alf[mt],
                             bhf[nt >> 1][nt & 1], bhf[nt >> 1][(nt & 1) + 2]);
        }
    }

    const int er = lane >> 2;
    const int ec = (lane & 3) * 2;
    #pragma unroll
    for (int mt = 0; mt < 4; mt++) {
        #pragma unroll
        for (int nt = 0; nt < 4; nt++) {
            const int col = n0 + nw + nt * 8 + ec;
            const float bx = __ldg(&bias[col]);
            const float by = __ldg(&bias[col + 1]);
            const int r0 = m0 + mw + mt * 16 + er;
            float2 v0 = make_float2(acc[mt][nt][0] + bx, acc[mt][nt][1] + by);
            float2 v1 = make_float2(acc[mt][nt][2] + bx, acc[mt][nt][3] + by);
            if (C) {
                *(float2*)(C + (size_t)r0 * N + col) = v0;
                *(float2*)(C + (size_t)(r0 + 8) * N + col) = v1;
            }
            if (Ch) {
                const float s = (qkv_mode && (((col >> 6) % 3) == 0)) ? 0.125f : 1.0f;
                split2(v0.x * s, v0.y * s, Ch + (size_t)r0 * N + col,
                       Cl + (size_t)r0 * N + col);
                split2(v1.x * s, v1.y * s, Ch + (size_t)(r0 + 8) * N + col,
                       Cl + (size_t)(r0 + 8) * N + col);
            }
        }
    }
}

// ---------------------------------------------------------------------------
// Fused prep: split x + transpose-split qkv_w + out_w + split rpe table.
// ---------------------------------------------------------------------------
__global__ __launch_bounds__(256) void prep_kernel(
    const float* __restrict__ x,
    __nv_bfloat16* __restrict__ ah, __nv_bfloat16* __restrict__ al,
    const float* __restrict__ qkv_w,
    __nv_bfloat16* __restrict__ wqh, __nv_bfloat16* __restrict__ wql,
    const float* __restrict__ out_w,
    __nv_bfloat16* __restrict__ woh, __nv_bfloat16* __restrict__ wol,
    const float* __restrict__ rpe,
    __nv_bfloat16* __restrict__ rpeh, __nv_bfloat16* __restrict__ rpel)
{
    __shared__ float t[32][33];
    const int bid = blockIdx.x;
    const int tid = threadIdx.x;
    if (bid < 3072) {
        const int i = bid * 256 + tid;
        float4 v = ((const float4*)x)[i];
        split2(v.x, v.y, ah + 4 * (size_t)i, al + 4 * (size_t)i);
        split2(v.z, v.w, ah + 4 * (size_t)i + 2, al + 4 * (size_t)i + 2);
        return;
    }
    if (bid >= 7168) {
        const int i = (bid - 7168) * 256 + tid;
        float4 v = ((const float4*)rpe)[i];
        split2(v.x, v.y, rpeh + 4 * (size_t)i, rpel + 4 * (size_t)i);
        split2(v.z, v.w, rpeh + 4 * (size_t)i + 2, rpel + 4 * (size_t)i + 2);
        return;
    }
    const float* W;
    __nv_bfloat16 *Th, *Tl;
    int N, bx, by;
    if (bid < 6144) {
        const int r = bid - 3072;
        W = qkv_w; Th = wqh; Tl = wql; N = D3c;
        bx = r % 96; by = r / 96;
    } else {
        const int r = bid - 6144;
        W = out_w; Th = woh; Tl = wol; N = Dc;
        bx = r % 32; by = r / 32;
    }
    const int K = Dc;
    const int n0 = bx * 32, k0 = by * 32;
    const int tx = tid & 31, ty = tid >> 5;
    #pragma unroll
    for (int r = 0; r < 4; r++)
        t[ty + 8 * r][tx] = W[(size_t)(k0 + ty + 8 * r) * N + n0 + tx];
    __syncthreads();
    #pragma unroll
    for (int r = 0; r < 4; r++) {
        float v = t[tx][ty + 8 * r];
        __nv_bfloat16 h = __float2bfloat16(v);
        __nv_bfloat16 l = __float2bfloat16(v - __bfloat162float(h));
        size_t o = (size_t)(n0 + ty + 8 * r) * K + k0 + tx;
        Th[o] = h; Tl[o] = l;
    }
}

// ---------------------------------------------------------------------------
// qk HMMA: logits = (scaled q).k, 3-pass bf16 split, interleaved LDSM.
// ---------------------------------------------------------------------------
#define QK_SMEM (4 * 16384)

__global__ __launch_bounds__(256, 2) void qk_mma_kernel(
    const __nv_bfloat16* __restrict__ qkvh, const __nv_bfloat16* __restrict__ qkvl,
    float* __restrict__ attn)
{
    extern __shared__ char smem[];
    const uint32_t sb = smem_u32(smem);
    const int tid = threadIdx.x, wid = tid >> 5, lane = tid & 31;
    const int bh = blockIdx.z, b = bh >> 4, h = bh & 15;
    const int i0 = blockIdx.y * 128, j0 = blockIdx.x * 128;

    #pragma unroll
    for (int t = 0; t < 4; t++) {
        const __nv_bfloat16* base = (t & 1) ? qkvl : qkvh;
        const int roff = (t < 2) ? i0 : j0;
        const int coff = h * 192 + ((t < 2) ? 0 : 64);
        for (int idx = tid; idx < 1024; idx += 256) {
            const int row = idx >> 3, c = idx & 7;
            const uint32_t dst = sb + t * 16384 + row * 128 + ((c ^ (row & 7)) << 4);
            CP_ASYNC16(dst, base + (size_t)(b * Sc + roff + row) * D3c + coff + c * 8);
        }
    }
    CP_COMMIT(); CP_WAIT0();
    __syncthreads();

    const int mw = (wid & 1) * 64;
    const int nw = (wid >> 1) * 32;
    const int frow = lane & 15, fc = lane >> 4;

    float acc[4][4][4];
    #pragma unroll
    for (int i = 0; i < 4; i++)
        #pragma unroll
        for (int j = 0; j < 4; j++)
            #pragma unroll
            for (int r = 0; r < 4; r++) acc[i][j][r] = 0.f;

    #pragma unroll
    for (int ks = 0; ks < 4; ks++) {
        uint32_t aadr[4], badr[2];
        #pragma unroll
        for (int mt = 0; mt < 4; mt++) {
            const int row = mw + mt * 16 + frow;
            aadr[mt] = row * 128 + (((2 * ks + fc) ^ (row & 7)) << 4);
        }
        #pragma unroll
        for (int bt = 0; bt < 2; bt++) {
            const int row = nw + bt * 16 + frow;
            badr[bt] = row * 128 + (((2 * ks + fc) ^ (row & 7)) << 4);
        }
        uint32_t ahf[4][4], bhf[2][4];
        #pragma unroll
        for (int mt = 0; mt < 4; mt++) LDSM_X4(ahf[mt], sb + aadr[mt]);
        #pragma unroll
        for (int bt = 0; bt < 2; bt++) LDSM_X4(bhf[bt], sb + 2 * 16384 + badr[bt]);
        #pragma unroll
        for (int mt = 0; mt < 4; mt++)
            #pragma unroll
            for (int nt = 0; nt < 4; nt++)
                mma_bf16(acc[mt][nt], ahf[mt],
                         bhf[nt >> 1][nt & 1], bhf[nt >> 1][(nt & 1) + 2]);
        uint32_t blf[2][4];
        #pragma unroll
        for (int bt = 0; bt < 2; bt++) LDSM_X4(blf[bt], sb + 3 * 16384 + badr[bt]);
        #pragma unroll
        for (int mt = 0; mt < 4; mt++)
            #pragma unroll
            for (int nt = 0; nt < 4; nt++)
                mma_bf16(acc[mt][nt], ahf[mt],
                         blf[nt >> 1][nt & 1], blf[nt >> 1][(nt & 1) + 2]);
        uint32_t alf[4][4];
        #pragma unroll
        for (int mt = 0; mt < 4; mt++) LDSM_X4(alf[mt], sb + 16384 + aadr[mt]);
        #pragma unroll
        for (int mt = 0; mt < 4; mt++)
            #pragma unroll
            for (int nt = 0; nt < 4; nt++)
                mma_bf16(acc[mt][nt], alf[mt],
                         bhf[nt >> 1][nt & 1], bhf[nt >> 1][(nt & 1) + 2]);
    }

    const int er = lane >> 2, ec = (lane & 3) * 2;
    float* ob = attn + (size_t)bh * Sc * Sc;
    #pragma unroll
    for (int mt = 0; mt < 4; mt++) {
        #pragma unroll
        for (int nt = 0; nt < 4; nt++) {
            const int r0 = i0 + mw + mt * 16 + er;
            const int col = j0 + nw + nt * 8 + ec;
            *(float2*)(ob + (size_t)r0 * Sc + col) =
                make_float2(acc[mt][nt][0], acc[mt][nt][1]);
            *(float2*)(ob + (size_t)(r0 + 8) * Sc + col) =
                make_float2(acc[mt][nt][2], acc[mt][nt][3]);
        }
    }
}

// ---------------------------------------------------------------------------
// rpe bias via HMMA + fused softmax — 4 same-slab items per block.
// Single-buffered slab (16KB) -> SMEM 72KB -> 3 CTA/SM (occupancy play;
// intra-block load exposure hidden by cross-CTA overlap).
// SMEM: q 8KB | slab 16KB | L 48KB = 73728 B.
// ---------------------------------------------------------------------------
#define RPE_SMEM (8192 + 16384 + 32 * Sc * 4)   // 73728

__global__ __launch_bounds__(256, 3) void rpe_mma_softmax_kernel(
    const __nv_bfloat16* __restrict__ qkvh, const __nv_bfloat16* __restrict__ qkvl,
    const __nv_bfloat16* __restrict__ rpeh, const __nv_bfloat16* __restrict__ rpel,
    float* __restrict__ attn)
{
    extern __shared__ char smem[];
    const uint32_t sb = smem_u32(smem);
    const uint32_t slab0 = sb + 8192;
    float* L = (float*)(smem + 8192 + 16384);     // [32][384]
    const uint32_t Lbase = sb + 8192 + 16384;
    const int tid = threadIdx.x, wid = tid >> 5, lane = tid & 31;

    const int a = blockIdx.x / 31;
    const int d = blockIdx.x % 31 - 15;
    const int h_lo = d < 0 ? -d : 0;
    const int h_hi = d > 0 ? 15 - d : 15;
    const int h0 = h_lo + 4 * (int)blockIdx.y;
    if (h0 > h_hi) return;
    int hh[4], ii[4];
    #pragma unroll
    for (int it = 0; it < 4; it++) {
        const int hx = (h0 + it <= h_hi) ? (h0 + it) : h_hi;
        hh[it] = hx;
        ii[it] = 16 * a + hx + d;
    }
    const size_t r0off = (size_t)(384 + 24 * d - a) * 1024;

    // slab chunk loader: 64 rows x 128B, hi+lo into the single 16KB stage
    auto slab_issue = [&](int nc) {
        for (int idx = tid; idx < 512; idx += 256) {
            const int row = idx >> 3, c2 = idx & 7;
            const uint32_t sw = row * 128 + ((c2 ^ (row & 7)) << 4);
            const size_t go = r0off + (size_t)(nc * 64 + row) * 64 + c2 * 8;
            CP_ASYNC16(slab0 + sw, rpeh + go);
            CP_ASYNC16(slab0 + 8192 + sw, rpel + go);
        }
        CP_COMMIT();
    };

    // group A: q tiles (2 arrays x 32 rows x 8 chunks) + attn prefetch
    for (int t = tid; t < 512; t += 256) {
        const int arr = t >> 8;          // 0=hi,1=lo
        const int r = (t >> 3) & 31;     // it*8+b
        const int c = t & 7;
        const int it = r >> 3, b = r & 7;
        const __nv_bfloat16* src = arr ? qkvl : qkvh;
        CP_ASYNC16(sb + arr * 4096 + r * 128 + ((c ^ (r & 7)) << 4),
                   src + (size_t)(b * Sc + ii[it]) * D3c + hh[it] * 192 + c * 8);
    }
    #pragma unroll
    for (int rr = 0; rr < 12; rr++) {
        const int idx = tid + rr * 256;
        const int row = idx / 96, cc = idx % 96;
        const int it2 = row >> 3, b2 = row & 7;
        CP_ASYNC16(Lbase + (uint32_t)(row * Sc + cc * 4) * 4,
                   attn + ((size_t)(b2 * Hc + hh[it2]) * Sc + ii[it2]) * Sc + cc * 4);
    }
    CP_COMMIT();

    const int frow = lane & 15, fc = lane >> 4;
    const int mt = wid >> 2;               // m16 tile 0/1
    const int wn = (wid & 3) * 16;         // warp's 16 j-rows within chunk
    const int er = lane >> 2, ec = (lane & 3) * 2;
    const int arow = mt * 16 + frow;

    for (int ck = 0; ck < 6; ck++) {
        slab_issue(ck);
        CP_WAIT0();
        __syncthreads();
        float acc[2][4];
        #pragma unroll
        for (int nt = 0; nt < 2; nt++)
            #pragma unroll
            for (int r = 0; r < 4; r++) acc[nt][r] = 0.f;

        #pragma unroll
        for (int ks = 0; ks < 4; ks++) {
            const uint32_t aadr = arow * 128 + (((2 * ks + fc) ^ (arow & 7)) << 4);
            const int brow = wn + frow;
            const uint32_t badr = brow * 128 + (((2 * ks + fc) ^ (brow & 7)) << 4);
            uint32_t ah4[4], al4[4], bh4[4], bl4[4];
            LDSM_X4(ah4, sb + aadr);
            LDSM_X4(bh4, slab0 + badr);
            #pragma unroll
            for (int nt = 0; nt < 2; nt++)
                mma_bf16(acc[nt], ah4, bh4[nt], bh4[nt + 2]);
            LDSM_X4(bl4, slab0 + 8192 + badr);
            #pragma unroll
            for (int nt = 0; nt < 2; nt++)
                mma_bf16(acc[nt], ah4, bl4[nt], bl4[nt + 2]);
            LDSM_X4(al4, sb + 4096 + aadr);
            #pragma unroll
            for (int nt = 0; nt < 2; nt++)
                mma_bf16(acc[nt], al4, bh4[nt], bh4[nt + 2]);
        }
        // add bias (x8 undoes q/8 pre-scale; exact pow2); attn resident since
        // group A drained at first CP_WAIT0. Each (row,col) owned by 1 thread.
        #pragma unroll
        for (int nt = 0; nt < 2; nt++) {
            const int col = ck * 64 + wn + nt * 8 + ec;
            const int rbase = mt * 16;
            L[(rbase + er) * Sc + col]           += 8.f * acc[nt][0];
            L[(rbase + er) * Sc + col + 1]       += 8.f * acc[nt][1];
            L[(rbase + er + 8) * Sc + col]       += 8.f * acc[nt][2];
            L[(rbase + er + 8) * Sc + col + 1]   += 8.f * acc[nt][3];
        }
        __syncthreads();   // all reads of slab done before next overwrite
    }

    // softmax: 32 (it,b) rows over 8 warps = 4 rows per warp
    #pragma unroll
    for (int rr = 0; rr < 4; rr++) {
        const int row = wid * 4 + rr;
        const int it = row >> 3, b = row & 7;
        float v[12];
        float m = -1e30f;
        #pragma unroll
        for (int r = 0; r < 12; r++) { v[r] = L[row * Sc + lane + 32 * r]; m = fmaxf(m, v[r]); }
        #pragma unroll
        for (int o = 16; o > 0; o >>= 1) m = fmaxf(m, __shfl_xor_sync(0xffffffffu, m, o));
        float s = 0.f;
        #pragma unroll
        for (int r = 0; r < 12; r++) { v[r] = __expf(v[r] - m); s += v[r]; }
        #pragma unroll
        for (int o = 16; o > 0; o >>= 1) s += __shfl_xor_sync(0xffffffffu, s, o);
        const float inv = 1.0f / s;
        float* orow = attn + ((size_t)(b * Hc + hh[it]) * Sc + ii[it]) * Sc;
        #pragma unroll
        for (int r = 0; r < 12; r++) orow[lane + 32 * r] = v[r] * inv;
    }
}

// ---------------------------------------------------------------------------
// av HMMA: values = attn(fp32) @ v, 3-pass bf16 split.
// 64-row i-tiles (grid (6, B*H) = 768 blocks), 3 CTA/SM (wave balance).
// Warp layout: 2 warps over 64 rows (32 each), 4 warps over 64 cols (16 each).
// ---------------------------------------------------------------------------
#define AV_AROW 72
#define AV_ATILE (64 * AV_AROW * 4)          // 18432
#define AV_VTILE 8192
#define AV_STAGE (AV_ATILE + 2 * AV_VTILE)   // 34816
#define AV_SMEM  (2 * AV_STAGE)              // 69632

__global__ __launch_bounds__(256, 3) void av_mma_kernel(
    const float* __restrict__ attn,
    const __nv_bfloat16* __restrict__ qkvh, const __nv_bfloat16* __restrict__ qkvl,
    __nv_bfloat16* __restrict__ vh_out, __nv_bfloat16* __restrict__ vl_out)
{
    extern __shared__ char smem[];
    const uint32_t sb = smem_u32(smem);
    float* sA_f = (float*)smem;
    const int tid = threadIdx.x, wid = tid >> 5, lane = tid & 31;
    const int bh = blockIdx.y, b = bh >> 4, h = bh & 15;
    const int i0 = blockIdx.x * 64;

    const float* abase = attn + ((size_t)bh * Sc + i0) * Sc;
    const __nv_bfloat16* vbase_h = qkvh + h * 192 + 128;
    const __nv_bfloat16* vbase_l = qkvl + h * 192 + 128;

    auto issue = [&](int ck) {
        if (ck >= 6) { CP_COMMIT(); return; }
        const uint32_t st = sb + (ck & 1) * AV_STAGE;
        const int j0 = ck * 64;
        for (int idx = tid; idx < 1024; idx += 256) {
            const int row = idx >> 4, c = idx & 15;
            CP_ASYNC16(st + row * (AV_AROW * 4) + c * 16,
                       abase + (size_t)row * Sc + j0 + c * 4);
        }
        for (int idx = tid; idx < 512; idx += 256) {
            const int row = idx >> 3, c = idx & 7;
            const uint32_t sw = row * 128 + ((c ^ (row & 7)) << 4);
            const size_t go = (size_t)(b * Sc + j0 + row) * D3c + c * 8;
            CP_ASYNC16(st + AV_ATILE + sw, vbase_h + go);
            CP_ASYNC16(st + AV_ATILE + AV_VTILE + sw, vbase_l + go);
        }
        CP_COMMIT();
    };

    const int wm = (wid & 1) * 32;        // 2 warps over 64 rows
    const int wn = (wid >> 1) * 16;       // 4 warps over 64 cols
    const int er = lane >> 2;
    const int ecb = (lane & 3) * 2;
    const int krow = (lane & 7) | ((lane & 16) >> 1);
    const int colc = (lane >> 3) & 1;

    float acc[2][2][4];
    #pragma unroll
    for (int i = 0; i < 2; i++)
        #pragma unroll
        for (int j = 0; j < 2; j++)
            #pragma unroll
            for (int r = 0; r < 4; r++) acc[i][j][r] = 0.f;

    issue(0);
    for (int ck = 0; ck < 6; ck++) {
        issue(ck + 1);
        CP_WAIT1();
        __syncthreads();
        const int stg = (ck & 1);
        float* sA = sA_f + stg * (AV_STAGE / 4);
        const uint32_t vt_h = sb + stg * AV_STAGE + AV_ATILE;
        const uint32_t vt_l = vt_h + AV_VTILE;
        #pragma unroll
        for (int ks = 0; ks < 4; ks++) {
            uint32_t ahf[2][4], alf[2][4];
            #pragma unroll
            for (int mt = 0; mt < 2; mt++) {
                const int r_ = wm + mt * 16 + er;
                const int cb = ks * 16 + ecb;
                float2 x0 = *(float2*)(sA + (size_t)r_ * AV_AROW + cb);
                float2 x1 = *(float2*)(sA + (size_t)(r_ + 8) * AV_AROW + cb);
                float2 x2 = *(float2*)(sA + (size_t)r_ * AV_AROW + cb + 8);
                float2 x3 = *(float2*)(sA + (size_t)(r_ + 8) * AV_AROW + cb + 8);
                pack_hilo(x0.x, x0.y, ahf[mt][0], alf[mt][0]);
                pack_hilo(x1.x, x1.y, ahf[mt][1], alf[mt][1]);
                pack_hilo(x2.x, x2.y, ahf[mt][2], alf[mt][2]);
                pack_hilo(x3.x, x3.y, ahf[mt][3], alf[mt][3]);
            }
            // V frag: 16 cols for this warp (one LDSM_X4_T per array)
            const int vrow = ks * 16 + krow;
            const int vc = (wn >> 3) + colc;
            const uint32_t badr = vrow * 128 + ((vc ^ (vrow & 7)) << 4);
            uint32_t bhf[4], blf[4];
            LDSM_X4_T(bhf, vt_h + badr);
            LDSM_X4_T(blf, vt_l + badr);
            #pragma unroll
            for (int mt = 0; mt < 2; mt++)
                #pragma unroll
                for (int nt = 0; nt < 2; nt++)
                    mma_bf16(acc[mt][nt], ahf[mt], bhf[nt], bhf[nt + 2]);
            #pragma unroll
            for (int mt = 0; mt < 2; mt++)
                #pragma unroll
                for (int nt = 0; nt < 2; nt++)
                    mma_bf16(acc[mt][nt], alf[mt], bhf[nt], bhf[nt + 2]);
            #pragma unroll
            for (int mt = 0; mt < 2; mt++)
                #pragma unroll
                for (int nt = 0; nt < 2; nt++)
                    mma_bf16(acc[mt][nt], ahf[mt], blf[nt], blf[nt + 2]);
        }
        __syncthreads();
    }

    const int ec = (lane & 3) * 2;
    #pragma unroll
    for (int mt = 0; mt < 2; mt++) {
        #pragma unroll
        for (int nt = 0; nt < 2; nt++) {
            const int row = i0 + wm + mt * 16 + er;
            const int col = h * 64 + wn + nt * 8 + ec;
            const size_t o0 = (size_t)(b * Sc + row) * Dc + col;
            const size_t o1 = (size_t)(b * Sc + row + 8) * Dc + col;
            split2(acc[mt][nt][0], acc[mt][nt][1], vh_out + o0, vl_out + o0);
            split2(acc[mt][nt][2], acc[mt][nt][3], vh_out + o1, vl_out + o1);
        }
    }
}

// ---------------------------------------------------------------------------
extern "C" void kernel_launch(void* const* d_in, const int* in_sizes, int n_in,
                              void* d_out, int out_size)
{
    const float* x     = (const float*)d_in[0];
    const float* qkv_w = (const float*)d_in[1];
    const float* qkv_b = (const float*)d_in[2];
    const float* out_w = (const float*)d_in[3];
    const float* out_b = (const float*)d_in[4];
    const float* rpe   = (const float*)d_in[5];

    float* attnscr;
    __nv_bfloat16 *ah, *al, *wqh, *wql, *woh, *wol, *qkvh, *qkvl, *rpeh, *rpel;
    cudaGetSymbolAddress((void**)&attnscr, g_attn);
    cudaGetSymbolAddress((void**)&ah, g_ah);
    cudaGetSymbolAddress((void**)&al, g_al);
    cudaGetSymbolAddress((void**)&wqh, g_wqh);
    cudaGetSymbolAddress((void**)&wql, g_wql);
    cudaGetSymbolAddress((void**)&woh, g_woh);
    cudaGetSymbolAddress((void**)&wol, g_wol);
    cudaGetSymbolAddress((void**)&qkvh, g_qkvh);
    cudaGetSymbolAddress((void**)&qkvl, g_qkvl);
    cudaGetSymbolAddress((void**)&rpeh, g_rpeh);
    cudaGetSymbolAddress((void**)&rpel, g_rpel);

    float* out = (float*)d_out;
    const long OUT_E = (long)BSc * Dc;
    const long ATT_E = (long)Bc * Hc * Sc * Sc;
    float* attn = ((long)out_size >= OUT_E + ATT_E) ? (out + OUT_E) : attnscr;

    cudaFuncSetAttribute(mma_gemm_kernel,
                         cudaFuncAttributeMaxDynamicSharedMemorySize, GSMEM);
    cudaFuncSetAttribute(qk_mma_kernel,
                         cudaFuncAttributeMaxDynamicSharedMemorySize, QK_SMEM);
    cudaFuncSetAttribute(rpe_mma_softmax_kernel,
                         cudaFuncAttributeMaxDynamicSharedMemorySize, RPE_SMEM);
    cudaFuncSetAttribute(av_mma_kernel,
                         cudaFuncAttributeMaxDynamicSharedMemorySize, AV_SMEM);

    // 0) fused prep: split x + weights + rpe table
    prep_kernel<<<8191, 256>>>(x, ah, al, qkv_w, wqh, wql, out_w, woh, wol,
                               rpe, rpeh, rpel);
    // 1) qkv: emit bf16 hi/lo (q cols pre-scaled 1/8)
    mma_gemm_kernel<<<dim3(D3c / 128, BSc / 128), 256, GSMEM>>>(
        ah, al, wqh, wql, qkv_b, nullptr, qkvh, qkvl, 1, BSc, D3c, Dc);
    // 2) logits = (q/8) . k
    qk_mma_kernel<<<dim3(3, 3, Bc * Hc), 256, QK_SMEM>>>(qkvh, qkvl, attn);
    // 3+4) rpe bias via HMMA + softmax (4 same-slab items; 3 CTA/SM)
    rpe_mma_softmax_kernel<<<dim3(24 * 31, 4), 256, RPE_SMEM>>>(
        qkvh, qkvl, rpeh, rpel, attn);
    // 5) values = attn @ v -> bf16 hi/lo (64-row tiles; 3 CTA/SM)
    av_mma_kernel<<<dim3(6, Bc * Hc), 256, AV_SMEM>>>(attn, qkvh, qkvl, ah, al);
    // 6) out = values @ out_w + out_b
    mma_gemm_kernel<<<dim3(Dc / 128, BSc / 128), 256, GSMEM>>>(
        ah, al, woh, wol, out_b, out, nullptr, nullptr, 0, BSc, Dc, Dc);
}

// round 16
// speedup vs baseline: 1.5330x; 1.0518x over previous
#include <cuda_runtime.h>
#include <cuda_bf16.h>
#include <cstdint>

#define Bc 8
#define Sc 384
#define Dc 1024
#define Hc 16
#define HDc 64
#define D3c 3072
#define BSc 3072   // B*S
#define RPE_ROWS 1023

// ---------------------------------------------------------------------------
// Scratch (static device globals; no runtime allocation)
// ---------------------------------------------------------------------------
__device__ float g_attn[(size_t)Bc * Hc * Sc * Sc];   // fallback attn buffer
__device__ __align__(16) __nv_bfloat16 g_ah[(size_t)BSc * Dc];    // A hi (x, then vals)
__device__ __align__(16) __nv_bfloat16 g_al[(size_t)BSc * Dc];    // A lo
__device__ __align__(16) __nv_bfloat16 g_wqh[(size_t)D3c * Dc];   // qkv_w^T hi [N,K]
__device__ __align__(16) __nv_bfloat16 g_wql[(size_t)D3c * Dc];   // qkv_w^T lo
__device__ __align__(16) __nv_bfloat16 g_woh[(size_t)Dc * Dc];    // out_w^T hi
__device__ __align__(16) __nv_bfloat16 g_wol[(size_t)Dc * Dc];    // out_w^T lo
__device__ __align__(16) __nv_bfloat16 g_qkvh[(size_t)BSc * D3c]; // qkv hi (q pre-scaled /8)
__device__ __align__(16) __nv_bfloat16 g_qkvl[(size_t)BSc * D3c]; // qkv lo
__device__ __align__(16) __nv_bfloat16 g_rpeh[(size_t)RPE_ROWS * Dc]; // rpe hi
__device__ __align__(16) __nv_bfloat16 g_rpel[(size_t)RPE_ROWS * Dc]; // rpe lo

// ---------------------------------------------------------------------------
// Baseline-PTX helpers
// ---------------------------------------------------------------------------
__device__ __forceinline__ uint32_t smem_u32(const void* p) {
    uint32_t a;
    asm("{ .reg .u64 t; cvta.to.shared.u64 t, %1; cvt.u32.u64 %0, t; }" : "=r"(a) : "l"(p));
    return a;
}
#define CP_ASYNC16(sm, gp) \
    asm volatile("cp.async.cg.shared.global [%0], [%1], 16;" :: "r"(sm), "l"(gp))
#define CP_COMMIT() asm volatile("cp.async.commit_group;" ::: "memory")
#define CP_WAIT0()  asm volatile("cp.async.wait_group 0;" ::: "memory")
#define CP_WAIT1()  asm volatile("cp.async.wait_group 1;" ::: "memory")

#define LDSM_X4(r, a) \
    asm volatile("ldmatrix.sync.aligned.m8n8.x4.shared.b16 {%0,%1,%2,%3}, [%4];" \
        : "=r"((r)[0]), "=r"((r)[1]), "=r"((r)[2]), "=r"((r)[3]) : "r"(a))
#define LDSM_X4_T(r, a) \
    asm volatile("ldmatrix.sync.aligned.m8n8.x4.trans.shared.b16 {%0,%1,%2,%3}, [%4];" \
        : "=r"((r)[0]), "=r"((r)[1]), "=r"((r)[2]), "=r"((r)[3]) : "r"(a))

__device__ __forceinline__ void mma_bf16(float* d, const uint32_t* a,
                                         uint32_t b0, uint32_t b1) {
    asm volatile(
        "mma.sync.aligned.m16n8k16.row.col.f32.bf16.bf16.f32 "
        "{%0,%1,%2,%3}, {%4,%5,%6,%7}, {%8,%9}, {%0,%1,%2,%3};"
        : "+f"(d[0]), "+f"(d[1]), "+f"(d[2]), "+f"(d[3])
        : "r"(a[0]), "r"(a[1]), "r"(a[2]), "r"(a[3]), "r"(b0), "r"(b1));
}

__device__ __forceinline__ void split2(float x, float y,
                                       __nv_bfloat16* ph, __nv_bfloat16* pl) {
    __nv_bfloat16 hx = __float2bfloat16(x), hy = __float2bfloat16(y);
    *(__nv_bfloat162*)ph = __nv_bfloat162(hx, hy);
    *(__nv_bfloat162*)pl = __nv_bfloat162(
        __float2bfloat16(x - __bfloat162float(hx)),
        __float2bfloat16(y - __bfloat162float(hy)));
}
__device__ __forceinline__ void pack_hilo(float x, float y,
                                          uint32_t& hi, uint32_t& lo) {
    __nv_bfloat16 hx = __float2bfloat16(x), hy = __float2bfloat16(y);
    __nv_bfloat162 h2(hx, hy);
    __nv_bfloat162 l2(__float2bfloat16(x - __bfloat162float(hx)),
                      __float2bfloat16(y - __bfloat162float(hy)));
    hi = *(uint32_t*)&h2;
    lo = *(uint32_t*)&l2;
}

// ---------------------------------------------------------------------------
// HMMA bf16-split GEMM (128x128 tile): used for the big qkv projection.
// ---------------------------------------------------------------------------
#define TILE_B 8192
#define BUF_B  (4 * TILE_B)
#define NSTAGE 3
#define GSMEM  (NSTAGE * BUF_B)   // 96 KB

__global__ __launch_bounds__(256, 2) void mma_gemm_kernel(
    const __nv_bfloat16* __restrict__ Ah, const __nv_bfloat16* __restrict__ Al,
    const __nv_bfloat16* __restrict__ Bh, const __nv_bfloat16* __restrict__ Bl,
    const float* __restrict__ bias, float* __restrict__ C,
    __nv_bfloat16* __restrict__ Ch, __nv_bfloat16* __restrict__ Cl,
    int qkv_mode, int M, int N, int K)
{
    extern __shared__ char smem[];
    const uint32_t sbase = smem_u32(smem);
    const int tid  = threadIdx.x;
    const int wid  = tid >> 5;
    const int lane = tid & 31;
    const int m0 = blockIdx.y * 128;
    const int n0 = blockIdx.x * 128;
    const int mw = (wid & 1) * 64;
    const int nw = (wid >> 1) * 32;

    const int lrow = tid >> 1;
    const int c0   = (tid & 1) * 2;
    const int sw0  = (lrow >> 1) & 3;
    const __nv_bfloat16* gAh = Ah + (size_t)(m0 + lrow) * K;
    const __nv_bfloat16* gAl = Al + (size_t)(m0 + lrow) * K;
    const __nv_bfloat16* gBh = Bh + (size_t)(n0 + lrow) * K;
    const __nv_bfloat16* gBl = Bl + (size_t)(n0 + lrow) * K;
    const uint32_t soff0 = lrow * 64 + (((c0 + 0) ^ sw0) << 4);
    const uint32_t soff1 = lrow * 64 + (((c0 + 1) ^ sw0) << 4);

    const int NK = K >> 5;

    auto issue = [&](int it) {
        if (it < NK) {
            const uint32_t tb = sbase + (it % NSTAGE) * BUF_B;
            const int k0 = it << 5;
            CP_ASYNC16(tb + 0 * TILE_B + soff0, gAh + k0 + (c0 + 0) * 8);
            CP_ASYNC16(tb + 0 * TILE_B + soff1, gAh + k0 + (c0 + 1) * 8);
            CP_ASYNC16(tb + 1 * TILE_B + soff0, gAl + k0 + (c0 + 0) * 8);
            CP_ASYNC16(tb + 1 * TILE_B + soff1, gAl + k0 + (c0 + 1) * 8);
            CP_ASYNC16(tb + 2 * TILE_B + soff0, gBh + k0 + (c0 + 0) * 8);
            CP_ASYNC16(tb + 2 * TILE_B + soff1, gBh + k0 + (c0 + 1) * 8);
            CP_ASYNC16(tb + 3 * TILE_B + soff0, gBl + k0 + (c0 + 0) * 8);
            CP_ASYNC16(tb + 3 * TILE_B + soff1, gBl + k0 + (c0 + 1) * 8);
        }
        CP_COMMIT();
    };

    const int frow = lane & 15;
    const int fc   = lane >> 4;
    auto fr_addr = [&](int rbase) -> uint32_t {
        const int row = rbase + frow;
        return (uint32_t)(row * 64 + ((fc ^ ((row >> 1) & 3)) << 4));
    };
    const uint32_t aoff = fr_addr(mw);
    const uint32_t boff = fr_addr(nw);

    float acc[4][4][4];
    #pragma unroll
    for (int i = 0; i < 4; i++)
        #pragma unroll
        for (int j = 0; j < 4; j++)
            #pragma unroll
            for (int r = 0; r < 4; r++) acc[i][j][r] = 0.f;

    issue(0); issue(1);

    for (int it = 0; it < NK; it++) {
        CP_WAIT1();
        __syncthreads();
        issue(it + 2);
        const uint32_t tb = sbase + (it % NSTAGE) * BUF_B;
        #pragma unroll
        for (int ks = 0; ks < 2; ks++) {
            const uint32_t kx = ks ? 32u : 0u;
            uint32_t ahf[4][4], bhf[2][4];
            #pragma unroll
            for (int mt = 0; mt < 4; mt++)
                LDSM_X4(ahf[mt], tb + ((aoff + mt * 1024) ^ kx));
            #pragma unroll
            for (int bt = 0; bt < 2; bt++)
                LDSM_X4(bhf[bt], tb + 2 * TILE_B + ((boff + bt * 1024) ^ kx));
            #pragma unroll
            for (int mt = 0; mt < 4; mt++)
                #pragma unroll
                for (int nt = 0; nt < 4; nt++)
                    mma_bf16(acc[mt][nt], ahf[mt],
                             bhf[nt >> 1][nt & 1], bhf[nt >> 1][(nt & 1) + 2]);
            uint32_t blf[2][4];
            #pragma unroll
            for (int bt = 0; bt < 2; bt++)
                LDSM_X4(blf[bt], tb + 3 * TILE_B + ((boff + bt * 1024) ^ kx));
            #pragma unroll
            for (int mt = 0; mt < 4; mt++)
                #pragma unroll
                for (int nt = 0; nt < 4; nt++)
                    mma_bf16(acc[mt][nt], ahf[mt],
                             blf[nt >> 1][nt & 1], blf[nt >> 1][(nt & 1) + 2]);
            uint32_t alf[4][4];
            #pragma unroll
            for (int mt = 0; mt < 4; mt++)
                LDSM_X4(alf[mt], tb + TILE_B + ((aoff + mt * 1024) ^ kx));
            #pragma unroll
            for (int mt = 0; mt < 4; mt++)
                #pragma unroll
                for (int nt = 0; nt < 4; nt++)
                    mma_bf16(acc[mt][nt], alf[mt],
                             bhf[nt >> 1][nt & 1], bhf[nt >> 1][(nt & 1) + 2]);
        }
    }

    const int er = lane >> 2;
    const int ec = (lane & 3) * 2;
    #pragma unroll
    for (int mt = 0; mt < 4; mt++) {
        #pragma unroll
        for (int nt = 0; nt < 4; nt++) {
            const int col = n0 + nw + nt * 8 + ec;
            const float bx = __ldg(&bias[col]);
            const float by = __ldg(&bias[col + 1]);
            const int r0 = m0 + mw + mt * 16 + er;
            float2 v0 = make_float2(acc[mt][nt][0] + bx, acc[mt][nt][1] + by);
            float2 v1 = make_float2(acc[mt][nt][2] + bx, acc[mt][nt][3] + by);
            if (C) {
                *(float2*)(C + (size_t)r0 * N + col) = v0;
                *(float2*)(C + (size_t)(r0 + 8) * N + col) = v1;
            }
            if (Ch) {
                const float s = (qkv_mode && (((col >> 6) % 3) == 0)) ? 0.125f : 1.0f;
                split2(v0.x * s, v0.y * s, Ch + (size_t)r0 * N + col,
                       Cl + (size_t)r0 * N + col);
                split2(v1.x * s, v1.y * s, Ch + (size_t)(r0 + 8) * N + col,
                       Cl + (size_t)(r0 + 8) * N + col);
            }
        }
    }
}

// ---------------------------------------------------------------------------
// out-proj GEMM: 64x128 tile (M-tile 64) to fix wave quantization.
// grid (N/128, M/64) = (8, 48) = 384 blocks; stage 24KB x 3 = 72KB -> 3 CTA/SM.
// Warp tile 32x32 (2 m16-tiles). Same K order per element -> bit-identical.
// ---------------------------------------------------------------------------
#define OTILE_A 4096                   // 64 rows x 64B
#define OTILE_B 8192                   // 128 rows x 64B
#define OBUF    (2 * OTILE_A + 2 * OTILE_B)   // 24576
#define OSMEM   (NSTAGE * OBUF)               // 73728

__global__ __launch_bounds__(256, 3) void out_gemm_kernel(
    const __nv_bfloat16* __restrict__ Ah, const __nv_bfloat16* __restrict__ Al,
    const __nv_bfloat16* __restrict__ Bh, const __nv_bfloat16* __restrict__ Bl,
    const float* __restrict__ bias, float* __restrict__ C,
    int M, int N, int K)
{
    extern __shared__ char smem[];
    const uint32_t sbase = smem_u32(smem);
    const int tid  = threadIdx.x;
    const int wid  = tid >> 5;
    const int lane = tid & 31;
    const int m0 = blockIdx.y * 64;
    const int n0 = blockIdx.x * 128;
    const int mw = (wid & 1) * 32;
    const int nw = (wid >> 1) * 32;

    // A loader: 256 chunks (64 rows x 4), one per thread
    const int arow_l = tid >> 2;
    const int ac     = tid & 3;
    const uint32_t soffA = arow_l * 64 + ((ac ^ ((arow_l >> 1) & 3)) << 4);
    const __nv_bfloat16* gAh = Ah + (size_t)(m0 + arow_l) * K;
    const __nv_bfloat16* gAl = Al + (size_t)(m0 + arow_l) * K;
    // B loader: 512 chunks (128 rows x 4), two per thread
    const int lrow = tid >> 1;
    const int c0   = (tid & 1) * 2;
    const int sw0  = (lrow >> 1) & 3;
    const __nv_bfloat16* gBh = Bh + (size_t)(n0 + lrow) * K;
    const __nv_bfloat16* gBl = Bl + (size_t)(n0 + lrow) * K;
    const uint32_t soff0 = lrow * 64 + (((c0 + 0) ^ sw0) << 4);
    const uint32_t soff1 = lrow * 64 + (((c0 + 1) ^ sw0) << 4);

    const int NK = K >> 5;

    auto issue = [&](int it) {
        if (it < NK) {
            const uint32_t tb = sbase + (it % NSTAGE) * OBUF;
            const int k0 = it << 5;
            CP_ASYNC16(tb + 0 * OTILE_A + soffA, gAh + k0 + ac * 8);
            CP_ASYNC16(tb + 1 * OTILE_A + soffA, gAl + k0 + ac * 8);
            CP_ASYNC16(tb + 2 * OTILE_A + soff0, gBh + k0 + (c0 + 0) * 8);
            CP_ASYNC16(tb + 2 * OTILE_A + soff1, gBh + k0 + (c0 + 1) * 8);
            CP_ASYNC16(tb + 2 * OTILE_A + OTILE_B + soff0, gBl + k0 + (c0 + 0) * 8);
            CP_ASYNC16(tb + 2 * OTILE_A + OTILE_B + soff1, gBl + k0 + (c0 + 1) * 8);
        }
        CP_COMMIT();
    };

    const int frow = lane & 15;
    const int fc   = lane >> 4;
    auto fr_addr = [&](int rbase) -> uint32_t {
        const int row = rbase + frow;
        return (uint32_t)(row * 64 + ((fc ^ ((row >> 1) & 3)) << 4));
    };
    const uint32_t aoff = fr_addr(mw);
    const uint32_t boff = fr_addr(nw);

    float acc[2][4][4];
    #pragma unroll
    for (int i = 0; i < 2; i++)
        #pragma unroll
        for (int j = 0; j < 4; j++)
            #pragma unroll
            for (int r = 0; r < 4; r++) acc[i][j][r] = 0.f;

    issue(0); issue(1);

    for (int it = 0; it < NK; it++) {
        CP_WAIT1();
        __syncthreads();
        issue(it + 2);
        const uint32_t tb = sbase + (it % NSTAGE) * OBUF;
        #pragma unroll
        for (int ks = 0; ks < 2; ks++) {
            const uint32_t kx = ks ? 32u : 0u;
            uint32_t ahf[2][4], bhf[2][4];
            #pragma unroll
            for (int mt = 0; mt < 2; mt++)
                LDSM_X4(ahf[mt], tb + ((aoff + mt * 1024) ^ kx));
            #pragma unroll
            for (int bt = 0; bt < 2; bt++)
                LDSM_X4(bhf[bt], tb + 2 * OTILE_A + ((boff + bt * 1024) ^ kx));
            #pragma unroll
            for (int mt = 0; mt < 2; mt++)
                #pragma unroll
                for (int nt = 0; nt < 4; nt++)
                    mma_bf16(acc[mt][nt], ahf[mt],
                             bhf[nt >> 1][nt & 1], bhf[nt >> 1][(nt & 1) + 2]);
            uint32_t blf[2][4];
            #pragma unroll
            for (int bt = 0; bt < 2; bt++)
                LDSM_X4(blf[bt], tb + 2 * OTILE_A + OTILE_B + ((boff + bt * 1024) ^ kx));
            #pragma unroll
            for (int mt = 0; mt < 2; mt++)
                #pragma unroll
                for (int nt = 0; nt < 4; nt++)
                    mma_bf16(acc[mt][nt], ahf[mt],
                             blf[nt >> 1][nt & 1], blf[nt >> 1][(nt & 1) + 2]);
            uint32_t alf[2][4];
            #pragma unroll
            for (int mt = 0; mt < 2; mt++)
                LDSM_X4(alf[mt], tb + OTILE_A + ((aoff + mt * 1024) ^ kx));
            #pragma unroll
            for (int mt = 0; mt < 2; mt++)
                #pragma unroll
                for (int nt = 0; nt < 4; nt++)
                    mma_bf16(acc[mt][nt], alf[mt],
                             bhf[nt >> 1][nt & 1], bhf[nt >> 1][(nt & 1) + 2]);
        }
    }

    const int er = lane >> 2;
    const int ec = (lane & 3) * 2;
    #pragma unroll
    for (int mt = 0; mt < 2; mt++) {
        #pragma unroll
        for (int nt = 0; nt < 4; nt++) {
            const int col = n0 + nw + nt * 8 + ec;
            const float bx = __ldg(&bias[col]);
            const float by = __ldg(&bias[col + 1]);
            const int r0 = m0 + mw + mt * 16 + er;
            *(float2*)(C + (size_t)r0 * N + col) =
                make_float2(acc[mt][nt][0] + bx, acc[mt][nt][1] + by);
            *(float2*)(C + (size_t)(r0 + 8) * N + col) =
                make_float2(acc[mt][nt][2] + bx, acc[mt][nt][3] + by);
        }
    }
}

// ---------------------------------------------------------------------------
// Fused prep: split x + transpose-split qkv_w + out_w + split rpe table.
// ---------------------------------------------------------------------------
__global__ __launch_bounds__(256) void prep_kernel(
    const float* __restrict__ x,
    __nv_bfloat16* __restrict__ ah, __nv_bfloat16* __restrict__ al,
    const float* __restrict__ qkv_w,
    __nv_bfloat16* __restrict__ wqh, __nv_bfloat16* __restrict__ wql,
    const float* __restrict__ out_w,
    __nv_bfloat16* __restrict__ woh, __nv_bfloat16* __restrict__ wol,
    const float* __restrict__ rpe,
    __nv_bfloat16* __restrict__ rpeh, __nv_bfloat16* __restrict__ rpel)
{
    __shared__ float t[32][33];
    const int bid = blockIdx.x;
    const int tid = threadIdx.x;
    if (bid < 3072) {
        const int i = bid * 256 + tid;
        float4 v = ((const float4*)x)[i];
        split2(v.x, v.y, ah + 4 * (size_t)i, al + 4 * (size_t)i);
        split2(v.z, v.w, ah + 4 * (size_t)i + 2, al + 4 * (size_t)i + 2);
        return;
    }
    if (bid >= 7168) {
        const int i = (bid - 7168) * 256 + tid;
        float4 v = ((const float4*)rpe)[i];
        split2(v.x, v.y, rpeh + 4 * (size_t)i, rpel + 4 * (size_t)i);
        split2(v.z, v.w, rpeh + 4 * (size_t)i + 2, rpel + 4 * (size_t)i + 2);
        return;
    }
    const float* W;
    __nv_bfloat16 *Th, *Tl;
    int N, bx, by;
    if (bid < 6144) {
        const int r = bid - 3072;
        W = qkv_w; Th = wqh; Tl = wql; N = D3c;
        bx = r % 96; by = r / 96;
    } else {
        const int r = bid - 6144;
        W = out_w; Th = woh; Tl = wol; N = Dc;
        bx = r % 32; by = r / 32;
    }
    const int K = Dc;
    const int n0 = bx * 32, k0 = by * 32;
    const int tx = tid & 31, ty = tid >> 5;
    #pragma unroll
    for (int r = 0; r < 4; r++)
        t[ty + 8 * r][tx] = W[(size_t)(k0 + ty + 8 * r) * N + n0 + tx];
    __syncthreads();
    #pragma unroll
    for (int r = 0; r < 4; r++) {
        float v = t[tx][ty + 8 * r];
        __nv_bfloat16 h = __float2bfloat16(v);
        __nv_bfloat16 l = __float2bfloat16(v - __bfloat162float(h));
        size_t o = (size_t)(n0 + ty + 8 * r) * K + k0 + tx;
        Th[o] = h; Tl[o] = l;
    }
}

// ---------------------------------------------------------------------------
// qk HMMA: logits = (scaled q).k, 3-pass bf16 split, interleaved LDSM.
// ---------------------------------------------------------------------------
#define QK_SMEM (4 * 16384)

__global__ __launch_bounds__(256, 2) void qk_mma_kernel(
    const __nv_bfloat16* __restrict__ qkvh, const __nv_bfloat16* __restrict__ qkvl,
    float* __restrict__ attn)
{
    extern __shared__ char smem[];
    const uint32_t sb = smem_u32(smem);
    const int tid = threadIdx.x, wid = tid >> 5, lane = tid & 31;
    const int bh = blockIdx.z, b = bh >> 4, h = bh & 15;
    const int i0 = blockIdx.y * 128, j0 = blockIdx.x * 128;

    #pragma unroll
    for (int t = 0; t < 4; t++) {
        const __nv_bfloat16* base = (t & 1) ? qkvl : qkvh;
        const int roff = (t < 2) ? i0 : j0;
        const int coff = h * 192 + ((t < 2) ? 0 : 64);
        for (int idx = tid; idx < 1024; idx += 256) {
            const int row = idx >> 3, c = idx & 7;
            const uint32_t dst = sb + t * 16384 + row * 128 + ((c ^ (row & 7)) << 4);
            CP_ASYNC16(dst, base + (size_t)(b * Sc + roff + row) * D3c + coff + c * 8);
        }
    }
    CP_COMMIT(); CP_WAIT0();
    __syncthreads();

    const int mw = (wid & 1) * 64;
    const int nw = (wid >> 1) * 32;
    const int frow = lane & 15, fc = lane >> 4;

    float acc[4][4][4];
    #pragma unroll
    for (int i = 0; i < 4; i++)
        #pragma unroll
        for (int j = 0; j < 4; j++)
            #pragma unroll
            for (int r = 0; r < 4; r++) acc[i][j][r] = 0.f;

    #pragma unroll
    for (int ks = 0; ks < 4; ks++) {
        uint32_t aadr[4], badr[2];
        #pragma unroll
        for (int mt = 0; mt < 4; mt++) {
            const int row = mw + mt * 16 + frow;
            aadr[mt] = row * 128 + (((2 * ks + fc) ^ (row & 7)) << 4);
        }
        #pragma unroll
        for (int bt = 0; bt < 2; bt++) {
            const int row = nw + bt * 16 + frow;
            badr[bt] = row * 128 + (((2 * ks + fc) ^ (row & 7)) << 4);
        }
        uint32_t ahf[4][4], bhf[2][4];
        #pragma unroll
        for (int mt = 0; mt < 4; mt++) LDSM_X4(ahf[mt], sb + aadr[mt]);
        #pragma unroll
        for (int bt = 0; bt < 2; bt++) LDSM_X4(bhf[bt], sb + 2 * 16384 + badr[bt]);
        #pragma unroll
        for (int mt = 0; mt < 4; mt++)
            #pragma unroll
            for (int nt = 0; nt < 4; nt++)
                mma_bf16(acc[mt][nt], ahf[mt],
                         bhf[nt >> 1][nt & 1], bhf[nt >> 1][(nt & 1) + 2]);
        uint32_t blf[2][4];
        #pragma unroll
        for (int bt = 0; bt < 2; bt++) LDSM_X4(blf[bt], sb + 3 * 16384 + badr[bt]);
        #pragma unroll
        for (int mt = 0; mt < 4; mt++)
            #pragma unroll
            for (int nt = 0; nt < 4; nt++)
                mma_bf16(acc[mt][nt], ahf[mt],
                         blf[nt >> 1][nt & 1], blf[nt >> 1][(nt & 1) + 2]);
        uint32_t alf[4][4];
        #pragma unroll
        for (int mt = 0; mt < 4; mt++) LDSM_X4(alf[mt], sb + 16384 + aadr[mt]);
        #pragma unroll
        for (int mt = 0; mt < 4; mt++)
            #pragma unroll
            for (int nt = 0; nt < 4; nt++)
                mma_bf16(acc[mt][nt], alf[mt],
                         bhf[nt >> 1][nt & 1], bhf[nt >> 1][(nt & 1) + 2]);
    }

    const int er = lane >> 2, ec = (lane & 3) * 2;
    float* ob = attn + (size_t)bh * Sc * Sc;
    #pragma unroll
    for (int mt = 0; mt < 4; mt++) {
        #pragma unroll
        for (int nt = 0; nt < 4; nt++) {
            const int r0 = i0 + mw + mt * 16 + er;
            const int col = j0 + nw + nt * 8 + ec;
            *(float2*)(ob + (size_t)r0 * Sc + col) =
                make_float2(acc[mt][nt][0], acc[mt][nt][1]);
            *(float2*)(ob + (size_t)(r0 + 8) * Sc + col) =
                make_float2(acc[mt][nt][2], acc[mt][nt][3]);
        }
    }
}

// ---------------------------------------------------------------------------
// rpe bias via HMMA + fused softmax — 4 same-slab items per block, 3 CTA/SM.
// cp.async addresses hoisted out of the chunk loop (alu reduction).
// SMEM: q 8KB | slab 16KB | L 48KB = 73728 B.
// ---------------------------------------------------------------------------
#define RPE_SMEM (8192 + 16384 + 32 * Sc * 4)   // 73728

__global__ __launch_bounds__(256, 3) void rpe_mma_softmax_kernel(
    const __nv_bfloat16* __restrict__ qkvh, const __nv_bfloat16* __restrict__ qkvl,
    const __nv_bfloat16* __restrict__ rpeh, const __nv_bfloat16* __restrict__ rpel,
    float* __restrict__ attn)
{
    extern __shared__ char smem[];
    const uint32_t sb = smem_u32(smem);
    const uint32_t slab0 = sb + 8192;
    float* L = (float*)(smem + 8192 + 16384);     // [32][384]
    const uint32_t Lbase = sb + 8192 + 16384;
    const int tid = threadIdx.x, wid = tid >> 5, lane = tid & 31;

    const int a = blockIdx.x / 31;
    const int d = blockIdx.x % 31 - 15;
    const int h_lo = d < 0 ? -d : 0;
    const int h_hi = d > 0 ? 15 - d : 15;
    const int h0 = h_lo + 4 * (int)blockIdx.y;
    if (h0 > h_hi) return;
    int hh[4], ii[4];
    #pragma unroll
    for (int it = 0; it < 4; it++) {
        const int hx = (h0 + it <= h_hi) ? (h0 + it) : h_hi;
        hh[it] = hx;
        ii[it] = 16 * a + hx + d;
    }
    const size_t r0off = (size_t)(384 + 24 * d - a) * 1024;

    // hoisted slab loader addresses: 2 chunks per thread (idx=tid, tid+256)
    const int srow0 = tid >> 3,        sc0 = tid & 7;
    const int srow1 = (tid + 256) >> 3, sc1 = (tid + 256) & 7;
    const uint32_t ssw0 = srow0 * 128 + ((sc0 ^ (srow0 & 7)) << 4);
    const uint32_t ssw1 = srow1 * 128 + ((sc1 ^ (srow1 & 7)) << 4);
    const __nv_bfloat16* sph0 = rpeh + r0off + (size_t)srow0 * 64 + sc0 * 8;
    const __nv_bfloat16* spl0 = rpel + r0off + (size_t)srow0 * 64 + sc0 * 8;
    const __nv_bfloat16* sph1 = rpeh + r0off + (size_t)srow1 * 64 + sc1 * 8;
    const __nv_bfloat16* spl1 = rpel + r0off + (size_t)srow1 * 64 + sc1 * 8;

    auto slab_issue = [&](int nc) {
        const int off = nc * 4096;    // 64 rows x 64 elems
        CP_ASYNC16(slab0 + ssw0, sph0 + off);
        CP_ASYNC16(slab0 + 8192 + ssw0, spl0 + off);
        CP_ASYNC16(slab0 + ssw1, sph1 + off);
        CP_ASYNC16(slab0 + 8192 + ssw1, spl1 + off);
        CP_COMMIT();
    };

    // group A: q tiles (2 arrays x 32 rows x 8 chunks) + attn prefetch
    for (int t = tid; t < 512; t += 256) {
        const int arr = t >> 8;          // 0=hi,1=lo
        const int r = (t >> 3) & 31;     // it*8+b
        const int c = t & 7;
        const int it = r >> 3, b = r & 7;
        const __nv_bfloat16* src = arr ? qkvl : qkvh;
        CP_ASYNC16(sb + arr * 4096 + r * 128 + ((c ^ (r & 7)) << 4),
                   src + (size_t)(b * Sc + ii[it]) * D3c + hh[it] * 192 + c * 8);
    }
    #pragma unroll
    for (int rr = 0; rr < 12; rr++) {
        const int idx = tid + rr * 256;
        const int row = idx / 96, cc = idx % 96;
        const int it2 = row >> 3, b2 = row & 7;
        CP_ASYNC16(Lbase + (uint32_t)(row * Sc + cc * 4) * 4,
                   attn + ((size_t)(b2 * Hc + hh[it2]) * Sc + ii[it2]) * Sc + cc * 4);
    }
    CP_COMMIT();

    const int frow = lane & 15, fc = lane >> 4;
    const int mt = wid >> 2;               // m16 tile 0/1
    const int wn = (wid & 3) * 16;         // warp's 16 j-rows within chunk
    const int er = lane >> 2, ec = (lane & 3) * 2;
    const int arow = mt * 16 + frow;

    for (int ck = 0; ck < 6; ck++) {
        slab_issue(ck);
        CP_WAIT0();
        __syncthreads();
        float acc[2][4];
        #pragma unroll
        for (int nt = 0; nt < 2; nt++)
            #pragma unroll
            for (int r = 0; r < 4; r++) acc[nt][r] = 0.f;

        #pragma unroll
        for (int ks = 0; ks < 4; ks++) {
            const uint32_t aadr = arow * 128 + (((2 * ks + fc) ^ (arow & 7)) << 4);
            const int brow = wn + frow;
            const uint32_t badr = brow * 128 + (((2 * ks + fc) ^ (brow & 7)) << 4);
            uint32_t ah4[4], al4[4], bh4[4], bl4[4];
            LDSM_X4(ah4, sb + aadr);
            LDSM_X4(bh4, slab0 + badr);
            #pragma unroll
            for (int nt = 0; nt < 2; nt++)
                mma_bf16(acc[nt], ah4, bh4[nt], bh4[nt + 2]);
            LDSM_X4(bl4, slab0 + 8192 + badr);
            #pragma unroll
            for (int nt = 0; nt < 2; nt++)
                mma_bf16(acc[nt], ah4, bl4[nt], bl4[nt + 2]);
            LDSM_X4(al4, sb + 4096 + aadr);
            #pragma unroll
            for (int nt = 0; nt < 2; nt++)
                mma_bf16(acc[nt], al4, bh4[nt], bh4[nt + 2]);
        }
        #pragma unroll
        for (int nt = 0; nt < 2; nt++) {
            const int col = ck * 64 + wn + nt * 8 + ec;
            const int rbase = mt * 16;
            L[(rbase + er) * Sc + col]           += 8.f * acc[nt][0];
            L[(rbase + er) * Sc + col + 1]       += 8.f * acc[nt][1];
            L[(rbase + er + 8) * Sc + col]       += 8.f * acc[nt][2];
            L[(rbase + er + 8) * Sc + col + 1]   += 8.f * acc[nt][3];
        }
        __syncthreads();   // all reads of slab done before next overwrite
    }

    // softmax: 32 (it,b) rows over 8 warps = 4 rows per warp
    #pragma unroll
    for (int rr = 0; rr < 4; rr++) {
        const int row = wid * 4 + rr;
        const int it = row >> 3, b = row & 7;
        float v[12];
        float m = -1e30f;
        #pragma unroll
        for (int r = 0; r < 12; r++) { v[r] = L[row * Sc + lane + 32 * r]; m = fmaxf(m, v[r]); }
        #pragma unroll
        for (int o = 16; o > 0; o >>= 1) m = fmaxf(m, __shfl_xor_sync(0xffffffffu, m, o));
        float s = 0.f;
        #pragma unroll
        for (int r = 0; r < 12; r++) { v[r] = __expf(v[r] - m); s += v[r]; }
        #pragma unroll
        for (int o = 16; o > 0; o >>= 1) s += __shfl_xor_sync(0xffffffffu, s, o);
        const float inv = 1.0f / s;
        float* orow = attn + ((size_t)(b * Hc + hh[it]) * Sc + ii[it]) * Sc;
        #pragma unroll
        for (int r = 0; r < 12; r++) orow[lane + 32 * r] = v[r] * inv;
    }
}

// ---------------------------------------------------------------------------
// av HMMA: values = attn(fp32) @ v, 3-pass bf16 split.
// 64-row i-tiles, 3 CTA/SM.
// ---------------------------------------------------------------------------
#define AV_AROW 72
#define AV_ATILE (64 * AV_AROW * 4)          // 18432
#define AV_VTILE 8192
#define AV_STAGE (AV_ATILE + 2 * AV_VTILE)   // 34816
#define AV_SMEM  (2 * AV_STAGE)              // 69632

__global__ __launch_bounds__(256, 3) void av_mma_kernel(
    const float* __restrict__ attn,
    const __nv_bfloat16* __restrict__ qkvh, const __nv_bfloat16* __restrict__ qkvl,
    __nv_bfloat16* __restrict__ vh_out, __nv_bfloat16* __restrict__ vl_out)
{
    extern __shared__ char smem[];
    const uint32_t sb = smem_u32(smem);
    float* sA_f = (float*)smem;
    const int tid = threadIdx.x, wid = tid >> 5, lane = tid & 31;
    const int bh = blockIdx.y, b = bh >> 4, h = bh & 15;
    const int i0 = blockIdx.x * 64;

    const float* abase = attn + ((size_t)bh * Sc + i0) * Sc;
    const __nv_bfloat16* vbase_h = qkvh + h * 192 + 128;
    const __nv_bfloat16* vbase_l = qkvl + h * 192 + 128;

    auto issue = [&](int ck) {
        if (ck >= 6) { CP_COMMIT(); return; }
        const uint32_t st = sb + (ck & 1) * AV_STAGE;
        const int j0 = ck * 64;
        for (int idx = tid; idx < 1024; idx += 256) {
            const int row = idx >> 4, c = idx & 15;
            CP_ASYNC16(st + row * (AV_AROW * 4) + c * 16,
                       abase + (size_t)row * Sc + j0 + c * 4);
        }
        for (int idx = tid; idx < 512; idx += 256) {
            const int row = idx >> 3, c = idx & 7;
            const uint32_t sw = row * 128 + ((c ^ (row & 7)) << 4);
            const size_t go = (size_t)(b * Sc + j0 + row) * D3c + c * 8;
            CP_ASYNC16(st + AV_ATILE + sw, vbase_h + go);
            CP_ASYNC16(st + AV_ATILE + AV_VTILE + sw, vbase_l + go);
        }
        CP_COMMIT();
    };

    const int wm = (wid & 1) * 32;
    const int wn = (wid >> 1) * 16;
    const int er = lane >> 2;
    const int ecb = (lane & 3) * 2;
    const int krow = (lane & 7) | ((lane & 16) >> 1);
    const int colc = (lane >> 3) & 1;

    float acc[2][2][4];
    #pragma unroll
    for (int i = 0; i < 2; i++)
        #pragma unroll
        for (int j = 0; j < 2; j++)
            #pragma unroll
            for (int r = 0; r < 4; r++) acc[i][j][r] = 0.f;

    issue(0);
    for (int ck = 0; ck < 6; ck++) {
        issue(ck + 1);
        CP_WAIT1();
        __syncthreads();
        const int stg = (ck & 1);
        float* sA = sA_f + stg * (AV_STAGE / 4);
        const uint32_t vt_h = sb + stg * AV_STAGE + AV_ATILE;
        const uint32_t vt_l = vt_h + AV_VTILE;
        #pragma unroll
        for (int ks = 0; ks < 4; ks++) {
            uint32_t ahf[2][4], alf[2][4];
            #pragma unroll
            for (int mt = 0; mt < 2; mt++) {
                const int r_ = wm + mt * 16 + er;
                const int cb = ks * 16 + ecb;
                float2 x0 = *(float2*)(sA + (size_t)r_ * AV_AROW + cb);
                float2 x1 = *(float2*)(sA + (size_t)(r_ + 8) * AV_AROW + cb);
                float2 x2 = *(float2*)(sA + (size_t)r_ * AV_AROW + cb + 8);
                float2 x3 = *(float2*)(sA + (size_t)(r_ + 8) * AV_AROW + cb + 8);
                pack_hilo(x0.x, x0.y, ahf[mt][0], alf[mt][0]);
                pack_hilo(x1.x, x1.y, ahf[mt][1], alf[mt][1]);
                pack_hilo(x2.x, x2.y, ahf[mt][2], alf[mt][2]);
                pack_hilo(x3.x, x3.y, ahf[mt][3], alf[mt][3]);
            }
            const int vrow = ks * 16 + krow;
            const int vc = (wn >> 3) + colc;
            const uint32_t badr = vrow * 128 + ((vc ^ (vrow & 7)) << 4);
            uint32_t bhf[4], blf[4];
            LDSM_X4_T(bhf, vt_h + badr);
            LDSM_X4_T(blf, vt_l + badr);
            #pragma unroll
            for (int mt = 0; mt < 2; mt++)
                #pragma unroll
                for (int nt = 0; nt < 2; nt++)
                    mma_bf16(acc[mt][nt], ahf[mt], bhf[nt], bhf[nt + 2]);
            #pragma unroll
            for (int mt = 0; mt < 2; mt++)
                #pragma unroll
                for (int nt = 0; nt < 2; nt++)
                    mma_bf16(acc[mt][nt], alf[mt], bhf[nt], bhf[nt + 2]);
            #pragma unroll
            for (int mt = 0; mt < 2; mt++)
                #pragma unroll
                for (int nt = 0; nt < 2; nt++)
                    mma_bf16(acc[mt][nt], ahf[mt], blf[nt], blf[nt + 2]);
        }
        __syncthreads();
    }

    const int ec = (lane & 3) * 2;
    #pragma unroll
    for (int mt = 0; mt < 2; mt++) {
        #pragma unroll
        for (int nt = 0; nt < 2; nt++) {
            const int row = i0 + wm + mt * 16 + er;
            const int col = h * 64 + wn + nt * 8 + ec;
            const size_t o0 = (size_t)(b * Sc + row) * Dc + col;
            const size_t o1 = (size_t)(b * Sc + row + 8) * Dc + col;
            split2(acc[mt][nt][0], acc[mt][nt][1], vh_out + o0, vl_out + o0);
            split2(acc[mt][nt][2], acc[mt][nt][3], vh_out + o1, vl_out + o1);
        }
    }
}

// ---------------------------------------------------------------------------
extern "C" void kernel_launch(void* const* d_in, const int* in_sizes, int n_in,
                              void* d_out, int out_size)
{
    const float* x     = (const float*)d_in[0];
    const float* qkv_w = (const float*)d_in[1];
    const float* qkv_b = (const float*)d_in[2];
    const float* out_w = (const float*)d_in[3];
    const float* out_b = (const float*)d_in[4];
    const float* rpe   = (const float*)d_in[5];

    float* attnscr;
    __nv_bfloat16 *ah, *al, *wqh, *wql, *woh, *wol, *qkvh, *qkvl, *rpeh, *rpel;
    cudaGetSymbolAddress((void**)&attnscr, g_attn);
    cudaGetSymbolAddress((void**)&ah, g_ah);
    cudaGetSymbolAddress((void**)&al, g_al);
    cudaGetSymbolAddress((void**)&wqh, g_wqh);
    cudaGetSymbolAddress((void**)&wql, g_wql);
    cudaGetSymbolAddress((void**)&woh, g_woh);
    cudaGetSymbolAddress((void**)&wol, g_wol);
    cudaGetSymbolAddress((void**)&qkvh, g_qkvh);
    cudaGetSymbolAddress((void**)&qkvl, g_qkvl);
    cudaGetSymbolAddress((void**)&rpeh, g_rpeh);
    cudaGetSymbolAddress((void**)&rpel, g_rpel);

    float* out = (float*)d_out;
    const long OUT_E = (long)BSc * Dc;
    const long ATT_E = (long)Bc * Hc * Sc * Sc;
    float* attn = ((long)out_size >= OUT_E + ATT_E) ? (out + OUT_E) : attnscr;

    cudaFuncSetAttribute(mma_gemm_kernel,
                         cudaFuncAttributeMaxDynamicSharedMemorySize, GSMEM);
    cudaFuncSetAttribute(out_gemm_kernel,
                         cudaFuncAttributeMaxDynamicSharedMemorySize, OSMEM);
    cudaFuncSetAttribute(qk_mma_kernel,
                         cudaFuncAttributeMaxDynamicSharedMemorySize, QK_SMEM);
    cudaFuncSetAttribute(rpe_mma_softmax_kernel,
                         cudaFuncAttributeMaxDynamicSharedMemorySize, RPE_SMEM);
    cudaFuncSetAttribute(av_mma_kernel,
                         cudaFuncAttributeMaxDynamicSharedMemorySize, AV_SMEM);

    // 0) fused prep: split x + weights + rpe table
    prep_kernel<<<8191, 256>>>(x, ah, al, qkv_w, wqh, wql, out_w, woh, wol,
                               rpe, rpeh, rpel);
    // 1) qkv: emit bf16 hi/lo (q cols pre-scaled 1/8)
    mma_gemm_kernel<<<dim3(D3c / 128, BSc / 128), 256, GSMEM>>>(
        ah, al, wqh, wql, qkv_b, nullptr, qkvh, qkvl, 1, BSc, D3c, Dc);
    // 2) logits = (q/8) . k
    qk_mma_kernel<<<dim3(3, 3, Bc * Hc), 256, QK_SMEM>>>(qkvh, qkvl, attn);
    // 3+4) rpe bias via HMMA + softmax (4 same-slab items; 3 CTA/SM)
    rpe_mma_softmax_kernel<<<dim3(24 * 31, 4), 256, RPE_SMEM>>>(
        qkvh, qkvl, rpeh, rpel, attn);
    // 5) values = attn @ v -> bf16 hi/lo (64-row tiles; 3 CTA/SM)
    av_mma_kernel<<<dim3(6, Bc * Hc), 256, AV_SMEM>>>(attn, qkvh, qkvl, ah, al);
    // 6) out = values @ out_w + out_b (64-row M-tiles; 384 blocks)
    out_gemm_kernel<<<dim3(Dc / 128, BSc / 64), 256, OSMEM>>>(
        ah, al, woh, wol, out_b, out, BSc, Dc, Dc);
}